// round 3
// baseline (speedup 1.0000x reference)
#include <cuda_runtime.h>
#include <cuda_bf16.h>
#include <math.h>
#include <stdint.h>

#define N_NODES 20000
#define N_EDGES 320000
#define H 128
#define CUTOFF_R 5.0f
#define PI_F 3.14159265358979323846f

// ========================= scratch (device globals) =========================
__device__ __align__(16) float g_scalar_out[N_NODES * H];
__device__ __align__(16) float g_ns[N_NODES * H];
__device__ __align__(16) float g_msg[N_EDGES * H];
__device__ __align__(16) float g_s[N_EDGES * 2 * H];
__device__ __align__(16) float g_nv[N_NODES * 3 * H];
__device__ __align__(16) float g_ns1[N_NODES * H];
__device__ __align__(16) float g_nvec1[N_NODES * 3 * H];
__device__ __align__(16) float g_wv[N_NODES * 3 * 2 * H];
__device__ __align__(16) float g_p[N_NODES * 3 * H];
// packed weights: 11 tiles, each = 16384 hi bf16 [n*128+k] then 16384 lo bf16
__device__ __align__(16) __nv_bfloat16 g_wpack[11 * 32768];

__device__ int g_deg[N_NODES];
__device__ int g_off[N_NODES + 1];
__device__ int g_cur[N_NODES];
__device__ int g_eids[N_EDGES];

// ========================= helpers =========================
__device__ __forceinline__ uint32_t smem_u32(const void* p) {
    uint32_t a;
    asm("{ .reg .u64 t; cvta.to.shared.u64 t, %1; cvt.u32.u64 %0, t; }" : "=r"(a) : "l"(p));
    return a;
}
__device__ __forceinline__ float silu_f(float x) { return x / (1.0f + __expf(-x)); }

#define LDSM4(r, addr) \
    asm volatile("ldmatrix.sync.aligned.m8n8.x4.shared.b16 {%0,%1,%2,%3}, [%4];" \
        : "=r"((r)[0]), "=r"((r)[1]), "=r"((r)[2]), "=r"((r)[3]) : "r"(addr))

#define MMA16816(c, a, b) \
    asm volatile("mma.sync.aligned.m16n8k16.row.col.f32.bf16.bf16.f32 " \
        "{%0,%1,%2,%3}, {%4,%5,%6,%7}, {%8,%9}, {%0,%1,%2,%3};" \
        : "+f"((c)[0]), "+f"((c)[1]), "+f"((c)[2]), "+f"((c)[3]) \
        : "r"((a)[0]), "r"((a)[1]), "r"((a)[2]), "r"((a)[3]), "r"((b)[0]), "r"((b)[1]))

// ========================= weight pre-pack: Bt[n][k] hi/lo bf16 ==============
__global__ void pack_w(const float* __restrict__ W, int NCOL, int tile0) {
    int t = blockIdx.x;
    __nv_bfloat16* dst = g_wpack + (size_t)(tile0 + t) * 32768;
    for (int it = 0; it < 64; it++) {
        int lin = threadIdx.x + it * 256;          // lin = n*128 + k
        int n = lin >> 7, k = lin & 127;
        float v = W[(size_t)k * NCOL + t * 128 + n];
        __nv_bfloat16 h = __float2bfloat16(v);
        __nv_bfloat16 l = __float2bfloat16(v - __bfloat162float(h));
        dst[lin] = h;
        dst[16384 + lin] = l;
    }
}

// ========================= HMMA GEMM (128x128x128, bf16x3 split) ============
// smem layout (bf16 elems, padded row stride 136):
//   A_hi @ 0 (34816 B), A_lo @ 34816, B_hi @ 69632, B_lo @ 104448; total 139264
// After MMA, smem reused as fp32 C staging [128][132].
#define SM_TOTAL 139264
#define ASTRIDE 136
#define CSTRIDE 132

// modes: 0 = plain(+bias), 1 = silu(+bias), 2 = fused edge message, 3 = fused edge final
__global__ __launch_bounds__(256, 1)
void gemm_tc(const float* __restrict__ A, int M,
             const __nv_bfloat16* __restrict__ Bpack,
             const float* __restrict__ bias,
             float* __restrict__ C, int ldc, int mode,
             const int* __restrict__ ei,
             const float* __restrict__ dist,
             const float* __restrict__ alpha,
             const float* __restrict__ ev,
             const float* __restrict__ efeat,
             const float* __restrict__ naux) {
    extern __shared__ char smem[];
    const int tid = threadIdx.x;
    const int lane = tid & 31, wid = tid >> 5;
    const int warp_m = wid >> 2, warp_n = wid & 3;   // 2 x 4 warp grid
    const int row0 = blockIdx.x * 128;

    __nv_bfloat16* sAhi = (__nv_bfloat16*)(smem);
    __nv_bfloat16* sAlo = (__nv_bfloat16*)(smem + 34816);
    __nv_bfloat16* sBhi = (__nv_bfloat16*)(smem + 69632);
    __nv_bfloat16* sBlo = (__nv_bfloat16*)(smem + 104448);

    // ---- load + split A (each thread: one row-half = 64 floats) ----
    {
        int r = tid >> 1, k0 = (tid & 1) * 64;
        bool vr = (row0 + r) < M;
        const float4* src = (const float4*)(A + (size_t)(row0 + r) * 128 + k0);
        #pragma unroll
        for (int q = 0; q < 16; q++) {
            float4 a = vr ? __ldg(src + q) : make_float4(0.f, 0.f, 0.f, 0.f);
            __nv_bfloat162 h01 = __float22bfloat162_rn(make_float2(a.x, a.y));
            __nv_bfloat162 h23 = __float22bfloat162_rn(make_float2(a.z, a.w));
            float2 f01 = __bfloat1622float2(h01);
            float2 f23 = __bfloat1622float2(h23);
            __nv_bfloat162 l01 = __float22bfloat162_rn(make_float2(a.x - f01.x, a.y - f01.y));
            __nv_bfloat162 l23 = __float22bfloat162_rn(make_float2(a.z - f23.x, a.w - f23.y));
            int k = k0 + q * 4;
            uint2 hv, lv;
            hv.x = *(uint32_t*)&h01; hv.y = *(uint32_t*)&h23;
            lv.x = *(uint32_t*)&l01; lv.y = *(uint32_t*)&l23;
            *(uint2*)(&sAhi[r * ASTRIDE + k]) = hv;
            *(uint2*)(&sAlo[r * ASTRIDE + k]) = lv;
        }
    }
    // ---- load B (pre-split, [n][k] row-major) ----
    {
        int n = tid >> 1, k0 = (tid & 1) * 64;
        const uint4* srcH = (const uint4*)(Bpack + n * 128 + k0);
        const uint4* srcL = (const uint4*)(Bpack + 16384 + n * 128 + k0);
        uint4* dstH = (uint4*)(&sBhi[n * ASTRIDE + k0]);
        uint4* dstL = (uint4*)(&sBlo[n * ASTRIDE + k0]);
        #pragma unroll
        for (int q = 0; q < 8; q++) { dstH[q] = __ldg(srcH + q); dstL[q] = __ldg(srcL + q); }
    }
    __syncthreads();

    // ---- MMA mainloop ----
    float acc[4][4][4];
    #pragma unroll
    for (int mt = 0; mt < 4; mt++)
        #pragma unroll
        for (int nt = 0; nt < 4; nt++)
            #pragma unroll
            for (int u = 0; u < 4; u++) acc[mt][nt][u] = 0.f;

    const uint32_t sb = smem_u32(smem);
    const int rin = lane & 7, sel = lane >> 3;
    uint32_t aoff[4], boff[2];
    #pragma unroll
    for (int mt = 0; mt < 4; mt++) {
        int row = warp_m * 64 + mt * 16 + (sel & 1) * 8 + rin;
        int col = (sel >> 1) * 8;
        aoff[mt] = (uint32_t)((row * ASTRIDE + col) * 2);
    }
    #pragma unroll
    for (int nt2 = 0; nt2 < 2; nt2++) {
        int n = warp_n * 32 + nt2 * 16 + (sel >> 1) * 8 + rin;
        int col = (sel & 1) * 8;
        boff[nt2] = (uint32_t)((n * ASTRIDE + col) * 2);
    }
    const uint32_t aHi = sb, aLo = sb + 34816, bHi = sb + 69632, bLo = sb + 104448;

    #pragma unroll
    for (int ks = 0; ks < 8; ks++) {
        uint32_t kb = ks * 32;   // 16 k-elems * 2B
        uint32_t ah[4][4], al[4][4], bh[4][2], bl[4][2];
        #pragma unroll
        for (int mt = 0; mt < 4; mt++) {
            LDSM4(ah[mt], aHi + aoff[mt] + kb);
            LDSM4(al[mt], aLo + aoff[mt] + kb);
        }
        #pragma unroll
        for (int nt2 = 0; nt2 < 2; nt2++) {
            uint32_t t[4];
            LDSM4(t, bHi + boff[nt2] + kb);
            bh[nt2 * 2][0] = t[0]; bh[nt2 * 2][1] = t[1];
            bh[nt2 * 2 + 1][0] = t[2]; bh[nt2 * 2 + 1][1] = t[3];
            LDSM4(t, bLo + boff[nt2] + kb);
            bl[nt2 * 2][0] = t[0]; bl[nt2 * 2][1] = t[1];
            bl[nt2 * 2 + 1][0] = t[2]; bl[nt2 * 2 + 1][1] = t[3];
        }
        #pragma unroll
        for (int mt = 0; mt < 4; mt++)
            #pragma unroll
            for (int nt = 0; nt < 4; nt++) {
                MMA16816(acc[mt][nt], ah[mt], bh[nt]);
                MMA16816(acc[mt][nt], ah[mt], bl[nt]);
                MMA16816(acc[mt][nt], al[mt], bh[nt]);
            }
    }
    __syncthreads();

    // ---- stage C to smem (fp32, stride 132) ----
    float* Cs = (float*)smem;
    {
        int gid = lane >> 2, tig = lane & 3;
        #pragma unroll
        for (int mt = 0; mt < 4; mt++) {
            int r = warp_m * 64 + mt * 16 + gid;
            #pragma unroll
            for (int nt = 0; nt < 4; nt++) {
                int cc = warp_n * 32 + nt * 8 + tig * 2;
                *(float2*)&Cs[r * CSTRIDE + cc] = make_float2(acc[mt][nt][0], acc[mt][nt][1]);
                *(float2*)&Cs[(r + 8) * CSTRIDE + cc] = make_float2(acc[mt][nt][2], acc[mt][nt][3]);
            }
        }
    }
    __syncthreads();

    // ---- per-row epilogue: thread handles half a row (64 cols) ----
    const int r = tid >> 1;
    const int c0g = (tid & 1) * 64;
    const int grow = row0 + r;
    if (grow >= M) return;

    int ii = 0, jj = 0;
    float cut = 0.f, v0 = 0.f, v1 = 0.f, v2 = 0.f, vvq = 0.f;
    if (mode == 2) {
        ii = ei[grow]; jj = ei[N_EDGES + grow];
        float dd = __ldg(dist + grow);
        cut = (dd < CUTOFF_R) ? 0.5f * (__cosf(PI_F * dd / CUTOFF_R) + 1.0f) : 0.0f;
    } else if (mode == 3) {
        ii = ei[grow]; jj = ei[N_EDGES + grow];
        v0 = __ldg(ev + grow * 3 + 0); v1 = __ldg(ev + grow * 3 + 1); v2 = __ldg(ev + grow * 3 + 2);
        vvq = v0 * v0 + v1 * v1 + v2 * v2;
    }

    float* dst = C + (size_t)grow * ldc + c0g;

    #pragma unroll
    for (int ch = 0; ch < 4; ch++) {            // 16-col chunks (one head each)
        const int cl = c0g + ch * 16;           // col within this 128 tile
        float d[16];
        #pragma unroll
        for (int c = 0; c < 16; c++) d[c] = Cs[r * CSTRIDE + cl + c];
        if (bias) {
            #pragma unroll
            for (int c = 0; c < 16; c++) d[c] += __ldg(bias + cl + c);
        }

        if (mode == 0) {
            // nothing
        } else if (mode == 1) {
            #pragma unroll
            for (int c = 0; c < 16; c++) d[c] = silu_f(d[c]);
        } else if (mode == 2) {
            float nsi[16], nsj[16];
            const float4* pi4 = (const float4*)(naux + (size_t)ii * H + cl);
            const float4* pj4 = (const float4*)(naux + (size_t)jj * H + cl);
            #pragma unroll
            for (int q = 0; q < 4; q++) {
                float4 a = __ldg(pi4 + q);
                nsi[4*q] = a.x; nsi[4*q+1] = a.y; nsi[4*q+2] = a.z; nsi[4*q+3] = a.w;
                float4 b = __ldg(pj4 + q);
                nsj[4*q] = b.x; nsj[4*q+1] = b.y; nsj[4*q+2] = b.z; nsj[4*q+3] = b.w;
            }
            float s = 0.f;
            #pragma unroll
            for (int c = 0; c < 16; c++) {
                float ef = silu_f(d[c]);
                d[c] = ef;
                float x = nsi[c] + nsj[c] + ef;
                s += silu_f(x) * __ldg(alpha + cl + c);
            }
            float attn = s * cut;
            #pragma unroll
            for (int c = 0; c < 16; c++) d[c] = nsj[c] * d[c] * attn;
        } else {
            // mode 3: out = efeat + silu(gemm+b) * sum_phi  (Lagrange identity)
            const float* arow = naux + (size_t)ii * 3 * H;
            const float* brow = naux + (size_t)jj * 3 * H;
            #pragma unroll
            for (int q = 0; q < 4; q++) {
                int c = cl + 4 * q;
                float4 a0 = __ldg((const float4*)(arow + 0 * H + c));
                float4 a1 = __ldg((const float4*)(arow + 1 * H + c));
                float4 a2 = __ldg((const float4*)(arow + 2 * H + c));
                float4 b0 = __ldg((const float4*)(brow + 0 * H + c));
                float4 b1 = __ldg((const float4*)(brow + 1 * H + c));
                float4 b2 = __ldg((const float4*)(brow + 2 * H + c));
                float4 e4 = __ldg((const float4*)(efeat + (size_t)grow * H + c));
                #pragma unroll
                for (int u = 0; u < 4; u++) {
                    float ax = (&a0.x)[u], ay = (&a1.x)[u], az = (&a2.x)[u];
                    float bx = (&b0.x)[u], by = (&b1.x)[u], bz = (&b2.x)[u];
                    float ab = ax * bx + ay * by + az * bz;
                    float avd = ax * v0 + ay * v1 + az * v2;
                    float bvd = bx * v0 + by * v1 + bz * v2;
                    float sphi = ab * vvq - avd * bvd;
                    float gf = silu_f(d[4 * q + u]);
                    d[4 * q + u] = (&e4.x)[u] + gf * sphi;
                }
            }
        }

        #pragma unroll
        for (int q = 0; q < 4; q++)
            *(float4*)(dst + ch * 16 + 4 * q) =
                make_float4(d[4*q], d[4*q+1], d[4*q+2], d[4*q+3]);
    }
}

// ========================= layernorm =========================
__global__ void ln_kernel(const float* __restrict__ x,
                          const float* __restrict__ gamma,
                          const float* __restrict__ beta,
                          float* __restrict__ y) {
    int n = blockIdx.x;
    int h = threadIdx.x;
    float v = x[(size_t)n * H + h];
    float s = v, s2 = v * v;
    #pragma unroll
    for (int o = 16; o > 0; o >>= 1) {
        s  += __shfl_xor_sync(0xffffffffu, s, o);
        s2 += __shfl_xor_sync(0xffffffffu, s2, o);
    }
    __shared__ float rs[4], rs2[4];
    int warp = h >> 5, lane = h & 31;
    if (lane == 0) { rs[warp] = s; rs2[warp] = s2; }
    __syncthreads();
    float ts  = rs[0] + rs[1] + rs[2] + rs[3];
    float ts2 = rs2[0] + rs2[1] + rs2[2] + rs2[3];
    float mu  = ts * (1.0f / H);
    float var = ts2 * (1.0f / H) - mu * mu;
    float inv = rsqrtf(var + 1e-5f);
    y[(size_t)n * H + h] = (v - mu) * inv * gamma[h] + beta[h];
}

// ========================= CSR build =========================
__global__ void csr_zero() {
    int n = blockIdx.x * blockDim.x + threadIdx.x;
    if (n < N_NODES) g_deg[n] = 0;
}
__global__ void csr_hist(const int* __restrict__ ei) {
    int e = blockIdx.x * blockDim.x + threadIdx.x;
    if (e < N_EDGES) atomicAdd(&g_deg[ei[e]], 1);
}
__global__ void csr_scan() {
    __shared__ int sh[1024];
    __shared__ int carry;
    int tid = threadIdx.x;
    if (tid == 0) carry = 0;
    for (int base = 0; base < N_NODES; base += 1024) {
        __syncthreads();
        int c = carry;
        int idx = base + tid;
        int v = (idx < N_NODES) ? g_deg[idx] : 0;
        sh[tid] = v;
        __syncthreads();
        #pragma unroll
        for (int o = 1; o < 1024; o <<= 1) {
            int t = (tid >= o) ? sh[tid - o] : 0;
            __syncthreads();
            sh[tid] += t;
            __syncthreads();
        }
        if (idx < N_NODES) {
            int excl = c + sh[tid] - v;
            g_off[idx] = excl;
            g_cur[idx] = excl;
        }
        int tot = sh[1023];
        __syncthreads();
        if (tid == 0) carry = c + tot;
    }
    __syncthreads();
    if (tid == 0) g_off[N_NODES] = carry;
}
__global__ void csr_scatter(const int* __restrict__ ei) {
    int e = blockIdx.x * blockDim.x + threadIdx.x;
    if (e < N_EDGES) {
        int i = ei[e];
        int pos = atomicAdd(&g_cur[i], 1);
        g_eids[pos] = e;
    }
}

// ========================= aggregation =========================
__global__ void aggregate(const int* __restrict__ ei,
                          const float* __restrict__ ev,
                          const float* __restrict__ nscal,
                          const float* __restrict__ nvec) {
    int n = blockIdx.x;
    int h = threadIdx.x;
    float as = 0.0f, av0 = 0.0f, av1 = 0.0f, av2 = 0.0f;
    int beg = g_off[n], end = g_off[n + 1];
    for (int idx = beg; idx < end; idx++) {
        int e = g_eids[idx];
        int j = ei[N_EDGES + e];
        float m  = g_msg[(size_t)e * H + h];
        float sa = g_s[(size_t)e * 256 + h];
        float sb = g_s[(size_t)e * 256 + 128 + h];
        float e0 = ev[e * 3 + 0], e1 = ev[e * 3 + 1], e2 = ev[e * 3 + 2];
        as  += m;
        av0 += nvec[((size_t)j * 3 + 0) * H + h] * sa + sb * e0;
        av1 += nvec[((size_t)j * 3 + 1) * H + h] * sa + sb * e1;
        av2 += nvec[((size_t)j * 3 + 2) * H + h] * sa + sb * e2;
    }
    g_ns1[(size_t)n * H + h] = nscal[(size_t)n * H + h] + as;
    g_nvec1[((size_t)n * 3 + 0) * H + h] = nvec[((size_t)n * 3 + 0) * H + h] + av0;
    g_nvec1[((size_t)n * 3 + 1) * H + h] = nvec[((size_t)n * 3 + 1) * H + h] + av1;
    g_nvec1[((size_t)n * 3 + 2) * H + h] = nvec[((size_t)n * 3 + 2) * H + h] + av2;
}

// ========================= node final =========================
__global__ void node_final(float* __restrict__ out_scal,
                           float* __restrict__ out_vec) {
    int n = blockIdx.x;
    int h = threadIdx.x;
    float v1d[3], v2d[3];
    #pragma unroll
    for (int d = 0; d < 3; d++) {
        v1d[d] = g_wv[((size_t)n * 3 + d) * 256 + h];
        v2d[d] = g_wv[((size_t)n * 3 + d) * 256 + 128 + h];
    }
    float tri = v1d[0] * v2d[0] + v1d[1] * v2d[1] + v1d[2] * v2d[2];
    float sq  = v2d[0] * v2d[0] + v2d[1] * v2d[1] + v2d[2] * v2d[2];
    float nrm = sqrtf(sq + 1e-8f);
    float qua = nrm * nrm * nrm;
    float p1 = g_p[(size_t)n * 384 + h];
    float p2 = g_p[(size_t)n * 384 + 128 + h];
    float p3 = g_p[(size_t)n * 384 + 256 + h];
    out_scal[(size_t)n * H + h] = g_ns1[(size_t)n * H + h] + (qua + tri) * p1 + p2;
    #pragma unroll
    for (int d = 0; d < 3; d++) {
        out_vec[((size_t)n * 3 + d) * H + h] =
            g_nvec1[((size_t)n * 3 + d) * H + h] + v1d[d] * p3;
    }
}

// ========================= launch =========================
extern "C" void kernel_launch(void* const* d_in, const int* in_sizes, int n_in,
                              void* d_out, int out_size) {
    const float* node_scalar = (const float*)d_in[0];
    const float* node_vector = (const float*)d_in[1];
    const int*   edge_index  = (const int*)  d_in[2];
    const float* dist        = (const float*)d_in[3];
    const float* edge_feats  = (const float*)d_in[4];
    const float* edge_vector = (const float*)d_in[5];
    const float* ln_gamma    = (const float*)d_in[6];
    const float* ln_beta     = (const float*)d_in[7];
    const float* alpha       = (const float*)d_in[8];
    const float* W_cross     = (const float*)d_in[9];
    const float* W_node      = (const float*)d_in[10];
    const float* b_node      = (const float*)d_in[11];
    const float* W_edge      = (const float*)d_in[12];
    const float* b_edge      = (const float*)d_in[13];
    const float* W_p1        = (const float*)d_in[14];
    const float* b_p1        = (const float*)d_in[15];
    const float* W_p2        = (const float*)d_in[16];
    const float* b_p2        = (const float*)d_in[17];
    const float* W_vec       = (const float*)d_in[18];
    const float* W_f         = (const float*)d_in[19];
    const float* b_f         = (const float*)d_in[20];

    float* out = (float*)d_out;
    float* out_scal = out;
    float* out_vec  = out + (size_t)N_NODES * H;
    float* out_edge = out + (size_t)N_NODES * H * 4;

    float* p_scalar_out; cudaGetSymbolAddress((void**)&p_scalar_out, g_scalar_out);
    float* p_ns;    cudaGetSymbolAddress((void**)&p_ns, g_ns);
    float* p_msg;   cudaGetSymbolAddress((void**)&p_msg, g_msg);
    float* p_s;     cudaGetSymbolAddress((void**)&p_s, g_s);
    float* p_nv;    cudaGetSymbolAddress((void**)&p_nv, g_nv);
    float* p_ns1;   cudaGetSymbolAddress((void**)&p_ns1, g_ns1);
    float* p_nvec1; cudaGetSymbolAddress((void**)&p_nvec1, g_nvec1);
    float* p_wv;    cudaGetSymbolAddress((void**)&p_wv, g_wv);
    float* p_p;     cudaGetSymbolAddress((void**)&p_p, g_p);
    __nv_bfloat16* wp; cudaGetSymbolAddress((void**)&wp, g_wpack);

    cudaFuncSetAttribute(gemm_tc, cudaFuncAttributeMaxDynamicSharedMemorySize, SM_TOTAL);

    const int GB_N  = (N_NODES + 127) / 128;       // 157
    const int GB_E  = N_EDGES / 128;               // 2500
    const int GB_3N = (3 * N_NODES + 127) / 128;   // 469

    // weight pre-pack (tiles: node=0, edge=1, p1=2..3, cross=4, f=5, vec=6..7, p2=8..10)
    pack_w<<<1, 256>>>(W_node, 128, 0);
    pack_w<<<1, 256>>>(W_edge, 128, 1);
    pack_w<<<2, 256>>>(W_p1, 256, 2);
    pack_w<<<1, 256>>>(W_cross, 128, 4);
    pack_w<<<1, 256>>>(W_f, 128, 5);
    pack_w<<<2, 256>>>(W_vec, 256, 6);
    pack_w<<<3, 256>>>(W_p2, 384, 8);

    // CSR build
    csr_zero<<<(N_NODES + 255) / 256, 256>>>();
    csr_hist<<<(N_EDGES + 255) / 256, 256>>>(edge_index);
    csr_scan<<<1, 1024>>>();
    csr_scatter<<<(N_EDGES + 255) / 256, 256>>>(edge_index);

    // scalar path
    ln_kernel<<<N_NODES, 128>>>(node_scalar, ln_gamma, ln_beta, p_scalar_out);
    gemm_tc<<<GB_N, 256, SM_TOTAL>>>(p_scalar_out, N_NODES, wp + 0 * 32768, b_node,
                                     p_ns, 128, 0, nullptr, nullptr, nullptr, nullptr, nullptr, nullptr);
    // fused: ef GEMM + silu + attention + message
    gemm_tc<<<GB_E, 256, SM_TOTAL>>>(edge_feats, N_EDGES, wp + 1 * 32768, b_edge,
                                     p_msg, 128, 2, edge_index, dist, alpha, nullptr, nullptr, p_ns);
    // s = silu(msg @ W_p1 + b), two n-tiles
    gemm_tc<<<GB_E, 256, SM_TOTAL>>>(p_msg, N_EDGES, wp + 2 * 32768, b_p1,
                                     p_s, 256, 1, nullptr, nullptr, nullptr, nullptr, nullptr, nullptr);
    gemm_tc<<<GB_E, 256, SM_TOTAL>>>(p_msg, N_EDGES, wp + 3 * 32768, b_p1 + 128,
                                     p_s + 128, 256, 1, nullptr, nullptr, nullptr, nullptr, nullptr, nullptr);
    aggregate<<<N_NODES, 128>>>(edge_index, edge_vector, node_scalar, node_vector);

    // edge update (uses ORIGINAL node_vector)
    gemm_tc<<<GB_3N, 256, SM_TOTAL>>>(node_vector, 3 * N_NODES, wp + 4 * 32768, nullptr,
                                      p_nv, 128, 0, nullptr, nullptr, nullptr, nullptr, nullptr, nullptr);
    // fused: gf GEMM + silu + cross-product contraction + residual
    gemm_tc<<<GB_E, 256, SM_TOTAL>>>(edge_feats, N_EDGES, wp + 5 * 32768, b_f,
                                     out_edge, 128, 3, edge_index, nullptr, nullptr,
                                     edge_vector, edge_feats, p_nv);

    // node update
    gemm_tc<<<GB_3N, 256, SM_TOTAL>>>(p_nvec1, 3 * N_NODES, wp + 6 * 32768, nullptr,
                                      p_wv, 256, 0, nullptr, nullptr, nullptr, nullptr, nullptr, nullptr);
    gemm_tc<<<GB_3N, 256, SM_TOTAL>>>(p_nvec1, 3 * N_NODES, wp + 7 * 32768, nullptr,
                                      p_wv + 128, 256, 0, nullptr, nullptr, nullptr, nullptr, nullptr, nullptr);
    gemm_tc<<<GB_N, 256, SM_TOTAL>>>(p_ns1, N_NODES, wp + 8 * 32768, b_p2,
                                     p_p, 384, 0, nullptr, nullptr, nullptr, nullptr, nullptr, nullptr);
    gemm_tc<<<GB_N, 256, SM_TOTAL>>>(p_ns1, N_NODES, wp + 9 * 32768, b_p2 + 128,
                                     p_p + 128, 384, 0, nullptr, nullptr, nullptr, nullptr, nullptr, nullptr);
    gemm_tc<<<GB_N, 256, SM_TOTAL>>>(p_ns1, N_NODES, wp + 10 * 32768, b_p2 + 256,
                                     p_p + 256, 384, 0, nullptr, nullptr, nullptr, nullptr, nullptr, nullptr);
    node_final<<<N_NODES, 128>>>(out_scal, out_vec);
}

// round 4
// speedup vs baseline: 1.0110x; 1.0110x over previous
#include <cuda_runtime.h>
#include <cuda_bf16.h>
#include <math.h>
#include <stdint.h>

#define N_NODES 20000
#define N_EDGES 320000
#define H 128
#define CUTOFF_R 5.0f
#define PI_F 3.14159265358979323846f

// ========================= scratch (device globals) =========================
__device__ __align__(16) float g_scalar_out[N_NODES * H];
__device__ __align__(16) float g_ns[N_NODES * H];
__device__ __align__(16) float g_msg[N_EDGES * H];
__device__ __align__(16) float g_s[N_EDGES * 2 * H];
__device__ __align__(16) float g_nv[N_NODES * 3 * H];
__device__ __align__(16) float g_ns1[N_NODES * H];
__device__ __align__(16) float g_nvec1[N_NODES * 3 * H];
__device__ __align__(16) float g_wv[N_NODES * 3 * 2 * H];
__device__ __align__(16) float g_p[N_NODES * 3 * H];
// packed weights: 11 tiles, each = 16384 hi bf16 [n*128+k] then 16384 lo bf16
__device__ __align__(16) __nv_bfloat16 g_wpack[11 * 32768];

__device__ int g_deg[N_NODES];
__device__ int g_off[N_NODES + 1];
__device__ int g_cur[N_NODES];
__device__ int g_eids[N_EDGES];

// ========================= helpers =========================
__device__ __forceinline__ uint32_t smem_u32(const void* p) {
    uint32_t a;
    asm("{ .reg .u64 t; cvta.to.shared.u64 t, %1; cvt.u32.u64 %0, t; }" : "=r"(a) : "l"(p));
    return a;
}
__device__ __forceinline__ float silu_f(float x) { return x / (1.0f + __expf(-x)); }

#define LDSM4(r, addr) \
    asm volatile("ldmatrix.sync.aligned.m8n8.x4.shared.b16 {%0,%1,%2,%3}, [%4];" \
        : "=r"((r)[0]), "=r"((r)[1]), "=r"((r)[2]), "=r"((r)[3]) : "r"(addr))

#define MMA16816(c, a, b) \
    asm volatile("mma.sync.aligned.m16n8k16.row.col.f32.bf16.bf16.f32 " \
        "{%0,%1,%2,%3}, {%4,%5,%6,%7}, {%8,%9}, {%0,%1,%2,%3};" \
        : "+f"((c)[0]), "+f"((c)[1]), "+f"((c)[2]), "+f"((c)[3]) \
        : "r"((a)[0]), "r"((a)[1]), "r"((a)[2]), "r"((a)[3]), "r"((b)[0]), "r"((b)[1]))

#define CP_ASYNC16(dst, src) \
    asm volatile("cp.async.cg.shared.global [%0], [%1], 16;" :: "r"(dst), "l"(src))
#define CP_COMMIT() asm volatile("cp.async.commit_group;")
#define CP_WAIT0()  asm volatile("cp.async.wait_group 0;")

// ========================= weight pre-pack: Bt[n][k] hi/lo bf16 ==============
__global__ void pack_w(const float* __restrict__ W, int NCOL, int tile0) {
    int t = blockIdx.x;
    __nv_bfloat16* dst = g_wpack + (size_t)(tile0 + t) * 32768;
    int base = blockIdx.y * 2048;
    #pragma unroll
    for (int it = 0; it < 8; it++) {
        int lin = base + threadIdx.x + it * 256;   // lin = n*128 + k
        int n = lin >> 7, k = lin & 127;
        float v = W[(size_t)k * NCOL + t * 128 + n];
        __nv_bfloat16 h = __float2bfloat16(v);
        __nv_bfloat16 l = __float2bfloat16(v - __bfloat162float(h));
        dst[lin] = h;
        dst[16384 + lin] = l;
    }
}

// ========================= HMMA GEMM (64x128x128 tile, bf16x3 split) =========
// smem (bytes): A_hi @0 (17408), A_lo @17408, B_hi @34816 (34816), B_lo @69632
// total 104448 -> 2 CTAs/SM. C staged fp32 in A region (64*132*4 = 33792).
#define SM_TOTAL 104448
#define ASTRIDE 136
#define CSTRIDE 132

// modes: 0 = plain(+bias), 1 = silu(+bias), 2 = fused edge message, 3 = fused edge final
__global__ __launch_bounds__(256, 2)
void gemm_tc(const float* __restrict__ A, int M,
             const __nv_bfloat16* __restrict__ Bpack0,
             const float* __restrict__ bias0,
             float* __restrict__ C, int ldc, int mode,
             const int* __restrict__ ei,
             const float* __restrict__ dist,
             const float* __restrict__ alpha,
             const float* __restrict__ ev,
             const float* __restrict__ efeat,
             const float* __restrict__ naux) {
    extern __shared__ char smem[];
    const int tid = threadIdx.x;
    const int lane = tid & 31, wid = tid >> 5;
    const int warp_m = wid >> 2, warp_n = wid & 3;   // 2m x 4n warps
    const int row0 = blockIdx.x * 64;
    const int ytile = blockIdx.y;
    const __nv_bfloat16* Bpack = Bpack0 + (size_t)ytile * 32768;
    const float* bias = bias0 ? bias0 + ytile * 128 : nullptr;

    const uint32_t sb = smem_u32(smem);
    const uint32_t aHi = sb, aLo = sb + 17408, bHi = sb + 34816, bLo = sb + 69632;

    // ---- B tile via cp.async (pre-split bf16, [n][k] row-major) ----
    {
        int n = tid >> 1, k0 = (tid & 1) * 64;
        const __nv_bfloat16* srcH = Bpack + n * 128 + k0;
        const __nv_bfloat16* srcL = srcH + 16384;
        uint32_t dH = bHi + (uint32_t)(n * ASTRIDE + k0) * 2;
        uint32_t dL = bLo + (uint32_t)(n * ASTRIDE + k0) * 2;
        #pragma unroll
        for (int q = 0; q < 8; q++) {
            CP_ASYNC16(dH + q * 16, srcH + q * 8);
            CP_ASYNC16(dL + q * 16, srcL + q * 8);
        }
        CP_COMMIT();
    }

    // ---- A tile: fp32 -> (hi, lo) bf16 (each thread: 32 floats of one row) ----
    {
        int r = tid >> 2, k0 = (tid & 3) * 32;
        bool vr = (row0 + r) < M;
        const float4* src = (const float4*)(A + (size_t)(row0 + r) * 128 + k0);
        float4 av[8];
        #pragma unroll
        for (int q = 0; q < 8; q++)
            av[q] = vr ? __ldg(src + q) : make_float4(0.f, 0.f, 0.f, 0.f);
        #pragma unroll
        for (int q = 0; q < 8; q++) {
            float4 a = av[q];
            __nv_bfloat162 h01 = __float22bfloat162_rn(make_float2(a.x, a.y));
            __nv_bfloat162 h23 = __float22bfloat162_rn(make_float2(a.z, a.w));
            float2 f01 = __bfloat1622float2(h01);
            float2 f23 = __bfloat1622float2(h23);
            __nv_bfloat162 l01 = __float22bfloat162_rn(make_float2(a.x - f01.x, a.y - f01.y));
            __nv_bfloat162 l23 = __float22bfloat162_rn(make_float2(a.z - f23.x, a.w - f23.y));
            int k = k0 + q * 4;
            uint2 hv, lv;
            hv.x = *(uint32_t*)&h01; hv.y = *(uint32_t*)&h23;
            lv.x = *(uint32_t*)&l01; lv.y = *(uint32_t*)&l23;
            *(uint2*)(smem + (aHi - sb) + (r * ASTRIDE + k) * 2) = hv;
            *(uint2*)(smem + (aLo - sb) + (r * ASTRIDE + k) * 2) = lv;
        }
    }
    CP_WAIT0();
    __syncthreads();

    // ---- MMA mainloop ----
    float acc[2][4][4];
    #pragma unroll
    for (int mt = 0; mt < 2; mt++)
        #pragma unroll
        for (int nt = 0; nt < 4; nt++)
            #pragma unroll
            for (int u = 0; u < 4; u++) acc[mt][nt][u] = 0.f;

    const int rin = lane & 7, sel = lane >> 3;
    uint32_t aoff[2], boff[2];
    #pragma unroll
    for (int mt = 0; mt < 2; mt++) {
        int row = warp_m * 32 + mt * 16 + (sel & 1) * 8 + rin;
        int col = (sel >> 1) * 8;
        aoff[mt] = (uint32_t)((row * ASTRIDE + col) * 2);
    }
    #pragma unroll
    for (int nt2 = 0; nt2 < 2; nt2++) {
        int n = warp_n * 32 + nt2 * 16 + (sel >> 1) * 8 + rin;
        int col = (sel & 1) * 8;
        boff[nt2] = (uint32_t)((n * ASTRIDE + col) * 2);
    }

    #pragma unroll
    for (int ks = 0; ks < 8; ks++) {
        uint32_t kb = ks * 32;   // 16 k-elems * 2B
        uint32_t ah[2][4], al[2][4], bh[4][2], bl[4][2];
        #pragma unroll
        for (int mt = 0; mt < 2; mt++) {
            LDSM4(ah[mt], aHi + aoff[mt] + kb);
            LDSM4(al[mt], aLo + aoff[mt] + kb);
        }
        #pragma unroll
        for (int nt2 = 0; nt2 < 2; nt2++) {
            uint32_t t[4];
            LDSM4(t, bHi + boff[nt2] + kb);
            bh[nt2 * 2][0] = t[0]; bh[nt2 * 2][1] = t[1];
            bh[nt2 * 2 + 1][0] = t[2]; bh[nt2 * 2 + 1][1] = t[3];
            LDSM4(t, bLo + boff[nt2] + kb);
            bl[nt2 * 2][0] = t[0]; bl[nt2 * 2][1] = t[1];
            bl[nt2 * 2 + 1][0] = t[2]; bl[nt2 * 2 + 1][1] = t[3];
        }
        #pragma unroll
        for (int mt = 0; mt < 2; mt++)
            #pragma unroll
            for (int nt = 0; nt < 4; nt++) {
                MMA16816(acc[mt][nt], ah[mt], bh[nt]);
                MMA16816(acc[mt][nt], ah[mt], bl[nt]);
                MMA16816(acc[mt][nt], al[mt], bh[nt]);
            }
    }
    __syncthreads();

    // ---- stage C to smem fp32 (reuses A region) ----
    float* Cs = (float*)smem;
    {
        int gid = lane >> 2, tig = lane & 3;
        #pragma unroll
        for (int mt = 0; mt < 2; mt++) {
            int r = warp_m * 32 + mt * 16 + gid;
            #pragma unroll
            for (int nt = 0; nt < 4; nt++) {
                int cc = warp_n * 32 + nt * 8 + tig * 2;
                *(float2*)&Cs[r * CSTRIDE + cc] = make_float2(acc[mt][nt][0], acc[mt][nt][1]);
                *(float2*)&Cs[(r + 8) * CSTRIDE + cc] = make_float2(acc[mt][nt][2], acc[mt][nt][3]);
            }
        }
    }
    __syncthreads();

    // ---- per-row epilogue: thread handles 32 cols (2 heads) of one row ----
    const int r = tid >> 2;
    const int c0g = (tid & 3) * 32;
    const int grow = row0 + r;
    if (grow >= M) return;

    int ii = 0, jj = 0;
    float cut = 0.f, v0 = 0.f, v1 = 0.f, v2 = 0.f, vvq = 0.f;
    if (mode == 2) {
        ii = ei[grow]; jj = ei[N_EDGES + grow];
        float dd = __ldg(dist + grow);
        cut = (dd < CUTOFF_R) ? 0.5f * (__cosf(PI_F * dd / CUTOFF_R) + 1.0f) : 0.0f;
    } else if (mode == 3) {
        ii = ei[grow]; jj = ei[N_EDGES + grow];
        v0 = __ldg(ev + grow * 3 + 0); v1 = __ldg(ev + grow * 3 + 1); v2 = __ldg(ev + grow * 3 + 2);
        vvq = v0 * v0 + v1 * v1 + v2 * v2;
    }

    float* dst = C + (size_t)grow * ldc + ytile * 128 + c0g;

    #pragma unroll
    for (int ch = 0; ch < 2; ch++) {            // two 16-col head chunks
        const int cl = c0g + ch * 16;
        float d[16];
        #pragma unroll
        for (int c = 0; c < 16; c++) d[c] = Cs[r * CSTRIDE + cl + c];
        if (bias) {
            #pragma unroll
            for (int c = 0; c < 16; c++) d[c] += __ldg(bias + cl + c);
        }

        if (mode == 1) {
            #pragma unroll
            for (int c = 0; c < 16; c++) d[c] = silu_f(d[c]);
        } else if (mode == 2) {
            float nsi[16], nsj[16];
            const float4* pi4 = (const float4*)(naux + (size_t)ii * H + cl);
            const float4* pj4 = (const float4*)(naux + (size_t)jj * H + cl);
            #pragma unroll
            for (int q = 0; q < 4; q++) {
                float4 a = __ldg(pi4 + q);
                nsi[4*q] = a.x; nsi[4*q+1] = a.y; nsi[4*q+2] = a.z; nsi[4*q+3] = a.w;
                float4 b = __ldg(pj4 + q);
                nsj[4*q] = b.x; nsj[4*q+1] = b.y; nsj[4*q+2] = b.z; nsj[4*q+3] = b.w;
            }
            float s = 0.f;
            #pragma unroll
            for (int c = 0; c < 16; c++) {
                float ef = silu_f(d[c]);
                d[c] = ef;
                float x = nsi[c] + nsj[c] + ef;
                s += silu_f(x) * __ldg(alpha + cl + c);
            }
            float attn = s * cut;
            #pragma unroll
            for (int c = 0; c < 16; c++) d[c] = nsj[c] * d[c] * attn;
        } else if (mode == 3) {
            const float* arow = naux + (size_t)ii * 3 * H;
            const float* brow = naux + (size_t)jj * 3 * H;
            #pragma unroll
            for (int q = 0; q < 4; q++) {
                int c = cl + 4 * q;
                float4 a0 = __ldg((const float4*)(arow + 0 * H + c));
                float4 a1 = __ldg((const float4*)(arow + 1 * H + c));
                float4 a2 = __ldg((const float4*)(arow + 2 * H + c));
                float4 b0 = __ldg((const float4*)(brow + 0 * H + c));
                float4 b1 = __ldg((const float4*)(brow + 1 * H + c));
                float4 b2 = __ldg((const float4*)(brow + 2 * H + c));
                float4 e4 = __ldg((const float4*)(efeat + (size_t)grow * H + c));
                #pragma unroll
                for (int u = 0; u < 4; u++) {
                    float ax = (&a0.x)[u], ay = (&a1.x)[u], az = (&a2.x)[u];
                    float bx = (&b0.x)[u], by = (&b1.x)[u], bz = (&b2.x)[u];
                    float ab = ax * bx + ay * by + az * bz;
                    float avd = ax * v0 + ay * v1 + az * v2;
                    float bvd = bx * v0 + by * v1 + bz * v2;
                    float sphi = ab * vvq - avd * bvd;
                    float gf = silu_f(d[4 * q + u]);
                    d[4 * q + u] = (&e4.x)[u] + gf * sphi;
                }
            }
        }

        #pragma unroll
        for (int q = 0; q < 4; q++)
            *(float4*)(dst + ch * 16 + 4 * q) =
                make_float4(d[4*q], d[4*q+1], d[4*q+2], d[4*q+3]);
    }
}

// ========================= layernorm =========================
__global__ void ln_kernel(const float* __restrict__ x,
                          const float* __restrict__ gamma,
                          const float* __restrict__ beta,
                          float* __restrict__ y) {
    int n = blockIdx.x;
    int h = threadIdx.x;
    float v = x[(size_t)n * H + h];
    float s = v, s2 = v * v;
    #pragma unroll
    for (int o = 16; o > 0; o >>= 1) {
        s  += __shfl_xor_sync(0xffffffffu, s, o);
        s2 += __shfl_xor_sync(0xffffffffu, s2, o);
    }
    __shared__ float rs[4], rs2[4];
    int warp = h >> 5, lane = h & 31;
    if (lane == 0) { rs[warp] = s; rs2[warp] = s2; }
    __syncthreads();
    float ts  = rs[0] + rs[1] + rs[2] + rs[3];
    float ts2 = rs2[0] + rs2[1] + rs2[2] + rs2[3];
    float mu  = ts * (1.0f / H);
    float var = ts2 * (1.0f / H) - mu * mu;
    float inv = rsqrtf(var + 1e-5f);
    y[(size_t)n * H + h] = (v - mu) * inv * gamma[h] + beta[h];
}

// ========================= CSR build =========================
__global__ void csr_zero() {
    int n = blockIdx.x * blockDim.x + threadIdx.x;
    if (n < N_NODES) g_deg[n] = 0;
}
__global__ void csr_hist(const int* __restrict__ ei) {
    int e = blockIdx.x * blockDim.x + threadIdx.x;
    if (e < N_EDGES) atomicAdd(&g_deg[ei[e]], 1);
}
__global__ void csr_scan() {
    __shared__ int sh[1024];
    __shared__ int carry;
    int tid = threadIdx.x;
    if (tid == 0) carry = 0;
    for (int base = 0; base < N_NODES; base += 1024) {
        __syncthreads();
        int c = carry;
        int idx = base + tid;
        int v = (idx < N_NODES) ? g_deg[idx] : 0;
        sh[tid] = v;
        __syncthreads();
        #pragma unroll
        for (int o = 1; o < 1024; o <<= 1) {
            int t = (tid >= o) ? sh[tid - o] : 0;
            __syncthreads();
            sh[tid] += t;
            __syncthreads();
        }
        if (idx < N_NODES) {
            int excl = c + sh[tid] - v;
            g_off[idx] = excl;
            g_cur[idx] = excl;
        }
        int tot = sh[1023];
        __syncthreads();
        if (tid == 0) carry = c + tot;
    }
    __syncthreads();
    if (tid == 0) g_off[N_NODES] = carry;
}
__global__ void csr_scatter(const int* __restrict__ ei) {
    int e = blockIdx.x * blockDim.x + threadIdx.x;
    if (e < N_EDGES) {
        int i = ei[e];
        int pos = atomicAdd(&g_cur[i], 1);
        g_eids[pos] = e;
    }
}

// ========================= aggregation =========================
__global__ void aggregate(const int* __restrict__ ei,
                          const float* __restrict__ ev,
                          const float* __restrict__ nscal,
                          const float* __restrict__ nvec) {
    int n = blockIdx.x;
    int h = threadIdx.x;
    float as = 0.0f, av0 = 0.0f, av1 = 0.0f, av2 = 0.0f;
    int beg = g_off[n], end = g_off[n + 1];
    for (int idx = beg; idx < end; idx++) {
        int e = g_eids[idx];
        int j = ei[N_EDGES + e];
        float m  = g_msg[(size_t)e * H + h];
        float sa = g_s[(size_t)e * 256 + h];
        float sb = g_s[(size_t)e * 256 + 128 + h];
        float e0 = ev[e * 3 + 0], e1 = ev[e * 3 + 1], e2 = ev[e * 3 + 2];
        as  += m;
        av0 += nvec[((size_t)j * 3 + 0) * H + h] * sa + sb * e0;
        av1 += nvec[((size_t)j * 3 + 1) * H + h] * sa + sb * e1;
        av2 += nvec[((size_t)j * 3 + 2) * H + h] * sa + sb * e2;
    }
    g_ns1[(size_t)n * H + h] = nscal[(size_t)n * H + h] + as;
    g_nvec1[((size_t)n * 3 + 0) * H + h] = nvec[((size_t)n * 3 + 0) * H + h] + av0;
    g_nvec1[((size_t)n * 3 + 1) * H + h] = nvec[((size_t)n * 3 + 1) * H + h] + av1;
    g_nvec1[((size_t)n * 3 + 2) * H + h] = nvec[((size_t)n * 3 + 2) * H + h] + av2;
}

// ========================= node final =========================
__global__ void node_final(float* __restrict__ out_scal,
                           float* __restrict__ out_vec) {
    int n = blockIdx.x;
    int h = threadIdx.x;
    float v1d[3], v2d[3];
    #pragma unroll
    for (int d = 0; d < 3; d++) {
        v1d[d] = g_wv[((size_t)n * 3 + d) * 256 + h];
        v2d[d] = g_wv[((size_t)n * 3 + d) * 256 + 128 + h];
    }
    float tri = v1d[0] * v2d[0] + v1d[1] * v2d[1] + v1d[2] * v2d[2];
    float sq  = v2d[0] * v2d[0] + v2d[1] * v2d[1] + v2d[2] * v2d[2];
    float nrm = sqrtf(sq + 1e-8f);
    float qua = nrm * nrm * nrm;
    float p1 = g_p[(size_t)n * 384 + h];
    float p2 = g_p[(size_t)n * 384 + 128 + h];
    float p3 = g_p[(size_t)n * 384 + 256 + h];
    out_scal[(size_t)n * H + h] = g_ns1[(size_t)n * H + h] + (qua + tri) * p1 + p2;
    #pragma unroll
    for (int d = 0; d < 3; d++) {
        out_vec[((size_t)n * 3 + d) * H + h] =
            g_nvec1[((size_t)n * 3 + d) * H + h] + v1d[d] * p3;
    }
}

// ========================= launch =========================
extern "C" void kernel_launch(void* const* d_in, const int* in_sizes, int n_in,
                              void* d_out, int out_size) {
    const float* node_scalar = (const float*)d_in[0];
    const float* node_vector = (const float*)d_in[1];
    const int*   edge_index  = (const int*)  d_in[2];
    const float* dist        = (const float*)d_in[3];
    const float* edge_feats  = (const float*)d_in[4];
    const float* edge_vector = (const float*)d_in[5];
    const float* ln_gamma    = (const float*)d_in[6];
    const float* ln_beta     = (const float*)d_in[7];
    const float* alpha       = (const float*)d_in[8];
    const float* W_cross     = (const float*)d_in[9];
    const float* W_node      = (const float*)d_in[10];
    const float* b_node      = (const float*)d_in[11];
    const float* W_edge      = (const float*)d_in[12];
    const float* b_edge      = (const float*)d_in[13];
    const float* W_p1        = (const float*)d_in[14];
    const float* b_p1        = (const float*)d_in[15];
    const float* W_p2        = (const float*)d_in[16];
    const float* b_p2        = (const float*)d_in[17];
    const float* W_vec       = (const float*)d_in[18];
    const float* W_f         = (const float*)d_in[19];
    const float* b_f         = (const float*)d_in[20];

    float* out = (float*)d_out;
    float* out_scal = out;
    float* out_vec  = out + (size_t)N_NODES * H;
    float* out_edge = out + (size_t)N_NODES * H * 4;

    float* p_scalar_out; cudaGetSymbolAddress((void**)&p_scalar_out, g_scalar_out);
    float* p_ns;    cudaGetSymbolAddress((void**)&p_ns, g_ns);
    float* p_msg;   cudaGetSymbolAddress((void**)&p_msg, g_msg);
    float* p_s;     cudaGetSymbolAddress((void**)&p_s, g_s);
    float* p_nv;    cudaGetSymbolAddress((void**)&p_nv, g_nv);
    float* p_ns1;   cudaGetSymbolAddress((void**)&p_ns1, g_ns1);
    float* p_nvec1; cudaGetSymbolAddress((void**)&p_nvec1, g_nvec1);
    float* p_wv;    cudaGetSymbolAddress((void**)&p_wv, g_wv);
    float* p_p;     cudaGetSymbolAddress((void**)&p_p, g_p);
    __nv_bfloat16* wp; cudaGetSymbolAddress((void**)&wp, g_wpack);

    cudaFuncSetAttribute(gemm_tc, cudaFuncAttributeMaxDynamicSharedMemorySize, SM_TOTAL);

    const int GB_N  = (N_NODES + 63) / 64;        // 313
    const int GB_E  = N_EDGES / 64;               // 5000
    const int GB_3N = (3 * N_NODES + 63) / 64;    // 938

    // weight pre-pack (tiles: node=0, edge=1, p1=2..3, cross=4, f=5, vec=6..7, p2=8..10)
    pack_w<<<dim3(1, 8), 256>>>(W_node, 128, 0);
    pack_w<<<dim3(1, 8), 256>>>(W_edge, 128, 1);
    pack_w<<<dim3(2, 8), 256>>>(W_p1, 256, 2);
    pack_w<<<dim3(1, 8), 256>>>(W_cross, 128, 4);
    pack_w<<<dim3(1, 8), 256>>>(W_f, 128, 5);
    pack_w<<<dim3(2, 8), 256>>>(W_vec, 256, 6);
    pack_w<<<dim3(3, 8), 256>>>(W_p2, 384, 8);

    // CSR build
    csr_zero<<<(N_NODES + 255) / 256, 256>>>();
    csr_hist<<<(N_EDGES + 255) / 256, 256>>>(edge_index);
    csr_scan<<<1, 1024>>>();
    csr_scatter<<<(N_EDGES + 255) / 256, 256>>>(edge_index);

    // scalar path
    ln_kernel<<<N_NODES, 128>>>(node_scalar, ln_gamma, ln_beta, p_scalar_out);
    gemm_tc<<<dim3(GB_N, 1), 256, SM_TOTAL>>>(p_scalar_out, N_NODES, wp + 0 * 32768, b_node,
                                              p_ns, 128, 0, nullptr, nullptr, nullptr, nullptr, nullptr, nullptr);
    // fused: ef GEMM + silu + attention + message
    gemm_tc<<<dim3(GB_E, 1), 256, SM_TOTAL>>>(edge_feats, N_EDGES, wp + 1 * 32768, b_edge,
                                              p_msg, 128, 2, edge_index, dist, alpha, nullptr, nullptr, p_ns);
    // s = silu(msg @ W_p1 + b): both 128-col tiles in ONE launch
    gemm_tc<<<dim3(GB_E, 2), 256, SM_TOTAL>>>(p_msg, N_EDGES, wp + 2 * 32768, b_p1,
                                              p_s, 256, 1, nullptr, nullptr, nullptr, nullptr, nullptr, nullptr);
    aggregate<<<N_NODES, 128>>>(edge_index, edge_vector, node_scalar, node_vector);

    // edge update (uses ORIGINAL node_vector)
    gemm_tc<<<dim3(GB_3N, 1), 256, SM_TOTAL>>>(node_vector, 3 * N_NODES, wp + 4 * 32768, nullptr,
                                               p_nv, 128, 0, nullptr, nullptr, nullptr, nullptr, nullptr, nullptr);
    // fused: gf GEMM + silu + cross-product contraction + residual
    gemm_tc<<<dim3(GB_E, 1), 256, SM_TOTAL>>>(edge_feats, N_EDGES, wp + 5 * 32768, b_f,
                                              out_edge, 128, 3, edge_index, nullptr, nullptr,
                                              edge_vector, edge_feats, p_nv);

    // node update
    gemm_tc<<<dim3(GB_3N, 2), 256, SM_TOTAL>>>(p_nvec1, 3 * N_NODES, wp + 6 * 32768, nullptr,
                                               p_wv, 256, 0, nullptr, nullptr, nullptr, nullptr, nullptr, nullptr);
    gemm_tc<<<dim3(GB_N, 3), 256, SM_TOTAL>>>(p_ns1, N_NODES, wp + 8 * 32768, b_p2,
                                              p_p, 384, 0, nullptr, nullptr, nullptr, nullptr, nullptr, nullptr);
    node_final<<<N_NODES, 128>>>(out_scal, out_vec);
}

// round 5
// speedup vs baseline: 1.1201x; 1.1079x over previous
#include <cuda_runtime.h>
#include <cuda_bf16.h>
#include <math.h>
#include <stdint.h>

#define N_NODES 20000
#define N_EDGES 320000
#define H 128
#define CUTOFF_R 5.0f
#define PI_F 3.14159265358979323846f

// ========================= scratch (device globals) =========================
__device__ __align__(16) float g_scalar_out[N_NODES * H];
__device__ __align__(16) float g_ns[N_NODES * H];
__device__ __align__(16) float g_msg[N_EDGES * H];          // CSR order
__device__ __align__(16) float g_nv[N_NODES * 3 * H];
__device__ __align__(16) float g_ns1[N_NODES * H];          // node_scalar + agg
__device__ __align__(16) float g_nvec1[N_NODES * 3 * H];    // node_vector + agg
__device__ __align__(16) float g_wv[N_NODES * 3 * 2 * H];
__device__ __align__(16) float g_p[N_NODES * 3 * H];
__device__ __align__(16) __nv_bfloat16 g_wpack[11 * 32768];

__device__ int g_deg[N_NODES];
__device__ int g_off[N_NODES + 1];
__device__ int g_cur[N_NODES];
__device__ int g_eids[N_EDGES];      // CSR pos -> edge id
__device__ int g_own[N_EDGES];       // CSR pos -> dest node i
__device__ int g_ej[N_EDGES];        // CSR pos -> src node j
__device__ float g_distc[N_EDGES];   // CSR pos -> dist
__device__ float g_evc[N_EDGES * 3]; // CSR pos -> edge_vector

// ========================= helpers =========================
__device__ __forceinline__ uint32_t smem_u32(const void* p) {
    uint32_t a;
    asm("{ .reg .u64 t; cvta.to.shared.u64 t, %1; cvt.u32.u64 %0, t; }" : "=r"(a) : "l"(p));
    return a;
}
__device__ __forceinline__ float silu_f(float x) { return x / (1.0f + __expf(-x)); }

#define LDSM4(r, addr) \
    asm volatile("ldmatrix.sync.aligned.m8n8.x4.shared.b16 {%0,%1,%2,%3}, [%4];" \
        : "=r"((r)[0]), "=r"((r)[1]), "=r"((r)[2]), "=r"((r)[3]) : "r"(addr))

#define MMA16816(c, a, b) \
    asm volatile("mma.sync.aligned.m16n8k16.row.col.f32.bf16.bf16.f32 " \
        "{%0,%1,%2,%3}, {%4,%5,%6,%7}, {%8,%9}, {%0,%1,%2,%3};" \
        : "+f"((c)[0]), "+f"((c)[1]), "+f"((c)[2]), "+f"((c)[3]) \
        : "r"((a)[0]), "r"((a)[1]), "r"((a)[2]), "r"((a)[3]), "r"((b)[0]), "r"((b)[1]))

#define CP_ASYNC16(dst, src) \
    asm volatile("cp.async.cg.shared.global [%0], [%1], 16;" :: "r"(dst), "l"(src))
#define CP_COMMIT() asm volatile("cp.async.commit_group;")
#define CP_WAIT0()  asm volatile("cp.async.wait_group 0;")

// ========================= weight pre-pack (single launch) ===================
// tiles: 0=node 1=edge 2,3=p1 4=cross 5=f 6,7=vec 8,9,10=p2
__global__ void pack_all(const float* __restrict__ Wn, const float* __restrict__ We,
                         const float* __restrict__ Wp1, const float* __restrict__ Wc,
                         const float* __restrict__ Wf, const float* __restrict__ Wv,
                         const float* __restrict__ Wp2) {
    int tile = blockIdx.x;
    const float* W; int ncol, t;
    switch (tile) {
        case 0: W = Wn;  ncol = 128; t = 0; break;
        case 1: W = We;  ncol = 128; t = 0; break;
        case 2: case 3: W = Wp1; ncol = 256; t = tile - 2; break;
        case 4: W = Wc;  ncol = 128; t = 0; break;
        case 5: W = Wf;  ncol = 128; t = 0; break;
        case 6: case 7: W = Wv;  ncol = 256; t = tile - 6; break;
        default: W = Wp2; ncol = 384; t = tile - 8; break;
    }
    __nv_bfloat16* dst = g_wpack + (size_t)tile * 32768;
    int base = blockIdx.y * 2048;
    #pragma unroll
    for (int it = 0; it < 8; it++) {
        int lin = base + threadIdx.x + it * 256;   // lin = n*128 + k
        int n = lin >> 7, k = lin & 127;
        float v = W[(size_t)k * ncol + t * 128 + n];
        __nv_bfloat16 h = __float2bfloat16(v);
        __nv_bfloat16 l = __float2bfloat16(v - __bfloat162float(h));
        dst[lin] = h;
        dst[16384 + lin] = l;
    }
}

// ========================= shared GEMM plumbing ==============================
#define SM_TOTAL 104448
#define ASTRIDE 136
#define CSTRIDE 132
// smem map: aHi 0..17408, aLo 17408..34816, bHi 34816..69632, bLo 69632..104448
// post-MMA: Cs fp32 @34816 (33792B); mode2 sOwn @68608

struct MmaCtx {
    uint32_t aoff[2], boff[2];
};

__device__ __forceinline__ void a_split_store(char* smem, int r, int k0, float4 a) {
    __nv_bfloat162 h01 = __float22bfloat162_rn(make_float2(a.x, a.y));
    __nv_bfloat162 h23 = __float22bfloat162_rn(make_float2(a.z, a.w));
    float2 f01 = __bfloat1622float2(h01);
    float2 f23 = __bfloat1622float2(h23);
    __nv_bfloat162 l01 = __float22bfloat162_rn(make_float2(a.x - f01.x, a.y - f01.y));
    __nv_bfloat162 l23 = __float22bfloat162_rn(make_float2(a.z - f23.x, a.w - f23.y));
    uint2 hv, lv;
    hv.x = *(uint32_t*)&h01; hv.y = *(uint32_t*)&h23;
    lv.x = *(uint32_t*)&l01; lv.y = *(uint32_t*)&l23;
    *(uint2*)(smem + (r * ASTRIDE + k0) * 2) = hv;
    *(uint2*)(smem + 17408 + (r * ASTRIDE + k0) * 2) = lv;
}

__device__ __forceinline__ void b_async_load(uint32_t sb, const __nv_bfloat16* Bpack, int tid) {
    int n = tid >> 1, k0 = (tid & 1) * 64;
    const __nv_bfloat16* srcH = Bpack + n * 128 + k0;
    const __nv_bfloat16* srcL = srcH + 16384;
    uint32_t dH = sb + 34816 + (uint32_t)(n * ASTRIDE + k0) * 2;
    uint32_t dL = sb + 69632 + (uint32_t)(n * ASTRIDE + k0) * 2;
    #pragma unroll
    for (int q = 0; q < 8; q++) {
        CP_ASYNC16(dH + q * 16, srcH + q * 8);
        CP_ASYNC16(dL + q * 16, srcL + q * 8);
    }
    CP_COMMIT();
}

__device__ __forceinline__ void mma_setup(MmaCtx& cx, int lane, int warp_m, int warp_n) {
    const int rin = lane & 7, sel = lane >> 3;
    #pragma unroll
    for (int mt = 0; mt < 2; mt++) {
        int row = warp_m * 32 + mt * 16 + (sel & 1) * 8 + rin;
        int col = (sel >> 1) * 8;
        cx.aoff[mt] = (uint32_t)((row * ASTRIDE + col) * 2);
    }
    #pragma unroll
    for (int nt2 = 0; nt2 < 2; nt2++) {
        int n = warp_n * 32 + nt2 * 16 + (sel >> 1) * 8 + rin;
        int col = (sel & 1) * 8;
        cx.boff[nt2] = (uint32_t)((n * ASTRIDE + col) * 2);
    }
}

__device__ __forceinline__ void mma_mainloop(float acc[2][4][4], const MmaCtx& cx, uint32_t sb) {
    const uint32_t aHi = sb, aLo = sb + 17408, bHi = sb + 34816, bLo = sb + 69632;
    #pragma unroll
    for (int ks = 0; ks < 8; ks++) {
        uint32_t kb = ks * 32;
        uint32_t ah[2][4], al[2][4], bh[4][2], bl[4][2];
        #pragma unroll
        for (int mt = 0; mt < 2; mt++) {
            LDSM4(ah[mt], aHi + cx.aoff[mt] + kb);
            LDSM4(al[mt], aLo + cx.aoff[mt] + kb);
        }
        #pragma unroll
        for (int nt2 = 0; nt2 < 2; nt2++) {
            uint32_t t[4];
            LDSM4(t, bHi + cx.boff[nt2] + kb);
            bh[nt2 * 2][0] = t[0]; bh[nt2 * 2][1] = t[1];
            bh[nt2 * 2 + 1][0] = t[2]; bh[nt2 * 2 + 1][1] = t[3];
            LDSM4(t, bLo + cx.boff[nt2] + kb);
            bl[nt2 * 2][0] = t[0]; bl[nt2 * 2][1] = t[1];
            bl[nt2 * 2 + 1][0] = t[2]; bl[nt2 * 2 + 1][1] = t[3];
        }
        #pragma unroll
        for (int mt = 0; mt < 2; mt++)
            #pragma unroll
            for (int nt = 0; nt < 4; nt++) {
                MMA16816(acc[mt][nt], ah[mt], bh[nt]);
                MMA16816(acc[mt][nt], ah[mt], bl[nt]);
                MMA16816(acc[mt][nt], al[mt], bh[nt]);
            }
    }
}

__device__ __forceinline__ void stage_c(float* Cs, const float acc[2][4][4],
                                        int lane, int warp_m, int warp_n) {
    int gid = lane >> 2, tig = lane & 3;
    #pragma unroll
    for (int mt = 0; mt < 2; mt++) {
        int r = warp_m * 32 + mt * 16 + gid;
        #pragma unroll
        for (int nt = 0; nt < 4; nt++) {
            int cc = warp_n * 32 + nt * 8 + tig * 2;
            *(float2*)&Cs[r * CSTRIDE + cc] = make_float2(acc[mt][nt][0], acc[mt][nt][1]);
            *(float2*)&Cs[(r + 8) * CSTRIDE + cc] = make_float2(acc[mt][nt][2], acc[mt][nt][3]);
        }
    }
}

// ========================= gemm_tc: modes 0, 2, 3 ============================
// mode 0: C = gemm + bias
// mode 2: A gathered via eids; msg epilogue; writes g_msg (CSR) + atomically
//         accumulates scalar_agg into `agg` (=g_ns1)
// mode 3: edge final; efeat reconstructed from smem A; writes out_edge
__global__ __launch_bounds__(256, 2)
void gemm_tc(const float* __restrict__ A, int M,
             const __nv_bfloat16* __restrict__ Bpack0,
             const float* __restrict__ bias0,
             float* __restrict__ C, int ldc, int mode,
             const int* __restrict__ idx0,     // mode2: g_eids | mode3: edge_index
             const int* __restrict__ own,      // mode2: g_own
             const int* __restrict__ ejArr,    // mode2: g_ej
             const float* __restrict__ distc,  // mode2: g_distc
             const float* __restrict__ alpha,
             const float* __restrict__ ev,     // mode3: edge_vector
             const float* __restrict__ naux,   // mode2: g_ns | mode3: g_nv
             float* __restrict__ agg) {        // mode2: g_ns1
    extern __shared__ char smem[];
    const int tid = threadIdx.x;
    const int lane = tid & 31, wid = tid >> 5;
    const int warp_m = wid >> 2, warp_n = wid & 3;
    const int row0 = blockIdx.x * 64;
    const int ytile = blockIdx.y;
    const __nv_bfloat16* Bpack = Bpack0 + (size_t)ytile * 32768;
    const float* bias = bias0 ? bias0 + ytile * 128 : nullptr;
    const uint32_t sb = smem_u32(smem);

    b_async_load(sb, Bpack, tid);

    // A tile (each thread: 32 floats of one row); mode2 gathers rows via eids
    {
        int r = tid >> 2, k0 = (tid & 3) * 32;
        int arow = row0 + r;
        const float* srcrow;
        bool vr = arow < M;
        if (mode == 2) {
            int e = vr ? idx0[arow] : 0;
            srcrow = A + (size_t)e * 128;
        } else {
            srcrow = A + (size_t)arow * 128;
        }
        const float4* src = (const float4*)(srcrow + k0);
        float4 av[8];
        #pragma unroll
        for (int q = 0; q < 8; q++)
            av[q] = vr ? __ldg(src + q) : make_float4(0.f, 0.f, 0.f, 0.f);
        #pragma unroll
        for (int q = 0; q < 8; q++)
            a_split_store(smem, r, k0 + q * 4, av[q]);
    }
    CP_WAIT0();
    __syncthreads();

    float acc[2][4][4];
    #pragma unroll
    for (int mt = 0; mt < 2; mt++)
        #pragma unroll
        for (int nt = 0; nt < 4; nt++)
            #pragma unroll
            for (int u = 0; u < 4; u++) acc[mt][nt][u] = 0.f;

    MmaCtx cx; mma_setup(cx, lane, warp_m, warp_n);
    mma_mainloop(acc, cx, sb);
    __syncthreads();

    float* Cs = (float*)(smem + 34816);
    int* sOwn = (int*)(smem + 68608);
    stage_c(Cs, acc, lane, warp_m, warp_n);
    if (mode == 2 && tid < 64) sOwn[tid] = own[row0 + tid];
    __syncthreads();

    // ---- per-row epilogue ----
    const int r = tid >> 2;
    const int c0g = (tid & 3) * 32;
    const int grow = row0 + r;
    if (grow < M) {
        int ii = 0, jj = 0;
        float cut = 0.f, v0 = 0.f, v1 = 0.f, v2 = 0.f, vvq = 0.f;
        if (mode == 2) {
            jj = ejArr[grow];
            float dd = __ldg(distc + grow);
            cut = (dd < CUTOFF_R) ? 0.5f * (__cosf(PI_F * dd / CUTOFF_R) + 1.0f) : 0.0f;
            ii = sOwn[r];
        } else if (mode == 3) {
            ii = idx0[grow]; jj = idx0[N_EDGES + grow];
            v0 = __ldg(ev + grow * 3 + 0); v1 = __ldg(ev + grow * 3 + 1); v2 = __ldg(ev + grow * 3 + 2);
            vvq = v0 * v0 + v1 * v1 + v2 * v2;
        }
        float* dst = C + (size_t)grow * ldc + ytile * 128 + c0g;

        #pragma unroll
        for (int ch = 0; ch < 2; ch++) {
            const int cl = c0g + ch * 16;
            float d[16];
            #pragma unroll
            for (int c = 0; c < 16; c++) d[c] = Cs[r * CSTRIDE + cl + c];
            if (bias) {
                #pragma unroll
                for (int c = 0; c < 16; c++) d[c] += __ldg(bias + cl + c);
            }

            if (mode == 2) {
                float nsi[16], nsj[16];
                const float4* pi4 = (const float4*)(naux + (size_t)ii * H + cl);
                const float4* pj4 = (const float4*)(naux + (size_t)jj * H + cl);
                #pragma unroll
                for (int q = 0; q < 4; q++) {
                    float4 a = __ldg(pi4 + q);
                    nsi[4*q] = a.x; nsi[4*q+1] = a.y; nsi[4*q+2] = a.z; nsi[4*q+3] = a.w;
                    float4 b = __ldg(pj4 + q);
                    nsj[4*q] = b.x; nsj[4*q+1] = b.y; nsj[4*q+2] = b.z; nsj[4*q+3] = b.w;
                }
                float s = 0.f;
                #pragma unroll
                for (int c = 0; c < 16; c++) {
                    float ef = silu_f(d[c]);
                    d[c] = ef;
                    float x = nsi[c] + nsj[c] + ef;
                    s += silu_f(x) * __ldg(alpha + cl + c);
                }
                float attn = s * cut;
                #pragma unroll
                for (int c = 0; c < 16; c++) {
                    d[c] = nsj[c] * d[c] * attn;
                    Cs[r * CSTRIDE + cl + c] = d[c];   // for segmented agg walk
                }
            } else if (mode == 3) {
                // reconstruct efeat from smem A (hi+lo)
                float efv[16];
                #pragma unroll
                for (int q = 0; q < 8; q++) {
                    uint32_t h2 = *(uint32_t*)(smem + (r * ASTRIDE + cl + q * 2) * 2);
                    uint32_t l2 = *(uint32_t*)(smem + 17408 + (r * ASTRIDE + cl + q * 2) * 2);
                    __nv_bfloat162 hb = *(__nv_bfloat162*)&h2;
                    __nv_bfloat162 lb = *(__nv_bfloat162*)&l2;
                    float2 hf = __bfloat1622float2(hb);
                    float2 lf = __bfloat1622float2(lb);
                    efv[q*2] = hf.x + lf.x; efv[q*2+1] = hf.y + lf.y;
                }
                const float* arow = naux + (size_t)ii * 3 * H;
                const float* brow = naux + (size_t)jj * 3 * H;
                #pragma unroll
                for (int q = 0; q < 4; q++) {
                    int c = cl + 4 * q;
                    float4 a0 = __ldg((const float4*)(arow + 0 * H + c));
                    float4 a1 = __ldg((const float4*)(arow + 1 * H + c));
                    float4 a2 = __ldg((const float4*)(arow + 2 * H + c));
                    float4 b0 = __ldg((const float4*)(brow + 0 * H + c));
                    float4 b1 = __ldg((const float4*)(brow + 1 * H + c));
                    float4 b2 = __ldg((const float4*)(brow + 2 * H + c));
                    #pragma unroll
                    for (int u = 0; u < 4; u++) {
                        float ax = (&a0.x)[u], ay = (&a1.x)[u], az = (&a2.x)[u];
                        float bx = (&b0.x)[u], by = (&b1.x)[u], bz = (&b2.x)[u];
                        float ab = ax * bx + ay * by + az * bz;
                        float avd = ax * v0 + ay * v1 + az * v2;
                        float bvd = bx * v0 + by * v1 + bz * v2;
                        float sphi = ab * vvq - avd * bvd;
                        float gf = silu_f(d[4 * q + u]);
                        d[4 * q + u] = efv[4 * q + u] + gf * sphi;
                    }
                }
            }

            #pragma unroll
            for (int q = 0; q < 4; q++)
                *(float4*)(dst + ch * 16 + 4 * q) =
                    make_float4(d[4*q], d[4*q+1], d[4*q+2], d[4*q+3]);
        }
    }

    // ---- mode2: segmented column walk -> scalar_agg atomics ----
    if (mode == 2) {
        __syncthreads();
        if (tid < 128) {
            int col = tid;
            float a = 0.f;
            int prev = sOwn[0];
            #pragma unroll 4
            for (int r2 = 0; r2 < 64; r2++) {
                int o = sOwn[r2];
                float v = Cs[r2 * CSTRIDE + col];
                if (o != prev) { atomicAdd(&agg[(size_t)prev * H + col], a); a = 0.f; prev = o; }
                a += v;
            }
            atomicAdd(&agg[(size_t)prev * H + col], a);
        }
    }
}

// ========================= gemm_p1: dual-tile + fused vmsg ==================
// A = g_msg (CSR order). Computes s1 = silu(A@Wp1[:,:128]+b), s2 = silu(...+128)
// and accumulates vmsg = nvec[j]*s1 + s2*ev into nvec1 (segmented atomics).
// No C output.
__global__ __launch_bounds__(256, 2)
void gemm_p1(const float* __restrict__ A,
             const __nv_bfloat16* __restrict__ Bpack0,
             const float* __restrict__ bias,
             const int* __restrict__ own,
             const int* __restrict__ ejArr,
             const float* __restrict__ evc,
             const float* __restrict__ nvec,
             float* __restrict__ nvec1) {
    extern __shared__ char smem[];
    const int tid = threadIdx.x;
    const int lane = tid & 31, wid = tid >> 5;
    const int warp_m = wid >> 2, warp_n = wid & 3;
    const int row0 = blockIdx.x * 64;
    const uint32_t sb = smem_u32(smem);

    b_async_load(sb, Bpack0, tid);
    {
        int r = tid >> 2, k0 = (tid & 3) * 32;
        const float4* src = (const float4*)(A + (size_t)(row0 + r) * 128 + k0);
        float4 av[8];
        #pragma unroll
        for (int q = 0; q < 8; q++) av[q] = __ldg(src + q);
        #pragma unroll
        for (int q = 0; q < 8; q++) a_split_store(smem, r, k0 + q * 4, av[q]);
    }
    CP_WAIT0();
    __syncthreads();

    MmaCtx cx; mma_setup(cx, lane, warp_m, warp_n);

    float acc0[2][4][4], acc1[2][4][4];
    #pragma unroll
    for (int mt = 0; mt < 2; mt++)
        #pragma unroll
        for (int nt = 0; nt < 4; nt++)
            #pragma unroll
            for (int u = 0; u < 4; u++) { acc0[mt][nt][u] = 0.f; acc1[mt][nt][u] = 0.f; }

    mma_mainloop(acc0, cx, sb);
    __syncthreads();
    b_async_load(sb, Bpack0 + 32768, tid);   // second N-tile
    CP_WAIT0();
    __syncthreads();
    mma_mainloop(acc1, cx, sb);
    __syncthreads();

    float* Cs0 = (float*)(smem + 34816);
    float* Cs1 = (float*)(smem + 68608);
    int*   sOwn = (int*)(smem + 102400);
    int*   sEj  = (int*)(smem + 102656);
    float* sEv  = (float*)(smem + 102912);
    stage_c(Cs0, acc0, lane, warp_m, warp_n);
    stage_c(Cs1, acc1, lane, warp_m, warp_n);
    if (tid < 64) {
        sOwn[tid] = own[row0 + tid];
        sEj[tid]  = ejArr[row0 + tid];
        sEv[tid * 3 + 0] = evc[(row0 + tid) * 3 + 0];
        sEv[tid * 3 + 1] = evc[(row0 + tid) * 3 + 1];
        sEv[tid * 3 + 2] = evc[(row0 + tid) * 3 + 2];
    }
    __syncthreads();

    if (tid < 128) {
        const int col = tid;
        const float b1 = __ldg(bias + col);
        const float b2 = __ldg(bias + 128 + col);
        float a0 = 0.f, a1 = 0.f, a2 = 0.f;
        int prev = sOwn[0];
        #pragma unroll 2
        for (int r2 = 0; r2 < 64; r2++) {
            int o = sOwn[r2];
            int j = sEj[r2];
            float s1 = silu_f(Cs0[r2 * CSTRIDE + col] + b1);
            float s2 = silu_f(Cs1[r2 * CSTRIDE + col] + b2);
            const float* nv = nvec + (size_t)j * 384 + col;
            float n0 = __ldg(nv);
            float n1 = __ldg(nv + 128);
            float n2 = __ldg(nv + 256);
            float e0 = sEv[r2 * 3 + 0], e1 = sEv[r2 * 3 + 1], e2 = sEv[r2 * 3 + 2];
            if (o != prev) {
                atomicAdd(&nvec1[(size_t)prev * 384 + col], a0);
                atomicAdd(&nvec1[(size_t)prev * 384 + 128 + col], a1);
                atomicAdd(&nvec1[(size_t)prev * 384 + 256 + col], a2);
                a0 = a1 = a2 = 0.f; prev = o;
            }
            a0 = fmaf(n0, s1, fmaf(s2, e0, a0));
            a1 = fmaf(n1, s1, fmaf(s2, e1, a1));
            a2 = fmaf(n2, s1, fmaf(s2, e2, a2));
        }
        atomicAdd(&nvec1[(size_t)prev * 384 + col], a0);
        atomicAdd(&nvec1[(size_t)prev * 384 + 128 + col], a1);
        atomicAdd(&nvec1[(size_t)prev * 384 + 256 + col], a2);
    }
}

// ========================= layernorm + residual init =========================
__global__ void ln_init(const float* __restrict__ x,
                        const float* __restrict__ nvec,
                        const float* __restrict__ gamma,
                        const float* __restrict__ beta,
                        float* __restrict__ y,
                        float* __restrict__ ns1,
                        float* __restrict__ nvec1) {
    int n = blockIdx.x;
    int h = threadIdx.x;
    float v = x[(size_t)n * H + h];
    float s = v, s2 = v * v;
    #pragma unroll
    for (int o = 16; o > 0; o >>= 1) {
        s  += __shfl_xor_sync(0xffffffffu, s, o);
        s2 += __shfl_xor_sync(0xffffffffu, s2, o);
    }
    __shared__ float rs[4], rs2[4];
    int warp = h >> 5, lane = h & 31;
    if (lane == 0) { rs[warp] = s; rs2[warp] = s2; }
    __syncthreads();
    float ts  = rs[0] + rs[1] + rs[2] + rs[3];
    float ts2 = rs2[0] + rs2[1] + rs2[2] + rs2[3];
    float mu  = ts * (1.0f / H);
    float var = ts2 * (1.0f / H) - mu * mu;
    float inv = rsqrtf(var + 1e-5f);
    y[(size_t)n * H + h] = (v - mu) * inv * gamma[h] + beta[h];
    ns1[(size_t)n * H + h] = v;
    #pragma unroll
    for (int d = 0; d < 3; d++)
        nvec1[(size_t)n * 384 + d * 128 + h] = nvec[(size_t)n * 384 + d * 128 + h];
}

// ========================= CSR build =========================
__global__ void csr_zero() {
    int n = blockIdx.x * blockDim.x + threadIdx.x;
    if (n < N_NODES) g_deg[n] = 0;
}
__global__ void csr_hist(const int* __restrict__ ei) {
    int e = blockIdx.x * blockDim.x + threadIdx.x;
    if (e < N_EDGES) atomicAdd(&g_deg[ei[e]], 1);
}
__global__ void csr_scan() {
    __shared__ int sh[1024];
    __shared__ int carry;
    int tid = threadIdx.x;
    if (tid == 0) carry = 0;
    for (int base = 0; base < N_NODES; base += 1024) {
        __syncthreads();
        int c = carry;
        int idx = base + tid;
        int v = (idx < N_NODES) ? g_deg[idx] : 0;
        sh[tid] = v;
        __syncthreads();
        #pragma unroll
        for (int o = 1; o < 1024; o <<= 1) {
            int t = (tid >= o) ? sh[tid - o] : 0;
            __syncthreads();
            sh[tid] += t;
            __syncthreads();
        }
        if (idx < N_NODES) {
            int excl = c + sh[tid] - v;
            g_off[idx] = excl;
            g_cur[idx] = excl;
        }
        int tot = sh[1023];
        __syncthreads();
        if (tid == 0) carry = c + tot;
    }
    __syncthreads();
    if (tid == 0) g_off[N_NODES] = carry;
}
__global__ void csr_scatter(const int* __restrict__ ei,
                            const float* __restrict__ dist,
                            const float* __restrict__ ev) {
    int e = blockIdx.x * blockDim.x + threadIdx.x;
    if (e < N_EDGES) {
        int i = ei[e];
        int j = ei[N_EDGES + e];
        int pos = atomicAdd(&g_cur[i], 1);
        g_eids[pos] = e;
        g_own[pos] = i;
        g_ej[pos] = j;
        g_distc[pos] = dist[e];
        g_evc[pos * 3 + 0] = ev[e * 3 + 0];
        g_evc[pos * 3 + 1] = ev[e * 3 + 1];
        g_evc[pos * 3 + 2] = ev[e * 3 + 2];
    }
}

// ========================= node final =========================
__global__ void node_final(float* __restrict__ out_scal,
                           float* __restrict__ out_vec) {
    int n = blockIdx.x;
    int h = threadIdx.x;
    float v1d[3], v2d[3];
    #pragma unroll
    for (int d = 0; d < 3; d++) {
        v1d[d] = g_wv[((size_t)n * 3 + d) * 256 + h];
        v2d[d] = g_wv[((size_t)n * 3 + d) * 256 + 128 + h];
    }
    float tri = v1d[0] * v2d[0] + v1d[1] * v2d[1] + v1d[2] * v2d[2];
    float sq  = v2d[0] * v2d[0] + v2d[1] * v2d[1] + v2d[2] * v2d[2];
    float nrm = sqrtf(sq + 1e-8f);
    float qua = nrm * nrm * nrm;
    float p1 = g_p[(size_t)n * 384 + h];
    float p2 = g_p[(size_t)n * 384 + 128 + h];
    float p3 = g_p[(size_t)n * 384 + 256 + h];
    out_scal[(size_t)n * H + h] = g_ns1[(size_t)n * H + h] + (qua + tri) * p1 + p2;
    #pragma unroll
    for (int d = 0; d < 3; d++) {
        out_vec[((size_t)n * 3 + d) * H + h] =
            g_nvec1[((size_t)n * 3 + d) * H + h] + v1d[d] * p3;
    }
}

// ========================= launch =========================
extern "C" void kernel_launch(void* const* d_in, const int* in_sizes, int n_in,
                              void* d_out, int out_size) {
    const float* node_scalar = (const float*)d_in[0];
    const float* node_vector = (const float*)d_in[1];
    const int*   edge_index  = (const int*)  d_in[2];
    const float* dist        = (const float*)d_in[3];
    const float* edge_feats  = (const float*)d_in[4];
    const float* edge_vector = (const float*)d_in[5];
    const float* ln_gamma    = (const float*)d_in[6];
    const float* ln_beta     = (const float*)d_in[7];
    const float* alpha       = (const float*)d_in[8];
    const float* W_cross     = (const float*)d_in[9];
    const float* W_node      = (const float*)d_in[10];
    const float* b_node      = (const float*)d_in[11];
    const float* W_edge      = (const float*)d_in[12];
    const float* b_edge      = (const float*)d_in[13];
    const float* W_p1        = (const float*)d_in[14];
    const float* b_p1        = (const float*)d_in[15];
    const float* W_p2        = (const float*)d_in[16];
    const float* b_p2        = (const float*)d_in[17];
    const float* W_vec       = (const float*)d_in[18];
    const float* W_f         = (const float*)d_in[19];
    const float* b_f         = (const float*)d_in[20];

    float* out = (float*)d_out;
    float* out_scal = out;
    float* out_vec  = out + (size_t)N_NODES * H;
    float* out_edge = out + (size_t)N_NODES * H * 4;

    float* p_scalar_out; cudaGetSymbolAddress((void**)&p_scalar_out, g_scalar_out);
    float* p_ns;    cudaGetSymbolAddress((void**)&p_ns, g_ns);
    float* p_msg;   cudaGetSymbolAddress((void**)&p_msg, g_msg);
    float* p_nv;    cudaGetSymbolAddress((void**)&p_nv, g_nv);
    float* p_ns1;   cudaGetSymbolAddress((void**)&p_ns1, g_ns1);
    float* p_nvec1; cudaGetSymbolAddress((void**)&p_nvec1, g_nvec1);
    float* p_wv;    cudaGetSymbolAddress((void**)&p_wv, g_wv);
    float* p_p;     cudaGetSymbolAddress((void**)&p_p, g_p);
    __nv_bfloat16* wp; cudaGetSymbolAddress((void**)&wp, g_wpack);
    int* p_eids;  cudaGetSymbolAddress((void**)&p_eids, g_eids);
    int* p_own;   cudaGetSymbolAddress((void**)&p_own, g_own);
    int* p_ej;    cudaGetSymbolAddress((void**)&p_ej, g_ej);
    float* p_distc; cudaGetSymbolAddress((void**)&p_distc, g_distc);
    float* p_evc;   cudaGetSymbolAddress((void**)&p_evc, g_evc);

    cudaFuncSetAttribute(gemm_tc, cudaFuncAttributeMaxDynamicSharedMemorySize, SM_TOTAL);
    cudaFuncSetAttribute(gemm_p1, cudaFuncAttributeMaxDynamicSharedMemorySize, SM_TOTAL);

    const int GB_N  = (N_NODES + 63) / 64;        // 313
    const int GB_E  = N_EDGES / 64;               // 5000
    const int GB_3N = (3 * N_NODES + 63) / 64;    // 938

    pack_all<<<dim3(11, 8), 256>>>(W_node, W_edge, W_p1, W_cross, W_f, W_vec, W_p2);

    csr_zero<<<(N_NODES + 255) / 256, 256>>>();
    csr_hist<<<(N_EDGES + 255) / 256, 256>>>(edge_index);
    csr_scan<<<1, 1024>>>();
    csr_scatter<<<(N_EDGES + 255) / 256, 256>>>(edge_index, dist, edge_vector);

    ln_init<<<N_NODES, 128>>>(node_scalar, node_vector, ln_gamma, ln_beta,
                              p_scalar_out, p_ns1, p_nvec1);

    // ns = scalar_out @ W_node + b
    gemm_tc<<<dim3(GB_N, 1), 256, SM_TOTAL>>>(p_scalar_out, N_NODES, wp + 0 * 32768, b_node,
        p_ns, 128, 0, nullptr, nullptr, nullptr, nullptr, nullptr, nullptr, nullptr, nullptr);

    // fused: ef GEMM + attention + message (CSR order) + scalar agg
    gemm_tc<<<dim3(GB_E, 1), 256, SM_TOTAL>>>(edge_feats, N_EDGES, wp + 1 * 32768, b_edge,
        p_msg, 128, 2, p_eids, p_own, p_ej, p_distc, alpha, nullptr, p_ns, p_ns1);

    // fused: W_p1 dual-tile GEMM + vmsg accumulation
    gemm_p1<<<GB_E, 256, SM_TOTAL>>>(p_msg, wp + 2 * 32768, b_p1,
                                     p_own, p_ej, p_evc, node_vector, p_nvec1);

    // edge update path (independent of message path except launch order)
    gemm_tc<<<dim3(GB_3N, 1), 256, SM_TOTAL>>>(node_vector, 3 * N_NODES, wp + 4 * 32768, nullptr,
        p_nv, 128, 0, nullptr, nullptr, nullptr, nullptr, nullptr, nullptr, nullptr, nullptr);
    gemm_tc<<<dim3(GB_E, 1), 256, SM_TOTAL>>>(edge_feats, N_EDGES, wp + 5 * 32768, b_f,
        out_edge, 128, 3, edge_index, nullptr, nullptr, nullptr, nullptr, edge_vector, p_nv, nullptr);

    // node update
    gemm_tc<<<dim3(GB_3N, 2), 256, SM_TOTAL>>>(p_nvec1, 3 * N_NODES, wp + 6 * 32768, nullptr,
        p_wv, 256, 0, nullptr, nullptr, nullptr, nullptr, nullptr, nullptr, nullptr, nullptr);
    gemm_tc<<<dim3(GB_N, 3), 256, SM_TOTAL>>>(p_ns1, N_NODES, wp + 8 * 32768, b_p2,
        p_p, 384, 0, nullptr, nullptr, nullptr, nullptr, nullptr, nullptr, nullptr, nullptr);
    node_final<<<N_NODES, 128>>>(out_scal, out_vec);
}

// round 7
// speedup vs baseline: 1.2705x; 1.1343x over previous
#include <cuda_runtime.h>
#include <cuda_bf16.h>
#include <math.h>
#include <stdint.h>

#define N_NODES 20000
#define N_EDGES 320000
#define H 128
#define CUTOFF_R 5.0f
#define PI_F 3.14159265358979323846f

// ========================= scratch (device globals) =========================
__device__ __align__(16) float g_scalar_out[N_NODES * H];
__device__ __align__(16) float g_ns[N_NODES * H];
__device__ __align__(16) float g_nv[N_NODES * 3 * H];
__device__ __align__(16) float g_ns1[N_NODES * H];
__device__ __align__(16) float g_nvec1[N_NODES * 3 * H];
__device__ __align__(16) float g_wv[N_NODES * 3 * 2 * H];
__device__ __align__(16) float g_p[N_NODES * 3 * H];
__device__ __align__(16) __nv_bfloat16 g_wpack[11 * 32768];

__device__ int g_deg[N_NODES];
__device__ int g_off[N_NODES + 1];
__device__ int g_cur[N_NODES];
__device__ int g_eids[N_EDGES];
__device__ int g_own[N_EDGES];
__device__ int g_ej[N_EDGES];
__device__ float g_distc[N_EDGES];
__device__ float g_evc[N_EDGES * 3];

// ========================= helpers =========================
__device__ __forceinline__ uint32_t smem_u32(const void* p) {
    uint32_t a;
    asm("{ .reg .u64 t; cvta.to.shared.u64 t, %1; cvt.u32.u64 %0, t; }" : "=r"(a) : "l"(p));
    return a;
}
__device__ __forceinline__ float silu_f(float x) { return x / (1.0f + __expf(-x)); }

#define LDSM4(r, addr) \
    asm volatile("ldmatrix.sync.aligned.m8n8.x4.shared.b16 {%0,%1,%2,%3}, [%4];" \
        : "=r"((r)[0]), "=r"((r)[1]), "=r"((r)[2]), "=r"((r)[3]) : "r"(addr))

#define MMA16816(c, a, b) \
    asm volatile("mma.sync.aligned.m16n8k16.row.col.f32.bf16.bf16.f32 " \
        "{%0,%1,%2,%3}, {%4,%5,%6,%7}, {%8,%9}, {%0,%1,%2,%3};" \
        : "+f"((c)[0]), "+f"((c)[1]), "+f"((c)[2]), "+f"((c)[3]) \
        : "r"((a)[0]), "r"((a)[1]), "r"((a)[2]), "r"((a)[3]), "r"((b)[0]), "r"((b)[1]))

#define CP_ASYNC16(dst, src) \
    asm volatile("cp.async.cg.shared.global [%0], [%1], 16;" :: "r"(dst), "l"(src))
#define CP_COMMIT() asm volatile("cp.async.commit_group;")
#define CP_WAIT0()  asm volatile("cp.async.wait_group 0;")

// ========================= weight pre-pack ===================================
__global__ void pack_all(const float* __restrict__ Wn, const float* __restrict__ We,
                         const float* __restrict__ Wp1, const float* __restrict__ Wc,
                         const float* __restrict__ Wf, const float* __restrict__ Wv,
                         const float* __restrict__ Wp2) {
    int tile = blockIdx.x;
    const float* W; int ncol, t;
    switch (tile) {
        case 0: W = Wn;  ncol = 128; t = 0; break;
        case 1: W = We;  ncol = 128; t = 0; break;
        case 2: case 3: W = Wp1; ncol = 256; t = tile - 2; break;
        case 4: W = Wc;  ncol = 128; t = 0; break;
        case 5: W = Wf;  ncol = 128; t = 0; break;
        case 6: case 7: W = Wv;  ncol = 256; t = tile - 6; break;
        default: W = Wp2; ncol = 384; t = tile - 8; break;
    }
    __nv_bfloat16* dst = g_wpack + (size_t)tile * 32768;
    int base = blockIdx.y * 2048;
    #pragma unroll
    for (int it = 0; it < 8; it++) {
        int lin = base + threadIdx.x + it * 256;
        int n = lin >> 7, k = lin & 127;
        float v = W[(size_t)k * ncol + t * 128 + n];
        __nv_bfloat16 h = __float2bfloat16(v);
        __nv_bfloat16 l = __float2bfloat16(v - __bfloat162float(h));
        dst[lin] = h;
        dst[16384 + lin] = l;
    }
}

// ========================= shared GEMM plumbing ==============================
#define SM_TOTAL 104448
#define SM_MEGA  105984
#define ASTRIDE 136
#define CSTRIDE 132

struct MmaCtx { uint32_t aoff[2], boff[2]; };

__device__ __forceinline__ void a_split_store(char* smem, int r, int k0, float4 a) {
    __nv_bfloat162 h01 = __float22bfloat162_rn(make_float2(a.x, a.y));
    __nv_bfloat162 h23 = __float22bfloat162_rn(make_float2(a.z, a.w));
    float2 f01 = __bfloat1622float2(h01);
    float2 f23 = __bfloat1622float2(h23);
    __nv_bfloat162 l01 = __float22bfloat162_rn(make_float2(a.x - f01.x, a.y - f01.y));
    __nv_bfloat162 l23 = __float22bfloat162_rn(make_float2(a.z - f23.x, a.w - f23.y));
    uint2 hv, lv;
    hv.x = *(uint32_t*)&h01; hv.y = *(uint32_t*)&h23;
    lv.x = *(uint32_t*)&l01; lv.y = *(uint32_t*)&l23;
    *(uint2*)(smem + (r * ASTRIDE + k0) * 2) = hv;
    *(uint2*)(smem + 17408 + (r * ASTRIDE + k0) * 2) = lv;
}

__device__ __forceinline__ void b_async_load(uint32_t sb, const __nv_bfloat16* Bpack, int tid) {
    int n = tid >> 1, k0 = (tid & 1) * 64;
    const __nv_bfloat16* srcH = Bpack + n * 128 + k0;
    const __nv_bfloat16* srcL = srcH + 16384;
    uint32_t dH = sb + 34816 + (uint32_t)(n * ASTRIDE + k0) * 2;
    uint32_t dL = sb + 69632 + (uint32_t)(n * ASTRIDE + k0) * 2;
    #pragma unroll
    for (int q = 0; q < 8; q++) {
        CP_ASYNC16(dH + q * 16, srcH + q * 8);
        CP_ASYNC16(dL + q * 16, srcL + q * 8);
    }
    CP_COMMIT();
}

__device__ __forceinline__ void mma_setup(MmaCtx& cx, int lane, int warp_m, int warp_n) {
    const int rin = lane & 7, sel = lane >> 3;
    #pragma unroll
    for (int mt = 0; mt < 2; mt++) {
        int row = warp_m * 32 + mt * 16 + (sel & 1) * 8 + rin;
        int col = (sel >> 1) * 8;
        cx.aoff[mt] = (uint32_t)((row * ASTRIDE + col) * 2);
    }
    #pragma unroll
    for (int nt2 = 0; nt2 < 2; nt2++) {
        int n = warp_n * 32 + nt2 * 16 + (sel >> 1) * 8 + rin;
        int col = (sel & 1) * 8;
        cx.boff[nt2] = (uint32_t)((n * ASTRIDE + col) * 2);
    }
}

__device__ __forceinline__ void zero_acc(float acc[2][4][4]) {
    #pragma unroll
    for (int mt = 0; mt < 2; mt++)
        #pragma unroll
        for (int nt = 0; nt < 4; nt++)
            #pragma unroll
            for (int u = 0; u < 4; u++) acc[mt][nt][u] = 0.f;
}

__device__ __forceinline__ void mma_mainloop(float acc[2][4][4], const MmaCtx& cx, uint32_t sb) {
    const uint32_t aHi = sb, aLo = sb + 17408, bHi = sb + 34816, bLo = sb + 69632;
    #pragma unroll
    for (int ks = 0; ks < 8; ks++) {
        uint32_t kb = ks * 32;
        uint32_t ah[2][4], al[2][4], bh[4][2], bl[4][2];
        #pragma unroll
        for (int mt = 0; mt < 2; mt++) {
            LDSM4(ah[mt], aHi + cx.aoff[mt] + kb);
            LDSM4(al[mt], aLo + cx.aoff[mt] + kb);
        }
        #pragma unroll
        for (int nt2 = 0; nt2 < 2; nt2++) {
            uint32_t t[4];
            LDSM4(t, bHi + cx.boff[nt2] + kb);
            bh[nt2 * 2][0] = t[0]; bh[nt2 * 2][1] = t[1];
            bh[nt2 * 2 + 1][0] = t[2]; bh[nt2 * 2 + 1][1] = t[3];
            LDSM4(t, bLo + cx.boff[nt2] + kb);
            bl[nt2 * 2][0] = t[0]; bl[nt2 * 2][1] = t[1];
            bl[nt2 * 2 + 1][0] = t[2]; bl[nt2 * 2 + 1][1] = t[3];
        }
        #pragma unroll
        for (int mt = 0; mt < 2; mt++)
            #pragma unroll
            for (int nt = 0; nt < 4; nt++) {
                MMA16816(acc[mt][nt], ah[mt], bh[nt]);
                MMA16816(acc[mt][nt], ah[mt], bl[nt]);
                MMA16816(acc[mt][nt], al[mt], bh[nt]);
            }
    }
}

__device__ __forceinline__ void stage_c(float* Cs, const float acc[2][4][4],
                                        int lane, int warp_m, int warp_n) {
    int gid = lane >> 2, tig = lane & 3;
    #pragma unroll
    for (int mt = 0; mt < 2; mt++) {
        int r = warp_m * 32 + mt * 16 + gid;
        #pragma unroll
        for (int nt = 0; nt < 4; nt++) {
            int cc = warp_n * 32 + nt * 8 + tig * 2;
            *(float2*)&Cs[r * CSTRIDE + cc] = make_float2(acc[mt][nt][0], acc[mt][nt][1]);
            *(float2*)&Cs[(r + 8) * CSTRIDE + cc] = make_float2(acc[mt][nt][2], acc[mt][nt][3]);
        }
    }
}

// ========================= gemm_tc: modes 0 and 3 ============================
__global__ __launch_bounds__(256, 2)
void gemm_tc(const float* __restrict__ A, int M,
             const __nv_bfloat16* __restrict__ Bpack0,
             const float* __restrict__ bias0,
             float* __restrict__ C, int ldc, int mode,
             const int* __restrict__ ei,
             const float* __restrict__ ev,
             const float* __restrict__ naux) {
    extern __shared__ char smem[];
    const int tid = threadIdx.x;
    const int lane = tid & 31, wid = tid >> 5;
    const int warp_m = wid >> 2, warp_n = wid & 3;
    const int row0 = blockIdx.x * 64;
    const int ytile = blockIdx.y;
    const __nv_bfloat16* Bpack = Bpack0 + (size_t)ytile * 32768;
    const float* bias = bias0 ? bias0 + ytile * 128 : nullptr;
    const uint32_t sb = smem_u32(smem);

    b_async_load(sb, Bpack, tid);
    {
        int r = tid >> 2, k0 = (tid & 3) * 32;
        int arow = row0 + r;
        bool vr = arow < M;
        const float4* src = (const float4*)(A + (size_t)arow * 128 + k0);
        float4 av[8];
        #pragma unroll
        for (int q = 0; q < 8; q++)
            av[q] = vr ? __ldg(src + q) : make_float4(0.f, 0.f, 0.f, 0.f);
        #pragma unroll
        for (int q = 0; q < 8; q++)
            a_split_store(smem, r, k0 + q * 4, av[q]);
    }
    CP_WAIT0();
    __syncthreads();

    float acc[2][4][4];
    zero_acc(acc);
    MmaCtx cx; mma_setup(cx, lane, warp_m, warp_n);
    mma_mainloop(acc, cx, sb);
    __syncthreads();

    float* Cs = (float*)(smem + 34816);
    stage_c(Cs, acc, lane, warp_m, warp_n);
    __syncthreads();

    const int r = tid >> 2;
    const int c0g = (tid & 3) * 32;
    const int grow = row0 + r;
    if (grow >= M) return;

    int ii = 0, jj = 0;
    float v0 = 0.f, v1 = 0.f, v2 = 0.f, vvq = 0.f;
    if (mode == 3) {
        ii = ei[grow]; jj = ei[N_EDGES + grow];
        v0 = __ldg(ev + grow * 3 + 0); v1 = __ldg(ev + grow * 3 + 1); v2 = __ldg(ev + grow * 3 + 2);
        vvq = v0 * v0 + v1 * v1 + v2 * v2;
    }
    float* dst = C + (size_t)grow * ldc + ytile * 128 + c0g;

    #pragma unroll
    for (int ch = 0; ch < 2; ch++) {
        const int cl = c0g + ch * 16;
        float d[16];
        #pragma unroll
        for (int c = 0; c < 16; c++) d[c] = Cs[r * CSTRIDE + cl + c];
        if (bias) {
            #pragma unroll
            for (int c = 0; c < 16; c++) d[c] += __ldg(bias + cl + c);
        }
        if (mode == 3) {
            float efv[16];
            #pragma unroll
            for (int q = 0; q < 8; q++) {
                uint32_t h2 = *(uint32_t*)(smem + (r * ASTRIDE + cl + q * 2) * 2);
                uint32_t l2 = *(uint32_t*)(smem + 17408 + (r * ASTRIDE + cl + q * 2) * 2);
                __nv_bfloat162 hb = *(__nv_bfloat162*)&h2;
                __nv_bfloat162 lb = *(__nv_bfloat162*)&l2;
                float2 hf = __bfloat1622float2(hb);
                float2 lf = __bfloat1622float2(lb);
                efv[q*2] = hf.x + lf.x; efv[q*2+1] = hf.y + lf.y;
            }
            const float* arow = naux + (size_t)ii * 3 * H;
            const float* brow = naux + (size_t)jj * 3 * H;
            #pragma unroll
            for (int q = 0; q < 4; q++) {
                int c = cl + 4 * q;
                float4 a0 = __ldg((const float4*)(arow + 0 * H + c));
                float4 a1 = __ldg((const float4*)(arow + 1 * H + c));
                float4 a2 = __ldg((const float4*)(arow + 2 * H + c));
                float4 b0 = __ldg((const float4*)(brow + 0 * H + c));
                float4 b1 = __ldg((const float4*)(brow + 1 * H + c));
                float4 b2 = __ldg((const float4*)(brow + 2 * H + c));
                #pragma unroll
                for (int u = 0; u < 4; u++) {
                    float ax = (&a0.x)[u], ay = (&a1.x)[u], az = (&a2.x)[u];
                    float bx = (&b0.x)[u], by = (&b1.x)[u], bz = (&b2.x)[u];
                    float ab = ax * bx + ay * by + az * bz;
                    float avd = ax * v0 + ay * v1 + az * v2;
                    float bvd = bx * v0 + by * v1 + bz * v2;
                    float sphi = ab * vvq - avd * bvd;
                    float gf = silu_f(d[4 * q + u]);
                    d[4 * q + u] = efv[4 * q + u] + gf * sphi;
                }
            }
        }
        #pragma unroll
        for (int q = 0; q < 4; q++)
            *(float4*)(dst + ch * 16 + 4 * q) =
                make_float4(d[4*q], d[4*q+1], d[4*q+2], d[4*q+3]);
    }
}

// ========================= MEGA message kernel ==============================
__global__ __launch_bounds__(256, 2)
void mega_msg(const float* __restrict__ efeat,
              const __nv_bfloat16* __restrict__ Wedge,
              const __nv_bfloat16* __restrict__ Wp1,
              const float* __restrict__ b_edge,
              const float* __restrict__ b_p1,
              const int* __restrict__ eids,
              const int* __restrict__ own,
              const int* __restrict__ ejArr,
              const float* __restrict__ distc,
              const float* __restrict__ alpha,
              const float* __restrict__ evc,
              const float* __restrict__ ns,
              const float* __restrict__ nvec,
              float* __restrict__ ns1,
              float* __restrict__ nvec1) {
    extern __shared__ char smem[];
    const int tid = threadIdx.x;
    const int lane = tid & 31, wid = tid >> 5;
    const int warp_m = wid >> 2, warp_n = wid & 3;
    const int row0 = blockIdx.x * 64;
    const uint32_t sb = smem_u32(smem);

    int* sOwn = (int*)(smem + 104448);
    int* sEj  = (int*)(smem + 104704);
    float* sEv = (float*)(smem + 104960);

    // Phase A: B = W_edge async; A = gathered edge_feats rows, split
    b_async_load(sb, Wedge, tid);
    {
        int r = tid >> 2, k0 = (tid & 3) * 32;
        int e = eids[row0 + r];
        const float4* src = (const float4*)(efeat + (size_t)e * 128 + k0);
        float4 av[8];
        #pragma unroll
        for (int q = 0; q < 8; q++) av[q] = __ldg(src + q);
        #pragma unroll
        for (int q = 0; q < 8; q++) a_split_store(smem, r, k0 + q * 4, av[q]);
    }
    if (tid < 64) {
        sOwn[tid] = own[row0 + tid];
        sEj[tid]  = ejArr[row0 + tid];
        sEv[tid * 3 + 0] = evc[(row0 + tid) * 3 + 0];
        sEv[tid * 3 + 1] = evc[(row0 + tid) * 3 + 1];
        sEv[tid * 3 + 2] = evc[(row0 + tid) * 3 + 2];
    }
    CP_WAIT0();
    __syncthreads();

    MmaCtx cx; mma_setup(cx, lane, warp_m, warp_n);

    // Phase B: ef GEMM
    float acc0[2][4][4], acc1[2][4][4];
    zero_acc(acc0);
    mma_mainloop(acc0, cx, sb);
    __syncthreads();

    float* Cs = (float*)(smem + 34816);
    stage_c(Cs, acc0, lane, warp_m, warp_n);
    __syncthreads();

    // Phase C: per-row msg epilogue (writes msg into Cs)
    {
        const int r = tid >> 2;
        const int c0g = (tid & 3) * 32;
        const int grow = row0 + r;
        int ii = sOwn[r], jj = sEj[r];
        float dd = __ldg(distc + grow);
        float cut = (dd < CUTOFF_R) ? 0.5f * (__cosf(PI_F * dd / CUTOFF_R) + 1.0f) : 0.0f;
        #pragma unroll
        for (int ch = 0; ch < 2; ch++) {
            const int cl = c0g + ch * 16;
            float d[16], nsi[16], nsj[16];
            #pragma unroll
            for (int c = 0; c < 16; c++) d[c] = Cs[r * CSTRIDE + cl + c] + __ldg(b_edge + cl + c);
            const float4* pi4 = (const float4*)(ns + (size_t)ii * H + cl);
            const float4* pj4 = (const float4*)(ns + (size_t)jj * H + cl);
            #pragma unroll
            for (int q = 0; q < 4; q++) {
                float4 a = __ldg(pi4 + q);
                nsi[4*q] = a.x; nsi[4*q+1] = a.y; nsi[4*q+2] = a.z; nsi[4*q+3] = a.w;
                float4 b = __ldg(pj4 + q);
                nsj[4*q] = b.x; nsj[4*q+1] = b.y; nsj[4*q+2] = b.z; nsj[4*q+3] = b.w;
            }
            float s = 0.f;
            #pragma unroll
            for (int c = 0; c < 16; c++) {
                float ef = silu_f(d[c]);
                d[c] = ef;
                s += silu_f(nsi[c] + nsj[c] + ef) * __ldg(alpha + cl + c);
            }
            float attn = s * cut;
            #pragma unroll
            for (int c = 0; c < 16; c++)
                Cs[r * CSTRIDE + cl + c] = nsj[c] * d[c] * attn;
        }
    }
    __syncthreads();

    // Phase D: scalar agg walk (256 threads: 2 row-halves x 128 cols)
    {
        int col = tid & 127, hf = tid >> 7;
        int rbeg = hf * 32, rend = rbeg + 32;
        float a = 0.f;
        int prev = sOwn[rbeg];
        #pragma unroll 4
        for (int r2 = rbeg; r2 < rend; r2++) {
            int o = sOwn[r2];
            float v = Cs[r2 * CSTRIDE + col];
            if (o != prev) { atomicAdd(&ns1[(size_t)prev * H + col], a); a = 0.f; prev = o; }
            a += v;
        }
        atomicAdd(&ns1[(size_t)prev * H + col], a);
    }

    // Phase E: re-split msg (Cs) to bf16 into A region
    {
        int r = tid >> 2, k0 = (tid & 3) * 32;
        float4 av[8];
        #pragma unroll
        for (int q = 0; q < 8; q++) {
            int k = k0 + q * 4;
            av[q] = make_float4(Cs[r * CSTRIDE + k], Cs[r * CSTRIDE + k + 1],
                                Cs[r * CSTRIDE + k + 2], Cs[r * CSTRIDE + k + 3]);
        }
        __syncthreads();   // all Cs reads (walk D + these) complete
        #pragma unroll
        for (int q = 0; q < 8; q++) a_split_store(smem, r, k0 + q * 4, av[q]);
    }
    __syncthreads();

    // Phase F/G: two W_p1 GEMM passes (fresh accumulators!)
    b_async_load(sb, Wp1, tid);
    CP_WAIT0();
    __syncthreads();
    zero_acc(acc0);
    mma_mainloop(acc0, cx, sb);
    __syncthreads();
    b_async_load(sb, Wp1 + 32768, tid);
    CP_WAIT0();
    __syncthreads();
    zero_acc(acc1);
    mma_mainloop(acc1, cx, sb);
    __syncthreads();

    // Phase H: stage both C tiles
    float* Cs0 = (float*)(smem + 34816);
    float* Cs1 = (float*)(smem + 68608);
    stage_c(Cs0, acc0, lane, warp_m, warp_n);
    stage_c(Cs1, acc1, lane, warp_m, warp_n);
    __syncthreads();

    // Phase I: vmsg walk (256 threads: 2 row-halves x 128 cols)
    {
        const int col = tid & 127, hf = tid >> 7;
        const int rbeg = hf * 32, rend = rbeg + 32;
        const float b1 = __ldg(b_p1 + col);
        const float b2 = __ldg(b_p1 + 128 + col);
        float a0 = 0.f, a1 = 0.f, a2 = 0.f;
        int prev = sOwn[rbeg];
        #pragma unroll 4
        for (int r2 = rbeg; r2 < rend; r2++) {
            int o = sOwn[r2];
            int j = sEj[r2];
            float s1 = silu_f(Cs0[r2 * CSTRIDE + col] + b1);
            float s2 = silu_f(Cs1[r2 * CSTRIDE + col] + b2);
            const float* nv = nvec + (size_t)j * 384 + col;
            float n0 = __ldg(nv);
            float n1 = __ldg(nv + 128);
            float n2 = __ldg(nv + 256);
            float e0 = sEv[r2 * 3 + 0], e1 = sEv[r2 * 3 + 1], e2 = sEv[r2 * 3 + 2];
            if (o != prev) {
                atomicAdd(&nvec1[(size_t)prev * 384 + col], a0);
                atomicAdd(&nvec1[(size_t)prev * 384 + 128 + col], a1);
                atomicAdd(&nvec1[(size_t)prev * 384 + 256 + col], a2);
                a0 = a1 = a2 = 0.f; prev = o;
            }
            a0 = fmaf(n0, s1, fmaf(s2, e0, a0));
            a1 = fmaf(n1, s1, fmaf(s2, e1, a1));
            a2 = fmaf(n2, s1, fmaf(s2, e2, a2));
        }
        atomicAdd(&nvec1[(size_t)prev * 384 + col], a0);
        atomicAdd(&nvec1[(size_t)prev * 384 + 128 + col], a1);
        atomicAdd(&nvec1[(size_t)prev * 384 + 256 + col], a2);
    }
}

// ========================= layernorm + residual init =========================
__global__ void ln_init(const float* __restrict__ x,
                        const float* __restrict__ nvec,
                        const float* __restrict__ gamma,
                        const float* __restrict__ beta,
                        float* __restrict__ y,
                        float* __restrict__ ns1,
                        float* __restrict__ nvec1) {
    int n = blockIdx.x;
    int h = threadIdx.x;
    float v = x[(size_t)n * H + h];
    float s = v, s2 = v * v;
    #pragma unroll
    for (int o = 16; o > 0; o >>= 1) {
        s  += __shfl_xor_sync(0xffffffffu, s, o);
        s2 += __shfl_xor_sync(0xffffffffu, s2, o);
    }
    __shared__ float rs[4], rs2[4];
    int warp = h >> 5, lane = h & 31;
    if (lane == 0) { rs[warp] = s; rs2[warp] = s2; }
    __syncthreads();
    float ts  = rs[0] + rs[1] + rs[2] + rs[3];
    float ts2 = rs2[0] + rs2[1] + rs2[2] + rs2[3];
    float mu  = ts * (1.0f / H);
    float var = ts2 * (1.0f / H) - mu * mu;
    float inv = rsqrtf(var + 1e-5f);
    y[(size_t)n * H + h] = (v - mu) * inv * gamma[h] + beta[h];
    ns1[(size_t)n * H + h] = v;
    #pragma unroll
    for (int d = 0; d < 3; d++)
        nvec1[(size_t)n * 384 + d * 128 + h] = nvec[(size_t)n * 384 + d * 128 + h];
}

// ========================= CSR build =========================
__global__ void csr_zero() {
    int n = blockIdx.x * blockDim.x + threadIdx.x;
    if (n < N_NODES) g_deg[n] = 0;
}
__global__ void csr_hist(const int* __restrict__ ei) {
    int e = blockIdx.x * blockDim.x + threadIdx.x;
    if (e < N_EDGES) atomicAdd(&g_deg[ei[e]], 1);
}
__global__ void csr_scan() {
    const int tid = threadIdx.x;
    const int lane = tid & 31, w = tid >> 5;
    __shared__ int wsum[32];
    __shared__ int carry;
    if (tid == 0) carry = 0;
    __syncthreads();
    for (int base = 0; base < N_NODES; base += 1024) {
        int idx = base + tid;
        int v = (idx < N_NODES) ? g_deg[idx] : 0;
        int s = v;
        #pragma unroll
        for (int o = 1; o < 32; o <<= 1) {
            int t = __shfl_up_sync(0xffffffffu, s, o);
            if (lane >= o) s += t;
        }
        if (lane == 31) wsum[w] = s;
        __syncthreads();
        if (w == 0) {
            int x = wsum[lane];
            #pragma unroll
            for (int o = 1; o < 32; o <<= 1) {
                int t = __shfl_up_sync(0xffffffffu, x, o);
                if (lane >= o) x += t;
            }
            wsum[lane] = x;
        }
        __syncthreads();
        int blockoff = (w > 0) ? wsum[w - 1] : 0;
        int c = carry;
        if (idx < N_NODES) {
            int excl = c + blockoff + s - v;
            g_off[idx] = excl;
            g_cur[idx] = excl;
        }
        int tot = wsum[31];
        __syncthreads();
        if (tid == 0) carry = c + tot;
        __syncthreads();
    }
    if (tid == 0) g_off[N_NODES] = carry;
}
__global__ void csr_scatter(const int* __restrict__ ei,
                            const float* __restrict__ dist,
                            const float* __restrict__ ev) {
    int e = blockIdx.x * blockDim.x + threadIdx.x;
    if (e < N_EDGES) {
        int i = ei[e];
        int j = ei[N_EDGES + e];
        int pos = atomicAdd(&g_cur[i], 1);
        g_eids[pos] = e;
        g_own[pos] = i;
        g_ej[pos] = j;
        g_distc[pos] = dist[e];
        g_evc[pos * 3 + 0] = ev[e * 3 + 0];
        g_evc[pos * 3 + 1] = ev[e * 3 + 1];
        g_evc[pos * 3 + 2] = ev[e * 3 + 2];
    }
}

// ========================= node final =========================
__global__ void node_final(float* __restrict__ out_scal,
                           float* __restrict__ out_vec) {
    int n = blockIdx.x;
    int h = threadIdx.x;
    float v1d[3], v2d[3];
    #pragma unroll
    for (int d = 0; d < 3; d++) {
        v1d[d] = g_wv[((size_t)n * 3 + d) * 256 + h];
        v2d[d] = g_wv[((size_t)n * 3 + d) * 256 + 128 + h];
    }
    float tri = v1d[0] * v2d[0] + v1d[1] * v2d[1] + v1d[2] * v2d[2];
    float sq  = v2d[0] * v2d[0] + v2d[1] * v2d[1] + v2d[2] * v2d[2];
    float nrm = sqrtf(sq + 1e-8f);
    float qua = nrm * nrm * nrm;
    float p1 = g_p[(size_t)n * 384 + h];
    float p2 = g_p[(size_t)n * 384 + 128 + h];
    float p3 = g_p[(size_t)n * 384 + 256 + h];
    out_scal[(size_t)n * H + h] = g_ns1[(size_t)n * H + h] + (qua + tri) * p1 + p2;
    #pragma unroll
    for (int d = 0; d < 3; d++) {
        out_vec[((size_t)n * 3 + d) * H + h] =
            g_nvec1[((size_t)n * 3 + d) * H + h] + v1d[d] * p3;
    }
}

// ========================= launch =========================
extern "C" void kernel_launch(void* const* d_in, const int* in_sizes, int n_in,
                              void* d_out, int out_size) {
    const float* node_scalar = (const float*)d_in[0];
    const float* node_vector = (const float*)d_in[1];
    const int*   edge_index  = (const int*)  d_in[2];
    const float* dist        = (const float*)d_in[3];
    const float* edge_feats  = (const float*)d_in[4];
    const float* edge_vector = (const float*)d_in[5];
    const float* ln_gamma    = (const float*)d_in[6];
    const float* ln_beta     = (const float*)d_in[7];
    const float* alpha       = (const float*)d_in[8];
    const float* W_cross     = (const float*)d_in[9];
    const float* W_node      = (const float*)d_in[10];
    const float* b_node      = (const float*)d_in[11];
    const float* W_edge      = (const float*)d_in[12];
    const float* b_edge      = (const float*)d_in[13];
    const float* W_p1        = (const float*)d_in[14];
    const float* b_p1        = (const float*)d_in[15];
    const float* W_p2        = (const float*)d_in[16];
    const float* b_p2        = (const float*)d_in[17];
    const float* W_vec       = (const float*)d_in[18];
    const float* W_f         = (const float*)d_in[19];
    const float* b_f         = (const float*)d_in[20];

    float* out = (float*)d_out;
    float* out_scal = out;
    float* out_vec  = out + (size_t)N_NODES * H;
    float* out_edge = out + (size_t)N_NODES * H * 4;

    float* p_scalar_out; cudaGetSymbolAddress((void**)&p_scalar_out, g_scalar_out);
    float* p_ns;    cudaGetSymbolAddress((void**)&p_ns, g_ns);
    float* p_nv;    cudaGetSymbolAddress((void**)&p_nv, g_nv);
    float* p_ns1;   cudaGetSymbolAddress((void**)&p_ns1, g_ns1);
    float* p_nvec1; cudaGetSymbolAddress((void**)&p_nvec1, g_nvec1);
    float* p_wv;    cudaGetSymbolAddress((void**)&p_wv, g_wv);
    float* p_p;     cudaGetSymbolAddress((void**)&p_p, g_p);
    __nv_bfloat16* wp; cudaGetSymbolAddress((void**)&wp, g_wpack);
    int* p_eids;  cudaGetSymbolAddress((void**)&p_eids, g_eids);
    int* p_own;   cudaGetSymbolAddress((void**)&p_own, g_own);
    int* p_ej;    cudaGetSymbolAddress((void**)&p_ej, g_ej);
    float* p_distc; cudaGetSymbolAddress((void**)&p_distc, g_distc);
    float* p_evc;   cudaGetSymbolAddress((void**)&p_evc, g_evc);

    cudaFuncSetAttribute(gemm_tc, cudaFuncAttributeMaxDynamicSharedMemorySize, SM_TOTAL);
    cudaFuncSetAttribute(mega_msg, cudaFuncAttributeMaxDynamicSharedMemorySize, SM_MEGA);

    const int GB_N  = (N_NODES + 63) / 64;        // 313
    const int GB_E  = N_EDGES / 64;               // 5000
    const int GB_3N = (3 * N_NODES + 63) / 64;    // 938

    pack_all<<<dim3(11, 8), 256>>>(W_node, W_edge, W_p1, W_cross, W_f, W_vec, W_p2);

    csr_zero<<<(N_NODES + 255) / 256, 256>>>();
    csr_hist<<<(N_EDGES + 255) / 256, 256>>>(edge_index);
    csr_scan<<<1, 1024>>>();
    csr_scatter<<<(N_EDGES + 255) / 256, 256>>>(edge_index, dist, edge_vector);

    ln_init<<<N_NODES, 128>>>(node_scalar, node_vector, ln_gamma, ln_beta,
                              p_scalar_out, p_ns1, p_nvec1);

    // ns = scalar_out @ W_node + b
    gemm_tc<<<dim3(GB_N, 1), 256, SM_TOTAL>>>(p_scalar_out, N_NODES, wp + 0 * 32768, b_node,
                                              p_ns, 128, 0, nullptr, nullptr, nullptr);

    // whole message path in one kernel
    mega_msg<<<GB_E, 256, SM_MEGA>>>(edge_feats, wp + 1 * 32768, wp + 2 * 32768,
                                     b_edge, b_p1, p_eids, p_own, p_ej, p_distc,
                                     alpha, p_evc, p_ns, node_vector, p_ns1, p_nvec1);

    // edge update path
    gemm_tc<<<dim3(GB_3N, 1), 256, SM_TOTAL>>>(node_vector, 3 * N_NODES, wp + 4 * 32768, nullptr,
                                               p_nv, 128, 0, nullptr, nullptr, nullptr);
    gemm_tc<<<dim3(GB_E, 1), 256, SM_TOTAL>>>(edge_feats, N_EDGES, wp + 5 * 32768, b_f,
                                              out_edge, 128, 3, edge_index, edge_vector, p_nv);

    // node update
    gemm_tc<<<dim3(GB_3N, 2), 256, SM_TOTAL>>>(p_nvec1, 3 * N_NODES, wp + 6 * 32768, nullptr,
                                               p_wv, 256, 0, nullptr, nullptr, nullptr);
    gemm_tc<<<dim3(GB_N, 3), 256, SM_TOTAL>>>(p_ns1, N_NODES, wp + 8 * 32768, b_p2,
                                              p_p, 384, 0, nullptr, nullptr, nullptr);
    node_final<<<N_NODES, 128>>>(out_scal, out_vec);
}

// round 8
// speedup vs baseline: 1.3581x; 1.0690x over previous
#include <cuda_runtime.h>
#include <cuda_bf16.h>
#include <math.h>
#include <stdint.h>

#define N_NODES 20000
#define N_EDGES 320000
#define H 128
#define CUTOFF_R 5.0f
#define PI_F 3.14159265358979323846f

// ========================= scratch (device globals) =========================
__device__ __align__(16) float g_scalar_out[N_NODES * H];
__device__ __align__(16) float g_ns[N_NODES * H];
__device__ __align__(16) float g_nv[N_NODES * 3 * H];
__device__ __align__(16) float g_ns1[N_NODES * H];
__device__ __align__(16) float g_nvec1[N_NODES * 3 * H];
__device__ __align__(16) float g_wv[N_NODES * 3 * 2 * H];
__device__ __align__(16) float g_p[N_NODES * 3 * H];
// packed weights, FRAGMENT order: per 128x128 tile: 8192 u32 hi + 8192 u32 lo
// entry e: r=e&7, lane=(e>>3)&31, ks=(e>>8)&7, wn=e>>11
//   nt=r>>1, half=r&1; n = wn*32+nt*8+(lane>>2); k = ks*16+half*8+(lane&3)*2
__device__ __align__(16) __nv_bfloat16 g_wpack[11 * 32768];

__device__ int g_deg[N_NODES];
__device__ int g_off[N_NODES + 1];
__device__ int g_cur[N_NODES];
__device__ int g_eids[N_EDGES];
__device__ int g_own[N_EDGES];
__device__ int g_ej[N_EDGES];
__device__ float g_distc[N_EDGES];
__device__ float g_evc[N_EDGES * 3];

// ========================= helpers =========================
__device__ __forceinline__ uint32_t smem_u32(const void* p) {
    uint32_t a;
    asm("{ .reg .u64 t; cvta.to.shared.u64 t, %1; cvt.u32.u64 %0, t; }" : "=r"(a) : "l"(p));
    return a;
}
__device__ __forceinline__ float silu_f(float x) { return x / (1.0f + __expf(-x)); }

#define LDSM4(r, addr) \
    asm volatile("ldmatrix.sync.aligned.m8n8.x4.shared.b16 {%0,%1,%2,%3}, [%4];" \
        : "=r"((r)[0]), "=r"((r)[1]), "=r"((r)[2]), "=r"((r)[3]) : "r"(addr))

#define MMA16816(c, a, b) \
    asm volatile("mma.sync.aligned.m16n8k16.row.col.f32.bf16.bf16.f32 " \
        "{%0,%1,%2,%3}, {%4,%5,%6,%7}, {%8,%9}, {%0,%1,%2,%3};" \
        : "+f"((c)[0]), "+f"((c)[1]), "+f"((c)[2]), "+f"((c)[3]) \
        : "r"((a)[0]), "r"((a)[1]), "r"((a)[2]), "r"((a)[3]), "r"((b)[0]), "r"((b)[1]))

// ========================= weight pre-pack (fragment order) ==================
__global__ void pack_all(const float* __restrict__ Wn, const float* __restrict__ We,
                         const float* __restrict__ Wp1, const float* __restrict__ Wc,
                         const float* __restrict__ Wf, const float* __restrict__ Wv,
                         const float* __restrict__ Wp2) {
    int tile = blockIdx.x;
    const float* W; int ncol, t;
    switch (tile) {
        case 0: W = Wn;  ncol = 128; t = 0; break;
        case 1: W = We;  ncol = 128; t = 0; break;
        case 2: case 3: W = Wp1; ncol = 256; t = tile - 2; break;
        case 4: W = Wc;  ncol = 128; t = 0; break;
        case 5: W = Wf;  ncol = 128; t = 0; break;
        case 6: case 7: W = Wv;  ncol = 256; t = tile - 6; break;
        default: W = Wp2; ncol = 384; t = tile - 8; break;
    }
    // fold in csr_zero (one fewer launch)
    if (blockIdx.y == 0) {
        #pragma unroll
        for (int q = 0; q < 8; q++) {
            int id = blockIdx.x * 2048 + q * 256 + threadIdx.x;
            if (id < N_NODES) g_deg[id] = 0;
        }
    }
    uint32_t* dst = (uint32_t*)(g_wpack + (size_t)tile * 32768);
    #pragma unroll
    for (int q = 0; q < 4; q++) {
        int e = (blockIdx.y * 256 + threadIdx.x) * 4 + q;   // 0..8191
        int r = e & 7, lane = (e >> 3) & 31, ks = (e >> 8) & 7, wn = e >> 11;
        int n = wn * 32 + (r >> 1) * 8 + (lane >> 2);
        int k = ks * 16 + (r & 1) * 8 + (lane & 3) * 2;
        float v0 = W[(size_t)k * ncol + t * 128 + n];
        float v1 = W[(size_t)(k + 1) * ncol + t * 128 + n];
        __nv_bfloat16 h0 = __float2bfloat16(v0);
        __nv_bfloat16 h1 = __float2bfloat16(v1);
        __nv_bfloat16 l0 = __float2bfloat16(v0 - __bfloat162float(h0));
        __nv_bfloat16 l1 = __float2bfloat16(v1 - __bfloat162float(h1));
        uint32_t hp = (uint32_t)*(uint16_t*)&h0 | ((uint32_t)*(uint16_t*)&h1 << 16);
        uint32_t lp = (uint32_t)*(uint16_t*)&l0 | ((uint32_t)*(uint16_t*)&l1 << 16);
        dst[e] = hp;
        dst[8192 + e] = lp;
    }
}

// ========================= shared GEMM plumbing ==============================
#define ASTRIDE 136
#define CSTRIDE 132
#define SM_GEMM 68608            // A(34816) + Cs(33792)
#define SM_MEGA 103680           // A + Cs0 + Cs1 + meta

__device__ __forceinline__ void a_split_store(char* smem, int r, int k0, float4 a) {
    __nv_bfloat162 h01 = __float22bfloat162_rn(make_float2(a.x, a.y));
    __nv_bfloat162 h23 = __float22bfloat162_rn(make_float2(a.z, a.w));
    float2 f01 = __bfloat1622float2(h01);
    float2 f23 = __bfloat1622float2(h23);
    __nv_bfloat162 l01 = __float22bfloat162_rn(make_float2(a.x - f01.x, a.y - f01.y));
    __nv_bfloat162 l23 = __float22bfloat162_rn(make_float2(a.z - f23.x, a.w - f23.y));
    uint2 hv, lv;
    hv.x = *(uint32_t*)&h01; hv.y = *(uint32_t*)&h23;
    lv.x = *(uint32_t*)&l01; lv.y = *(uint32_t*)&l23;
    *(uint2*)(smem + (r * ASTRIDE + k0) * 2) = hv;
    *(uint2*)(smem + 17408 + (r * ASTRIDE + k0) * 2) = lv;
}

__device__ __forceinline__ void mma_setup(uint32_t aoff[2], int lane, int warp_m) {
    const int rin = lane & 7, sel = lane >> 3;
    #pragma unroll
    for (int mt = 0; mt < 2; mt++) {
        int row = warp_m * 32 + mt * 16 + (sel & 1) * 8 + rin;
        int col = (sel >> 1) * 8;
        aoff[mt] = (uint32_t)((row * ASTRIDE + col) * 2);
    }
}

__device__ __forceinline__ void zero_acc(float acc[2][4][4]) {
    #pragma unroll
    for (int mt = 0; mt < 2; mt++)
        #pragma unroll
        for (int nt = 0; nt < 4; nt++)
            #pragma unroll
            for (int u = 0; u < 4; u++) acc[mt][nt][u] = 0.f;
}

// B fragments straight from gmem (L1-resident after first CTA on the SM)
__device__ __forceinline__ void mma_mainloop(float acc[2][4][4], const uint32_t aoff[2],
                                             uint32_t sb, const uint4* __restrict__ Bp,
                                             int warp_n, int lane) {
    const uint32_t aHi = sb, aLo = sb + 17408;
    #pragma unroll
    for (int ks = 0; ks < 8; ks++) {
        uint32_t kb = ks * 32;
        uint32_t ah[2][4], al[2][4];
        int idx = ((warp_n * 8 + ks) * 32 + lane) * 2;
        uint4 u0 = __ldg(Bp + idx);
        uint4 u1 = __ldg(Bp + idx + 1);
        uint4 l0 = __ldg(Bp + idx + 2048);
        uint4 l1 = __ldg(Bp + idx + 2049);
        LDSM4(ah[0], aHi + aoff[0] + kb);
        LDSM4(ah[1], aHi + aoff[1] + kb);
        LDSM4(al[0], aLo + aoff[0] + kb);
        LDSM4(al[1], aLo + aoff[1] + kb);
        uint32_t bh[4][2], bl[4][2];
        bh[0][0] = u0.x; bh[0][1] = u0.y; bh[1][0] = u0.z; bh[1][1] = u0.w;
        bh[2][0] = u1.x; bh[2][1] = u1.y; bh[3][0] = u1.z; bh[3][1] = u1.w;
        bl[0][0] = l0.x; bl[0][1] = l0.y; bl[1][0] = l0.z; bl[1][1] = l0.w;
        bl[2][0] = l1.x; bl[2][1] = l1.y; bl[3][0] = l1.z; bl[3][1] = l1.w;
        #pragma unroll
        for (int mt = 0; mt < 2; mt++)
            #pragma unroll
            for (int nt = 0; nt < 4; nt++) {
                MMA16816(acc[mt][nt], ah[mt], bh[nt]);
                MMA16816(acc[mt][nt], ah[mt], bl[nt]);
                MMA16816(acc[mt][nt], al[mt], bh[nt]);
            }
    }
}

__device__ __forceinline__ void stage_c(float* Cs, const float acc[2][4][4],
                                        int lane, int warp_m, int warp_n) {
    int gid = lane >> 2, tig = lane & 3;
    #pragma unroll
    for (int mt = 0; mt < 2; mt++) {
        int r = warp_m * 32 + mt * 16 + gid;
        #pragma unroll
        for (int nt = 0; nt < 4; nt++) {
            int cc = warp_n * 32 + nt * 8 + tig * 2;
            *(float2*)&Cs[r * CSTRIDE + cc] = make_float2(acc[mt][nt][0], acc[mt][nt][1]);
            *(float2*)&Cs[(r + 8) * CSTRIDE + cc] = make_float2(acc[mt][nt][2], acc[mt][nt][3]);
        }
    }
}

// ========================= gemm_tc: modes 0 and 3 ============================
__global__ __launch_bounds__(256, 3)
void gemm_tc(const float* __restrict__ A, int M,
             const __nv_bfloat16* __restrict__ Bpack0,
             const float* __restrict__ bias0,
             float* __restrict__ C, int ldc, int mode,
             const int* __restrict__ ei,
             const float* __restrict__ ev,
             const float* __restrict__ naux) {
    extern __shared__ char smem[];
    const int tid = threadIdx.x;
    const int lane = tid & 31, wid = tid >> 5;
    const int warp_m = wid >> 2, warp_n = wid & 3;
    const int row0 = blockIdx.x * 64;
    const int ytile = blockIdx.y;
    const uint4* Bp = (const uint4*)(Bpack0 + (size_t)ytile * 32768);
    const float* bias = bias0 ? bias0 + ytile * 128 : nullptr;
    const uint32_t sb = smem_u32(smem);

    {
        int r = tid >> 2, k0 = (tid & 3) * 32;
        int arow = row0 + r;
        bool vr = arow < M;
        const float4* src = (const float4*)(A + (size_t)arow * 128 + k0);
        float4 av[8];
        #pragma unroll
        for (int q = 0; q < 8; q++)
            av[q] = vr ? __ldg(src + q) : make_float4(0.f, 0.f, 0.f, 0.f);
        #pragma unroll
        for (int q = 0; q < 8; q++)
            a_split_store(smem, r, k0 + q * 4, av[q]);
    }
    __syncthreads();

    float acc[2][4][4];
    zero_acc(acc);
    uint32_t aoff[2];
    mma_setup(aoff, lane, warp_m);
    mma_mainloop(acc, aoff, sb, Bp, warp_n, lane);

    float* Cs = (float*)(smem + 34816);
    stage_c(Cs, acc, lane, warp_m, warp_n);
    __syncthreads();

    const int r = tid >> 2;
    const int c0g = (tid & 3) * 32;
    const int grow = row0 + r;
    if (grow >= M) return;

    int ii = 0, jj = 0;
    float v0 = 0.f, v1 = 0.f, v2 = 0.f, vvq = 0.f;
    if (mode == 3) {
        ii = ei[grow]; jj = ei[N_EDGES + grow];
        v0 = __ldg(ev + grow * 3 + 0); v1 = __ldg(ev + grow * 3 + 1); v2 = __ldg(ev + grow * 3 + 2);
        vvq = v0 * v0 + v1 * v1 + v2 * v2;
    }
    float* dst = C + (size_t)grow * ldc + ytile * 128 + c0g;

    #pragma unroll
    for (int ch = 0; ch < 2; ch++) {
        const int cl = c0g + ch * 16;
        float d[16];
        #pragma unroll
        for (int c = 0; c < 16; c++) d[c] = Cs[r * CSTRIDE + cl + c];
        if (bias) {
            #pragma unroll
            for (int c = 0; c < 16; c++) d[c] += __ldg(bias + cl + c);
        }
        if (mode == 3) {
            float efv[16];
            #pragma unroll
            for (int q = 0; q < 8; q++) {
                uint32_t h2 = *(uint32_t*)(smem + (r * ASTRIDE + cl + q * 2) * 2);
                uint32_t l2 = *(uint32_t*)(smem + 17408 + (r * ASTRIDE + cl + q * 2) * 2);
                __nv_bfloat162 hb = *(__nv_bfloat162*)&h2;
                __nv_bfloat162 lb = *(__nv_bfloat162*)&l2;
                float2 hf = __bfloat1622float2(hb);
                float2 lf = __bfloat1622float2(lb);
                efv[q*2] = hf.x + lf.x; efv[q*2+1] = hf.y + lf.y;
            }
            const float* arow = naux + (size_t)ii * 3 * H;
            const float* brow = naux + (size_t)jj * 3 * H;
            #pragma unroll
            for (int q = 0; q < 4; q++) {
                int c = cl + 4 * q;
                float4 a0 = __ldg((const float4*)(arow + 0 * H + c));
                float4 a1 = __ldg((const float4*)(arow + 1 * H + c));
                float4 a2 = __ldg((const float4*)(arow + 2 * H + c));
                float4 b0 = __ldg((const float4*)(brow + 0 * H + c));
                float4 b1 = __ldg((const float4*)(brow + 1 * H + c));
                float4 b2 = __ldg((const float4*)(brow + 2 * H + c));
                #pragma unroll
                for (int u = 0; u < 4; u++) {
                    float ax = (&a0.x)[u], ay = (&a1.x)[u], az = (&a2.x)[u];
                    float bx = (&b0.x)[u], by = (&b1.x)[u], bz = (&b2.x)[u];
                    float ab = ax * bx + ay * by + az * bz;
                    float avd = ax * v0 + ay * v1 + az * v2;
                    float bvd = bx * v0 + by * v1 + bz * v2;
                    float sphi = ab * vvq - avd * bvd;
                    float gf = silu_f(d[4 * q + u]);
                    d[4 * q + u] = efv[4 * q + u] + gf * sphi;
                }
            }
        }
        #pragma unroll
        for (int q = 0; q < 4; q++)
            *(float4*)(dst + ch * 16 + 4 * q) =
                make_float4(d[4*q], d[4*q+1], d[4*q+2], d[4*q+3]);
    }
}

// ========================= MEGA message kernel ==============================
__global__ __launch_bounds__(256, 2)
void mega_msg(const float* __restrict__ efeat,
              const __nv_bfloat16* __restrict__ Wedge,
              const __nv_bfloat16* __restrict__ Wp1,
              const float* __restrict__ b_edge,
              const float* __restrict__ b_p1,
              const int* __restrict__ eids,
              const int* __restrict__ own,
              const int* __restrict__ ejArr,
              const float* __restrict__ distc,
              const float* __restrict__ alpha,
              const float* __restrict__ evc,
              const float* __restrict__ ns,
              const float* __restrict__ nvec,
              float* __restrict__ ns1,
              float* __restrict__ nvec1) {
    extern __shared__ char smem[];
    const int tid = threadIdx.x;
    const int lane = tid & 31, wid = tid >> 5;
    const int warp_m = wid >> 2, warp_n = wid & 3;
    const int row0 = blockIdx.x * 64;
    const uint32_t sb = smem_u32(smem);
    const uint4* BpE = (const uint4*)Wedge;
    const uint4* Bp1a = (const uint4*)Wp1;
    const uint4* Bp1b = (const uint4*)(Wp1 + 32768);

    float* Cs0 = (float*)(smem + 34816);
    float* Cs1 = (float*)(smem + 68608);
    int* sOwn = (int*)(smem + 102400);
    int* sEj  = (int*)(smem + 102656);
    float* sEv = (float*)(smem + 102912);

    // Phase A: A = gathered edge_feats rows, split
    {
        int r = tid >> 2, k0 = (tid & 3) * 32;
        int e = eids[row0 + r];
        const float4* src = (const float4*)(efeat + (size_t)e * 128 + k0);
        float4 av[8];
        #pragma unroll
        for (int q = 0; q < 8; q++) av[q] = __ldg(src + q);
        #pragma unroll
        for (int q = 0; q < 8; q++) a_split_store(smem, r, k0 + q * 4, av[q]);
    }
    if (tid < 64) {
        sOwn[tid] = own[row0 + tid];
        sEj[tid]  = ejArr[row0 + tid];
        sEv[tid * 3 + 0] = evc[(row0 + tid) * 3 + 0];
        sEv[tid * 3 + 1] = evc[(row0 + tid) * 3 + 1];
        sEv[tid * 3 + 2] = evc[(row0 + tid) * 3 + 2];
    }
    __syncthreads();

    uint32_t aoff[2];
    mma_setup(aoff, lane, warp_m);

    // Phase B: ef GEMM
    float acc0[2][4][4], acc1[2][4][4];
    zero_acc(acc0);
    mma_mainloop(acc0, aoff, sb, BpE, warp_n, lane);
    stage_c(Cs0, acc0, lane, warp_m, warp_n);
    __syncthreads();

    // Phase C: per-row msg epilogue (msg back into Cs0)
    {
        const int r = tid >> 2;
        const int c0g = (tid & 3) * 32;
        const int grow = row0 + r;
        int ii = sOwn[r], jj = sEj[r];
        float dd = __ldg(distc + grow);
        float cut = (dd < CUTOFF_R) ? 0.5f * (__cosf(PI_F * dd / CUTOFF_R) + 1.0f) : 0.0f;
        #pragma unroll
        for (int ch = 0; ch < 2; ch++) {
            const int cl = c0g + ch * 16;
            float d[16], nsi[16], nsj[16];
            #pragma unroll
            for (int c = 0; c < 16; c++) d[c] = Cs0[r * CSTRIDE + cl + c] + __ldg(b_edge + cl + c);
            const float4* pi4 = (const float4*)(ns + (size_t)ii * H + cl);
            const float4* pj4 = (const float4*)(ns + (size_t)jj * H + cl);
            #pragma unroll
            for (int q = 0; q < 4; q++) {
                float4 a = __ldg(pi4 + q);
                nsi[4*q] = a.x; nsi[4*q+1] = a.y; nsi[4*q+2] = a.z; nsi[4*q+3] = a.w;
                float4 b = __ldg(pj4 + q);
                nsj[4*q] = b.x; nsj[4*q+1] = b.y; nsj[4*q+2] = b.z; nsj[4*q+3] = b.w;
            }
            float s = 0.f;
            #pragma unroll
            for (int c = 0; c < 16; c++) {
                float ef = silu_f(d[c]);
                d[c] = ef;
                s += silu_f(nsi[c] + nsj[c] + ef) * __ldg(alpha + cl + c);
            }
            float attn = s * cut;
            #pragma unroll
            for (int c = 0; c < 16; c++)
                Cs0[r * CSTRIDE + cl + c] = nsj[c] * d[c] * attn;
        }
    }
    __syncthreads();

    // Phase D: scalar agg walk (reads Cs0) — disjoint from Phase E's A writes
    {
        int col = tid & 127, hf = tid >> 7;
        int rbeg = hf * 32, rend = rbeg + 32;
        float a = 0.f;
        int prev = sOwn[rbeg];
        #pragma unroll 4
        for (int r2 = rbeg; r2 < rend; r2++) {
            int o = sOwn[r2];
            float v = Cs0[r2 * CSTRIDE + col];
            if (o != prev) { atomicAdd(&ns1[(size_t)prev * H + col], a); a = 0.f; prev = o; }
            a += v;
        }
        atomicAdd(&ns1[(size_t)prev * H + col], a);
    }

    // Phase E: re-split msg (own Cs0 row) into bf16 A region
    {
        int r = tid >> 2, k0 = (tid & 3) * 32;
        #pragma unroll
        for (int q = 0; q < 8; q++) {
            int k = k0 + q * 4;
            float4 a = make_float4(Cs0[r * CSTRIDE + k], Cs0[r * CSTRIDE + k + 1],
                                   Cs0[r * CSTRIDE + k + 2], Cs0[r * CSTRIDE + k + 3]);
            a_split_store(smem, r, k0 + q * 4, a);
        }
    }
    __syncthreads();

    // Phase F/G: two W_p1 GEMM passes (fresh accumulators)
    zero_acc(acc0);
    mma_mainloop(acc0, aoff, sb, Bp1a, warp_n, lane);
    zero_acc(acc1);
    mma_mainloop(acc1, aoff, sb, Bp1b, warp_n, lane);
    __syncthreads();

    // Phase H: stage both C tiles
    stage_c(Cs0, acc0, lane, warp_m, warp_n);
    stage_c(Cs1, acc1, lane, warp_m, warp_n);
    __syncthreads();

    // Phase I: vmsg walk
    {
        const int col = tid & 127, hf = tid >> 7;
        const int rbeg = hf * 32, rend = rbeg + 32;
        const float b1 = __ldg(b_p1 + col);
        const float b2 = __ldg(b_p1 + 128 + col);
        float a0 = 0.f, a1 = 0.f, a2 = 0.f;
        int prev = sOwn[rbeg];
        #pragma unroll 4
        for (int r2 = rbeg; r2 < rend; r2++) {
            int o = sOwn[r2];
            int j = sEj[r2];
            float s1 = silu_f(Cs0[r2 * CSTRIDE + col] + b1);
            float s2 = silu_f(Cs1[r2 * CSTRIDE + col] + b2);
            const float* nv = nvec + (size_t)j * 384 + col;
            float n0 = __ldg(nv);
            float n1 = __ldg(nv + 128);
            float n2 = __ldg(nv + 256);
            float e0 = sEv[r2 * 3 + 0], e1 = sEv[r2 * 3 + 1], e2 = sEv[r2 * 3 + 2];
            if (o != prev) {
                atomicAdd(&nvec1[(size_t)prev * 384 + col], a0);
                atomicAdd(&nvec1[(size_t)prev * 384 + 128 + col], a1);
                atomicAdd(&nvec1[(size_t)prev * 384 + 256 + col], a2);
                a0 = a1 = a2 = 0.f; prev = o;
            }
            a0 = fmaf(n0, s1, fmaf(s2, e0, a0));
            a1 = fmaf(n1, s1, fmaf(s2, e1, a1));
            a2 = fmaf(n2, s1, fmaf(s2, e2, a2));
        }
        atomicAdd(&nvec1[(size_t)prev * 384 + col], a0);
        atomicAdd(&nvec1[(size_t)prev * 384 + 128 + col], a1);
        atomicAdd(&nvec1[(size_t)prev * 384 + 256 + col], a2);
    }
}

// ========================= layernorm + residual init =========================
__global__ void ln_init(const float* __restrict__ x,
                        const float* __restrict__ nvec,
                        const float* __restrict__ gamma,
                        const float* __restrict__ beta,
                        float* __restrict__ y,
                        float* __restrict__ ns1,
                        float* __restrict__ nvec1) {
    int n = blockIdx.x;
    int h = threadIdx.x;
    float v = x[(size_t)n * H + h];
    float s = v, s2 = v * v;
    #pragma unroll
    for (int o = 16; o > 0; o >>= 1) {
        s  += __shfl_xor_sync(0xffffffffu, s, o);
        s2 += __shfl_xor_sync(0xffffffffu, s2, o);
    }
    __shared__ float rs[4], rs2[4];
    int warp = h >> 5, lane = h & 31;
    if (lane == 0) { rs[warp] = s; rs2[warp] = s2; }
    __syncthreads();
    float ts  = rs[0] + rs[1] + rs[2] + rs[3];
    float ts2 = rs2[0] + rs2[1] + rs2[2] + rs2[3];
    float mu  = ts * (1.0f / H);
    float var = ts2 * (1.0f / H) - mu * mu;
    float inv = rsqrtf(var + 1e-5f);
    y[(size_t)n * H + h] = (v - mu) * inv * gamma[h] + beta[h];
    ns1[(size_t)n * H + h] = v;
    #pragma unroll
    for (int d = 0; d < 3; d++)
        nvec1[(size_t)n * 384 + d * 128 + h] = nvec[(size_t)n * 384 + d * 128 + h];
}

// ========================= CSR build =========================
__global__ void csr_hist(const int* __restrict__ ei) {
    int e = blockIdx.x * blockDim.x + threadIdx.x;
    if (e < N_EDGES) atomicAdd(&g_deg[ei[e]], 1);
}
__global__ void csr_scan() {
    const int tid = threadIdx.x;
    const int lane = tid & 31, w = tid >> 5;
    __shared__ int wsum[32];
    __shared__ int carry;
    if (tid == 0) carry = 0;
    __syncthreads();
    for (int base = 0; base < N_NODES; base += 1024) {
        int idx = base + tid;
        int v = (idx < N_NODES) ? g_deg[idx] : 0;
        int s = v;
        #pragma unroll
        for (int o = 1; o < 32; o <<= 1) {
            int t = __shfl_up_sync(0xffffffffu, s, o);
            if (lane >= o) s += t;
        }
        if (lane == 31) wsum[w] = s;
        __syncthreads();
        if (w == 0) {
            int x = wsum[lane];
            #pragma unroll
            for (int o = 1; o < 32; o <<= 1) {
                int t = __shfl_up_sync(0xffffffffu, x, o);
                if (lane >= o) x += t;
            }
            wsum[lane] = x;
        }
        __syncthreads();
        int blockoff = (w > 0) ? wsum[w - 1] : 0;
        int c = carry;
        if (idx < N_NODES) {
            int excl = c + blockoff + s - v;
            g_off[idx] = excl;
            g_cur[idx] = excl;
        }
        int tot = wsum[31];
        __syncthreads();
        if (tid == 0) carry = c + tot;
        __syncthreads();
    }
    if (tid == 0) g_off[N_NODES] = carry;
}
__global__ void csr_scatter(const int* __restrict__ ei,
                            const float* __restrict__ dist,
                            const float* __restrict__ ev) {
    int e = blockIdx.x * blockDim.x + threadIdx.x;
    if (e < N_EDGES) {
        int i = ei[e];
        int j = ei[N_EDGES + e];
        int pos = atomicAdd(&g_cur[i], 1);
        g_eids[pos] = e;
        g_own[pos] = i;
        g_ej[pos] = j;
        g_distc[pos] = dist[e];
        g_evc[pos * 3 + 0] = ev[e * 3 + 0];
        g_evc[pos * 3 + 1] = ev[e * 3 + 1];
        g_evc[pos * 3 + 2] = ev[e * 3 + 2];
    }
}

// ========================= node final =========================
__global__ void node_final(float* __restrict__ out_scal,
                           float* __restrict__ out_vec) {
    int n = blockIdx.x;
    int h = threadIdx.x;
    float v1d[3], v2d[3];
    #pragma unroll
    for (int d = 0; d < 3; d++) {
        v1d[d] = g_wv[((size_t)n * 3 + d) * 256 + h];
        v2d[d] = g_wv[((size_t)n * 3 + d) * 256 + 128 + h];
    }
    float tri = v1d[0] * v2d[0] + v1d[1] * v2d[1] + v1d[2] * v2d[2];
    float sq  = v2d[0] * v2d[0] + v2d[1] * v2d[1] + v2d[2] * v2d[2];
    float nrm = sqrtf(sq + 1e-8f);
    float qua = nrm * nrm * nrm;
    float p1 = g_p[(size_t)n * 384 + h];
    float p2 = g_p[(size_t)n * 384 + 128 + h];
    float p3 = g_p[(size_t)n * 384 + 256 + h];
    out_scal[(size_t)n * H + h] = g_ns1[(size_t)n * H + h] + (qua + tri) * p1 + p2;
    #pragma unroll
    for (int d = 0; d < 3; d++) {
        out_vec[((size_t)n * 3 + d) * H + h] =
            g_nvec1[((size_t)n * 3 + d) * H + h] + v1d[d] * p3;
    }
}

// ========================= launch =========================
extern "C" void kernel_launch(void* const* d_in, const int* in_sizes, int n_in,
                              void* d_out, int out_size) {
    const float* node_scalar = (const float*)d_in[0];
    const float* node_vector = (const float*)d_in[1];
    const int*   edge_index  = (const int*)  d_in[2];
    const float* dist        = (const float*)d_in[3];
    const float* edge_feats  = (const float*)d_in[4];
    const float* edge_vector = (const float*)d_in[5];
    const float* ln_gamma    = (const float*)d_in[6];
    const float* ln_beta     = (const float*)d_in[7];
    const float* alpha       = (const float*)d_in[8];
    const float* W_cross     = (const float*)d_in[9];
    const float* W_node      = (const float*)d_in[10];
    const float* b_node      = (const float*)d_in[11];
    const float* W_edge      = (const float*)d_in[12];
    const float* b_edge      = (const float*)d_in[13];
    const float* W_p1        = (const float*)d_in[14];
    const float* b_p1        = (const float*)d_in[15];
    const float* W_p2        = (const float*)d_in[16];
    const float* b_p2        = (const float*)d_in[17];
    const float* W_vec       = (const float*)d_in[18];
    const float* W_f         = (const float*)d_in[19];
    const float* b_f         = (const float*)d_in[20];

    float* out = (float*)d_out;
    float* out_scal = out;
    float* out_vec  = out + (size_t)N_NODES * H;
    float* out_edge = out + (size_t)N_NODES * H * 4;

    float* p_scalar_out; cudaGetSymbolAddress((void**)&p_scalar_out, g_scalar_out);
    float* p_ns;    cudaGetSymbolAddress((void**)&p_ns, g_ns);
    float* p_nv;    cudaGetSymbolAddress((void**)&p_nv, g_nv);
    float* p_ns1;   cudaGetSymbolAddress((void**)&p_ns1, g_ns1);
    float* p_nvec1; cudaGetSymbolAddress((void**)&p_nvec1, g_nvec1);
    float* p_wv;    cudaGetSymbolAddress((void**)&p_wv, g_wv);
    float* p_p;     cudaGetSymbolAddress((void**)&p_p, g_p);
    __nv_bfloat16* wp; cudaGetSymbolAddress((void**)&wp, g_wpack);
    int* p_eids;  cudaGetSymbolAddress((void**)&p_eids, g_eids);
    int* p_own;   cudaGetSymbolAddress((void**)&p_own, g_own);
    int* p_ej;    cudaGetSymbolAddress((void**)&p_ej, g_ej);
    float* p_distc; cudaGetSymbolAddress((void**)&p_distc, g_distc);
    float* p_evc;   cudaGetSymbolAddress((void**)&p_evc, g_evc);

    cudaFuncSetAttribute(gemm_tc, cudaFuncAttributeMaxDynamicSharedMemorySize, SM_GEMM);
    cudaFuncSetAttribute(mega_msg, cudaFuncAttributeMaxDynamicSharedMemorySize, SM_MEGA);

    const int GB_N  = (N_NODES + 63) / 64;        // 313
    const int GB_E  = N_EDGES / 64;               // 5000
    const int GB_3N = (3 * N_NODES + 63) / 64;    // 938

    pack_all<<<dim3(11, 8), 256>>>(W_node, W_edge, W_p1, W_cross, W_f, W_vec, W_p2);

    csr_hist<<<(N_EDGES + 255) / 256, 256>>>(edge_index);
    csr_scan<<<1, 1024>>>();
    csr_scatter<<<(N_EDGES + 255) / 256, 256>>>(edge_index, dist, edge_vector);

    ln_init<<<N_NODES, 128>>>(node_scalar, node_vector, ln_gamma, ln_beta,
                              p_scalar_out, p_ns1, p_nvec1);

    // ns = scalar_out @ W_node + b
    gemm_tc<<<dim3(GB_N, 1), 256, SM_GEMM>>>(p_scalar_out, N_NODES, wp + 0 * 32768, b_node,
                                             p_ns, 128, 0, nullptr, nullptr, nullptr);

    // whole message path in one kernel
    mega_msg<<<GB_E, 256, SM_MEGA>>>(edge_feats, wp + 1 * 32768, wp + 2 * 32768,
                                     b_edge, b_p1, p_eids, p_own, p_ej, p_distc,
                                     alpha, p_evc, p_ns, node_vector, p_ns1, p_nvec1);

    // edge update path
    gemm_tc<<<dim3(GB_3N, 1), 256, SM_GEMM>>>(node_vector, 3 * N_NODES, wp + 4 * 32768, nullptr,
                                              p_nv, 128, 0, nullptr, nullptr, nullptr);
    gemm_tc<<<dim3(GB_E, 1), 256, SM_GEMM>>>(edge_feats, N_EDGES, wp + 5 * 32768, b_f,
                                             out_edge, 128, 3, edge_index, edge_vector, p_nv);

    // node update
    gemm_tc<<<dim3(GB_3N, 2), 256, SM_GEMM>>>(p_nvec1, 3 * N_NODES, wp + 6 * 32768, nullptr,
                                              p_wv, 256, 0, nullptr, nullptr, nullptr);
    gemm_tc<<<dim3(GB_N, 3), 256, SM_GEMM>>>(p_ns1, N_NODES, wp + 8 * 32768, b_p2,
                                             p_p, 384, 0, nullptr, nullptr, nullptr);
    node_final<<<N_NODES, 128>>>(out_scal, out_vec);
}

// round 9
// speedup vs baseline: 1.4830x; 1.0920x over previous
#include <cuda_runtime.h>
#include <cuda_bf16.h>
#include <math.h>
#include <stdint.h>

#define N_NODES 20000
#define N_EDGES 320000
#define H 128
#define CUTOFF_R 5.0f
#define PI_F 3.14159265358979323846f

// ========================= scratch (device globals) =========================
__device__ __align__(16) float g_ns[N_NODES * H];
__device__ __align__(16) float g_nv[N_NODES * 3 * H];
__device__ __align__(16) float g_ns1[N_NODES * H];
__device__ __align__(16) float g_nvec1[N_NODES * 3 * H];
__device__ __align__(16) float g_wv[N_NODES * 3 * 2 * H];
__device__ __align__(16) float g_p[N_NODES * 3 * H];
// packed weights, FRAGMENT order (see pack_all)
__device__ __align__(16) __nv_bfloat16 g_wpack[11 * 32768];

__device__ int g_off[N_NODES + 1];
__device__ int g_cur[N_NODES];
__device__ int g_eids[N_EDGES];
__device__ int g_own[N_EDGES];
__device__ int g_ej[N_EDGES];
__device__ float g_distc[N_EDGES];
__device__ float g_evc[N_EDGES * 3];

// ========================= helpers =========================
__device__ __forceinline__ uint32_t smem_u32(const void* p) {
    uint32_t a;
    asm("{ .reg .u64 t; cvta.to.shared.u64 t, %1; cvt.u32.u64 %0, t; }" : "=r"(a) : "l"(p));
    return a;
}
__device__ __forceinline__ float silu_f(float x) { return x / (1.0f + __expf(-x)); }

#define LDSM4(r, addr) \
    asm volatile("ldmatrix.sync.aligned.m8n8.x4.shared.b16 {%0,%1,%2,%3}, [%4];" \
        : "=r"((r)[0]), "=r"((r)[1]), "=r"((r)[2]), "=r"((r)[3]) : "r"(addr))

#define MMA16816(c, a, b) \
    asm volatile("mma.sync.aligned.m16n8k16.row.col.f32.bf16.bf16.f32 " \
        "{%0,%1,%2,%3}, {%4,%5,%6,%7}, {%8,%9}, {%0,%1,%2,%3};" \
        : "+f"((c)[0]), "+f"((c)[1]), "+f"((c)[2]), "+f"((c)[3]) \
        : "r"((a)[0]), "r"((a)[1]), "r"((a)[2]), "r"((a)[3]), "r"((b)[0]), "r"((b)[1]))

// ========================= weight pre-pack (fragment order) ==================
__global__ void pack_all(const float* __restrict__ Wn, const float* __restrict__ We,
                         const float* __restrict__ Wp1, const float* __restrict__ Wc,
                         const float* __restrict__ Wf, const float* __restrict__ Wv,
                         const float* __restrict__ Wp2) {
    int tile = blockIdx.x;
    const float* W; int ncol, t;
    switch (tile) {
        case 0: W = Wn;  ncol = 128; t = 0; break;
        case 1: W = We;  ncol = 128; t = 0; break;
        case 2: case 3: W = Wp1; ncol = 256; t = tile - 2; break;
        case 4: W = Wc;  ncol = 128; t = 0; break;
        case 5: W = Wf;  ncol = 128; t = 0; break;
        case 6: case 7: W = Wv;  ncol = 256; t = tile - 6; break;
        default: W = Wp2; ncol = 384; t = tile - 8; break;
    }
    uint32_t* dst = (uint32_t*)(g_wpack + (size_t)tile * 32768);
    #pragma unroll
    for (int q = 0; q < 4; q++) {
        int e = (blockIdx.y * 256 + threadIdx.x) * 4 + q;   // 0..8191
        int r = e & 7, lane = (e >> 3) & 31, ks = (e >> 8) & 7, wn = e >> 11;
        int n = wn * 32 + (r >> 1) * 8 + (lane >> 2);
        int k = ks * 16 + (r & 1) * 8 + (lane & 3) * 2;
        float v0 = W[(size_t)k * ncol + t * 128 + n];
        float v1 = W[(size_t)(k + 1) * ncol + t * 128 + n];
        __nv_bfloat16 h0 = __float2bfloat16(v0);
        __nv_bfloat16 h1 = __float2bfloat16(v1);
        __nv_bfloat16 l0 = __float2bfloat16(v0 - __bfloat162float(h0));
        __nv_bfloat16 l1 = __float2bfloat16(v1 - __bfloat162float(h1));
        uint32_t hp = (uint32_t)*(uint16_t*)&h0 | ((uint32_t)*(uint16_t*)&h1 << 16);
        uint32_t lp = (uint32_t)*(uint16_t*)&l0 | ((uint32_t)*(uint16_t*)&l1 << 16);
        dst[e] = hp;
        dst[8192 + e] = lp;
    }
}

// ========================= single-block CSR build (hist + scan) ==============
__global__ void csr_build(const int* __restrict__ ei) {
    extern __shared__ int sh[];          // N_NODES ints (80000 B)
    const int tid = threadIdx.x;
    const int lane = tid & 31, w = tid >> 5;
    __shared__ int wsum[32];
    __shared__ int carry;
    for (int i = tid; i < N_NODES; i += 1024) sh[i] = 0;
    if (tid == 0) carry = 0;
    __syncthreads();
    for (int e = tid; e < N_EDGES; e += 1024)
        atomicAdd(&sh[__ldg(ei + e)], 1);
    __syncthreads();
    for (int base = 0; base < N_NODES; base += 1024) {
        int idx = base + tid;
        int v = (idx < N_NODES) ? sh[idx] : 0;
        int s = v;
        #pragma unroll
        for (int o = 1; o < 32; o <<= 1) {
            int t = __shfl_up_sync(0xffffffffu, s, o);
            if (lane >= o) s += t;
        }
        if (lane == 31) wsum[w] = s;
        __syncthreads();
        if (w == 0) {
            int x = wsum[lane];
            #pragma unroll
            for (int o = 1; o < 32; o <<= 1) {
                int t = __shfl_up_sync(0xffffffffu, x, o);
                if (lane >= o) x += t;
            }
            wsum[lane] = x;
        }
        __syncthreads();
        int blockoff = (w > 0) ? wsum[w - 1] : 0;
        int c = carry;
        if (idx < N_NODES) {
            int excl = c + blockoff + s - v;
            g_off[idx] = excl;
            g_cur[idx] = excl;
        }
        int tot = wsum[31];
        __syncthreads();
        if (tid == 0) carry = c + tot;
        __syncthreads();
    }
    if (tid == 0) g_off[N_NODES] = carry;
}

__global__ void csr_scatter(const int* __restrict__ ei,
                            const float* __restrict__ dist,
                            const float* __restrict__ ev) {
    int e = blockIdx.x * blockDim.x + threadIdx.x;
    if (e < N_EDGES) {
        int i = ei[e];
        int j = ei[N_EDGES + e];
        int pos = atomicAdd(&g_cur[i], 1);
        g_eids[pos] = e;
        g_own[pos] = i;
        g_ej[pos] = j;
        g_distc[pos] = dist[e];
        g_evc[pos * 3 + 0] = ev[e * 3 + 0];
        g_evc[pos * 3 + 1] = ev[e * 3 + 1];
        g_evc[pos * 3 + 2] = ev[e * 3 + 2];
    }
}

// ========================= shared GEMM plumbing ==============================
#define ASTRIDE 136
#define CSTRIDE 132
#define SM_GEMM 68608            // A(34816) + Cs(33792)
#define SM_MEGA 103936           // A + Cs0 + Cs1 + meta

__device__ __forceinline__ void a_split_store(char* smem, int r, int k0, float4 a) {
    __nv_bfloat162 h01 = __float22bfloat162_rn(make_float2(a.x, a.y));
    __nv_bfloat162 h23 = __float22bfloat162_rn(make_float2(a.z, a.w));
    float2 f01 = __bfloat1622float2(h01);
    float2 f23 = __bfloat1622float2(h23);
    __nv_bfloat162 l01 = __float22bfloat162_rn(make_float2(a.x - f01.x, a.y - f01.y));
    __nv_bfloat162 l23 = __float22bfloat162_rn(make_float2(a.z - f23.x, a.w - f23.y));
    uint2 hv, lv;
    hv.x = *(uint32_t*)&h01; hv.y = *(uint32_t*)&h23;
    lv.x = *(uint32_t*)&l01; lv.y = *(uint32_t*)&l23;
    *(uint2*)(smem + (r * ASTRIDE + k0) * 2) = hv;
    *(uint2*)(smem + 17408 + (r * ASTRIDE + k0) * 2) = lv;
}

__device__ __forceinline__ void mma_setup(uint32_t aoff[2], int lane, int warp_m) {
    const int rin = lane & 7, sel = lane >> 3;
    #pragma unroll
    for (int mt = 0; mt < 2; mt++) {
        int row = warp_m * 32 + mt * 16 + (sel & 1) * 8 + rin;
        int col = (sel >> 1) * 8;
        aoff[mt] = (uint32_t)((row * ASTRIDE + col) * 2);
    }
}

__device__ __forceinline__ void zero_acc(float acc[2][4][4]) {
    #pragma unroll
    for (int mt = 0; mt < 2; mt++)
        #pragma unroll
        for (int nt = 0; nt < 4; nt++)
            #pragma unroll
            for (int u = 0; u < 4; u++) acc[mt][nt][u] = 0.f;
}

__device__ __forceinline__ void mma_mainloop(float acc[2][4][4], const uint32_t aoff[2],
                                             uint32_t sb, const uint4* __restrict__ Bp,
                                             int warp_n, int lane) {
    const uint32_t aHi = sb, aLo = sb + 17408;
    #pragma unroll
    for (int ks = 0; ks < 8; ks++) {
        uint32_t kb = ks * 32;
        uint32_t ah[2][4], al[2][4];
        int idx = ((warp_n * 8 + ks) * 32 + lane) * 2;
        uint4 u0 = __ldg(Bp + idx);
        uint4 u1 = __ldg(Bp + idx + 1);
        uint4 l0 = __ldg(Bp + idx + 2048);
        uint4 l1 = __ldg(Bp + idx + 2049);
        LDSM4(ah[0], aHi + aoff[0] + kb);
        LDSM4(ah[1], aHi + aoff[1] + kb);
        LDSM4(al[0], aLo + aoff[0] + kb);
        LDSM4(al[1], aLo + aoff[1] + kb);
        uint32_t bh[4][2], bl[4][2];
        bh[0][0] = u0.x; bh[0][1] = u0.y; bh[1][0] = u0.z; bh[1][1] = u0.w;
        bh[2][0] = u1.x; bh[2][1] = u1.y; bh[3][0] = u1.z; bh[3][1] = u1.w;
        bl[0][0] = l0.x; bl[0][1] = l0.y; bl[1][0] = l0.z; bl[1][1] = l0.w;
        bl[2][0] = l1.x; bl[2][1] = l1.y; bl[3][0] = l1.z; bl[3][1] = l1.w;
        #pragma unroll
        for (int mt = 0; mt < 2; mt++)
            #pragma unroll
            for (int nt = 0; nt < 4; nt++) {
                MMA16816(acc[mt][nt], ah[mt], bh[nt]);
                MMA16816(acc[mt][nt], ah[mt], bl[nt]);
                MMA16816(acc[mt][nt], al[mt], bh[nt]);
            }
    }
}

__device__ __forceinline__ void stage_c(float* Cs, const float acc[2][4][4],
                                        int lane, int warp_m, int warp_n) {
    int gid = lane >> 2, tig = lane & 3;
    #pragma unroll
    for (int mt = 0; mt < 2; mt++) {
        int r = warp_m * 32 + mt * 16 + gid;
        #pragma unroll
        for (int nt = 0; nt < 4; nt++) {
            int cc = warp_n * 32 + nt * 8 + tig * 2;
            *(float2*)&Cs[r * CSTRIDE + cc] = make_float2(acc[mt][nt][0], acc[mt][nt][1]);
            *(float2*)&Cs[(r + 8) * CSTRIDE + cc] = make_float2(acc[mt][nt][2], acc[mt][nt][3]);
        }
    }
}

// ========================= gemm_tc ==========================================
// mode 0: C = gemm + bias
// mode 1: LayerNorm prologue on A; also writes raw A to aux (=ns1)
// mode 2: writes raw A to aux (=nvec1)
__global__ __launch_bounds__(256, 3)
void gemm_tc(const float* __restrict__ A, int M,
             const __nv_bfloat16* __restrict__ Bpack0,
             const float* __restrict__ bias0,
             float* __restrict__ C, int ldc, int mode,
             const float* __restrict__ gamma,
             const float* __restrict__ beta,
             float* __restrict__ aux) {
    extern __shared__ char smem[];
    const int tid = threadIdx.x;
    const int lane = tid & 31, wid = tid >> 5;
    const int warp_m = wid >> 2, warp_n = wid & 3;
    const int row0 = blockIdx.x * 64;
    const int ytile = blockIdx.y;
    const uint4* Bp = (const uint4*)(Bpack0 + (size_t)ytile * 32768);
    const float* bias = bias0 ? bias0 + ytile * 128 : nullptr;
    const uint32_t sb = smem_u32(smem);

    {
        int r = tid >> 2, k0 = (tid & 3) * 32;
        int arow = row0 + r;
        bool vr = arow < M;
        const float4* src = (const float4*)(A + (size_t)arow * 128 + k0);
        float4 av[8];
        #pragma unroll
        for (int q = 0; q < 8; q++)
            av[q] = vr ? __ldg(src + q) : make_float4(0.f, 0.f, 0.f, 0.f);

        if (mode >= 1 && vr && ytile == 0) {
            float4* dstaux = (float4*)(aux + (size_t)arow * 128 + k0);
            #pragma unroll
            for (int q = 0; q < 8; q++) dstaux[q] = av[q];
        }
        if (mode == 1) {
            float s = 0.f, s2 = 0.f;
            #pragma unroll
            for (int q = 0; q < 8; q++) {
                s  += av[q].x + av[q].y + av[q].z + av[q].w;
                s2 += av[q].x*av[q].x + av[q].y*av[q].y + av[q].z*av[q].z + av[q].w*av[q].w;
            }
            s  += __shfl_xor_sync(0xffffffffu, s, 1);
            s  += __shfl_xor_sync(0xffffffffu, s, 2);
            s2 += __shfl_xor_sync(0xffffffffu, s2, 1);
            s2 += __shfl_xor_sync(0xffffffffu, s2, 2);
            float mu = s * (1.0f / H);
            float var = s2 * (1.0f / H) - mu * mu;
            float inv = rsqrtf(var + 1e-5f);
            #pragma unroll
            for (int q = 0; q < 8; q++) {
                int k = k0 + q * 4;
                float4 gm = __ldg((const float4*)(gamma + k));
                float4 bt = __ldg((const float4*)(beta + k));
                av[q].x = (av[q].x - mu) * inv * gm.x + bt.x;
                av[q].y = (av[q].y - mu) * inv * gm.y + bt.y;
                av[q].z = (av[q].z - mu) * inv * gm.z + bt.z;
                av[q].w = (av[q].w - mu) * inv * gm.w + bt.w;
            }
        }
        #pragma unroll
        for (int q = 0; q < 8; q++)
            a_split_store(smem, r, k0 + q * 4, av[q]);
    }
    __syncthreads();

    float acc[2][4][4];
    zero_acc(acc);
    uint32_t aoff[2];
    mma_setup(aoff, lane, warp_m);
    mma_mainloop(acc, aoff, sb, Bp, warp_n, lane);

    float* Cs = (float*)(smem + 34816);
    stage_c(Cs, acc, lane, warp_m, warp_n);
    __syncthreads();

    const int r = tid >> 2;
    const int c0g = (tid & 3) * 32;
    const int grow = row0 + r;
    if (grow >= M) return;
    float* dst = C + (size_t)grow * ldc + ytile * 128 + c0g;

    #pragma unroll
    for (int ch = 0; ch < 2; ch++) {
        const int cl = c0g + ch * 16;
        float d[16];
        #pragma unroll
        for (int c = 0; c < 16; c++) d[c] = Cs[r * CSTRIDE + cl + c];
        if (bias) {
            #pragma unroll
            for (int c = 0; c < 16; c++) d[c] += __ldg(bias + cl + c);
        }
        #pragma unroll
        for (int q = 0; q < 4; q++)
            *(float4*)(dst + ch * 16 + 4 * q) =
                make_float4(d[4*q], d[4*q+1], d[4*q+2], d[4*q+3]);
    }
}

// ========================= MEGA message + edge-final kernel ==================
__global__ __launch_bounds__(256, 2)
void mega_msg(const float* __restrict__ efeat,
              const __nv_bfloat16* __restrict__ Wedge,
              const __nv_bfloat16* __restrict__ Wp1,
              const __nv_bfloat16* __restrict__ Wf,
              const float* __restrict__ b_edge,
              const float* __restrict__ b_p1,
              const float* __restrict__ b_f,
              const int* __restrict__ eids,
              const int* __restrict__ own,
              const int* __restrict__ ejArr,
              const float* __restrict__ distc,
              const float* __restrict__ alpha,
              const float* __restrict__ evc,
              const float* __restrict__ ns,
              const float* __restrict__ nvec,
              const float* __restrict__ nv_cross,
              float* __restrict__ ns1,
              float* __restrict__ nvec1,
              float* __restrict__ out_edge) {
    extern __shared__ char smem[];
    const int tid = threadIdx.x;
    const int lane = tid & 31, wid = tid >> 5;
    const int warp_m = wid >> 2, warp_n = wid & 3;
    const int row0 = blockIdx.x * 64;
    const uint32_t sb = smem_u32(smem);
    const uint4* BpE = (const uint4*)Wedge;
    const uint4* Bp1a = (const uint4*)Wp1;
    const uint4* Bp1b = (const uint4*)(Wp1 + 32768);
    const uint4* BpF = (const uint4*)Wf;

    float* Cs0 = (float*)(smem + 34816);
    float* Cs1 = (float*)(smem + 68608);
    int* sOwn = (int*)(smem + 102400);
    int* sEj  = (int*)(smem + 102656);
    float* sEv = (float*)(smem + 102912);
    int* sEid = (int*)(smem + 103680);

    // Phase A: A = gathered edge_feats rows, split
    {
        int r = tid >> 2, k0 = (tid & 3) * 32;
        int e = eids[row0 + r];
        const float4* src = (const float4*)(efeat + (size_t)e * 128 + k0);
        float4 av[8];
        #pragma unroll
        for (int q = 0; q < 8; q++) av[q] = __ldg(src + q);
        #pragma unroll
        for (int q = 0; q < 8; q++) a_split_store(smem, r, k0 + q * 4, av[q]);
    }
    if (tid < 64) {
        sOwn[tid] = own[row0 + tid];
        sEj[tid]  = ejArr[row0 + tid];
        sEid[tid] = eids[row0 + tid];
        sEv[tid * 3 + 0] = evc[(row0 + tid) * 3 + 0];
        sEv[tid * 3 + 1] = evc[(row0 + tid) * 3 + 1];
        sEv[tid * 3 + 2] = evc[(row0 + tid) * 3 + 2];
    }
    __syncthreads();

    uint32_t aoff[2];
    mma_setup(aoff, lane, warp_m);

    // Phase B: ef GEMM (W_edge)
    float acc0[2][4][4], acc1[2][4][4];
    zero_acc(acc0);
    mma_mainloop(acc0, aoff, sb, BpE, warp_n, lane);
    stage_c(Cs0, acc0, lane, warp_m, warp_n);
    __syncthreads();

    // Phase C: per-row msg epilogue (msg back into Cs0)
    {
        const int r = tid >> 2;
        const int c0g = (tid & 3) * 32;
        const int grow = row0 + r;
        int ii = sOwn[r], jj = sEj[r];
        float dd = __ldg(distc + grow);
        float cut = (dd < CUTOFF_R) ? 0.5f * (__cosf(PI_F * dd / CUTOFF_R) + 1.0f) : 0.0f;
        #pragma unroll
        for (int ch = 0; ch < 2; ch++) {
            const int cl = c0g + ch * 16;
            float d[16], nsi[16], nsj[16];
            #pragma unroll
            for (int c = 0; c < 16; c++) d[c] = Cs0[r * CSTRIDE + cl + c] + __ldg(b_edge + cl + c);
            const float4* pi4 = (const float4*)(ns + (size_t)ii * H + cl);
            const float4* pj4 = (const float4*)(ns + (size_t)jj * H + cl);
            #pragma unroll
            for (int q = 0; q < 4; q++) {
                float4 a = __ldg(pi4 + q);
                nsi[4*q] = a.x; nsi[4*q+1] = a.y; nsi[4*q+2] = a.z; nsi[4*q+3] = a.w;
                float4 b = __ldg(pj4 + q);
                nsj[4*q] = b.x; nsj[4*q+1] = b.y; nsj[4*q+2] = b.z; nsj[4*q+3] = b.w;
            }
            float s = 0.f;
            #pragma unroll
            for (int c = 0; c < 16; c++) {
                float ef = silu_f(d[c]);
                d[c] = ef;
                s += silu_f(nsi[c] + nsj[c] + ef) * __ldg(alpha + cl + c);
            }
            float attn = s * cut;
            #pragma unroll
            for (int c = 0; c < 16; c++)
                Cs0[r * CSTRIDE + cl + c] = nsj[c] * d[c] * attn;
        }
    }
    __syncthreads();

    // Phase D2a: W_f GEMM (A still holds efeat)
    zero_acc(acc1);
    mma_mainloop(acc1, aoff, sb, BpF, warp_n, lane);
    stage_c(Cs1, acc1, lane, warp_m, warp_n);
    __syncthreads();

    // Phase D2b: edge-final epilogue (reads Cs1 + A own quarter) -> out_edge
    {
        const int r = tid >> 2;
        const int c0g = (tid & 3) * 32;
        int ii = sOwn[r], jj = sEj[r];
        int eorig = sEid[r];
        float v0 = sEv[r * 3 + 0], v1 = sEv[r * 3 + 1], v2 = sEv[r * 3 + 2];
        float vvq = v0 * v0 + v1 * v1 + v2 * v2;
        const float* arow = nv_cross + (size_t)ii * 3 * H;
        const float* brow = nv_cross + (size_t)jj * 3 * H;
        float* dst = out_edge + (size_t)eorig * H + c0g;
        #pragma unroll
        for (int ch = 0; ch < 2; ch++) {
            const int cl = c0g + ch * 16;
            float d[16];
            #pragma unroll
            for (int c = 0; c < 16; c++) d[c] = Cs1[r * CSTRIDE + cl + c] + __ldg(b_f + cl + c);
            float efv[16];
            #pragma unroll
            for (int q = 0; q < 8; q++) {
                uint32_t h2 = *(uint32_t*)(smem + (r * ASTRIDE + cl + q * 2) * 2);
                uint32_t l2 = *(uint32_t*)(smem + 17408 + (r * ASTRIDE + cl + q * 2) * 2);
                __nv_bfloat162 hb = *(__nv_bfloat162*)&h2;
                __nv_bfloat162 lb = *(__nv_bfloat162*)&l2;
                float2 hf = __bfloat1622float2(hb);
                float2 lf = __bfloat1622float2(lb);
                efv[q*2] = hf.x + lf.x; efv[q*2+1] = hf.y + lf.y;
            }
            #pragma unroll
            for (int q = 0; q < 4; q++) {
                int c = cl + 4 * q;
                float4 a0 = __ldg((const float4*)(arow + 0 * H + c));
                float4 a1 = __ldg((const float4*)(arow + 1 * H + c));
                float4 a2 = __ldg((const float4*)(arow + 2 * H + c));
                float4 b0 = __ldg((const float4*)(brow + 0 * H + c));
                float4 b1 = __ldg((const float4*)(brow + 1 * H + c));
                float4 b2 = __ldg((const float4*)(brow + 2 * H + c));
                float o4[4];
                #pragma unroll
                for (int u = 0; u < 4; u++) {
                    float ax = (&a0.x)[u], ay = (&a1.x)[u], az = (&a2.x)[u];
                    float bx = (&b0.x)[u], by = (&b1.x)[u], bz = (&b2.x)[u];
                    float ab = ax * bx + ay * by + az * bz;
                    float avd = ax * v0 + ay * v1 + az * v2;
                    float bvd = bx * v0 + by * v1 + bz * v2;
                    float sphi = ab * vvq - avd * bvd;
                    float gf = silu_f(d[4 * q + u]);
                    o4[u] = efv[4 * q + u] + gf * sphi;
                }
                *(float4*)(dst + ch * 16 + 4 * q) = make_float4(o4[0], o4[1], o4[2], o4[3]);
            }
        }
    }

    // Phase D: scalar agg walk (reads Cs0)
    {
        int col = tid & 127, hf = tid >> 7;
        int rbeg = hf * 32, rend = rbeg + 32;
        float a = 0.f;
        int prev = sOwn[rbeg];
        #pragma unroll 4
        for (int r2 = rbeg; r2 < rend; r2++) {
            int o = sOwn[r2];
            float v = Cs0[r2 * CSTRIDE + col];
            if (o != prev) { atomicAdd(&ns1[(size_t)prev * H + col], a); a = 0.f; prev = o; }
            a += v;
        }
        atomicAdd(&ns1[(size_t)prev * H + col], a);
    }

    // Phase E: re-split msg (own Cs0 row) into bf16 A region (own quarter)
    {
        int r = tid >> 2, k0 = (tid & 3) * 32;
        #pragma unroll
        for (int q = 0; q < 8; q++) {
            int k = k0 + q * 4;
            float4 a = make_float4(Cs0[r * CSTRIDE + k], Cs0[r * CSTRIDE + k + 1],
                                   Cs0[r * CSTRIDE + k + 2], Cs0[r * CSTRIDE + k + 3]);
            a_split_store(smem, r, k0 + q * 4, a);
        }
    }
    __syncthreads();

    // Phase F/G: two W_p1 GEMM passes
    zero_acc(acc0);
    mma_mainloop(acc0, aoff, sb, Bp1a, warp_n, lane);
    zero_acc(acc1);
    mma_mainloop(acc1, aoff, sb, Bp1b, warp_n, lane);
    __syncthreads();

    stage_c(Cs0, acc0, lane, warp_m, warp_n);
    stage_c(Cs1, acc1, lane, warp_m, warp_n);
    __syncthreads();

    // Phase I: vmsg walk
    {
        const int col = tid & 127, hf = tid >> 7;
        const int rbeg = hf * 32, rend = rbeg + 32;
        const float b1 = __ldg(b_p1 + col);
        const float b2 = __ldg(b_p1 + 128 + col);
        float a0 = 0.f, a1 = 0.f, a2 = 0.f;
        int prev = sOwn[rbeg];
        #pragma unroll 4
        for (int r2 = rbeg; r2 < rend; r2++) {
            int o = sOwn[r2];
            int j = sEj[r2];
            float s1 = silu_f(Cs0[r2 * CSTRIDE + col] + b1);
            float s2 = silu_f(Cs1[r2 * CSTRIDE + col] + b2);
            const float* nv = nvec + (size_t)j * 384 + col;
            float n0 = __ldg(nv);
            float n1 = __ldg(nv + 128);
            float n2 = __ldg(nv + 256);
            float e0 = sEv[r2 * 3 + 0], e1 = sEv[r2 * 3 + 1], e2 = sEv[r2 * 3 + 2];
            if (o != prev) {
                atomicAdd(&nvec1[(size_t)prev * 384 + col], a0);
                atomicAdd(&nvec1[(size_t)prev * 384 + 128 + col], a1);
                atomicAdd(&nvec1[(size_t)prev * 384 + 256 + col], a2);
                a0 = a1 = a2 = 0.f; prev = o;
            }
            a0 = fmaf(n0, s1, fmaf(s2, e0, a0));
            a1 = fmaf(n1, s1, fmaf(s2, e1, a1));
            a2 = fmaf(n2, s1, fmaf(s2, e2, a2));
        }
        atomicAdd(&nvec1[(size_t)prev * 384 + col], a0);
        atomicAdd(&nvec1[(size_t)prev * 384 + 128 + col], a1);
        atomicAdd(&nvec1[(size_t)prev * 384 + 256 + col], a2);
    }
}

// ========================= node final =========================
__global__ void node_final(float* __restrict__ out_scal,
                           float* __restrict__ out_vec) {
    int n = blockIdx.x;
    int h = threadIdx.x;
    float v1d[3], v2d[3];
    #pragma unroll
    for (int d = 0; d < 3; d++) {
        v1d[d] = g_wv[((size_t)n * 3 + d) * 256 + h];
        v2d[d] = g_wv[((size_t)n * 3 + d) * 256 + 128 + h];
    }
    float tri = v1d[0] * v2d[0] + v1d[1] * v2d[1] + v1d[2] * v2d[2];
    float sq  = v2d[0] * v2d[0] + v2d[1] * v2d[1] + v2d[2] * v2d[2];
    float nrm = sqrtf(sq + 1e-8f);
    float qua = nrm * nrm * nrm;
    float p1 = g_p[(size_t)n * 384 + h];
    float p2 = g_p[(size_t)n * 384 + 128 + h];
    float p3 = g_p[(size_t)n * 384 + 256 + h];
    out_scal[(size_t)n * H + h] = g_ns1[(size_t)n * H + h] + (qua + tri) * p1 + p2;
    #pragma unroll
    for (int d = 0; d < 3; d++) {
        out_vec[((size_t)n * 3 + d) * H + h] =
            g_nvec1[((size_t)n * 3 + d) * H + h] + v1d[d] * p3;
    }
}

// ========================= launch =========================
extern "C" void kernel_launch(void* const* d_in, const int* in_sizes, int n_in,
                              void* d_out, int out_size) {
    const float* node_scalar = (const float*)d_in[0];
    const float* node_vector = (const float*)d_in[1];
    const int*   edge_index  = (const int*)  d_in[2];
    const float* dist        = (const float*)d_in[3];
    const float* edge_feats  = (const float*)d_in[4];
    const float* edge_vector = (const float*)d_in[5];
    const float* ln_gamma    = (const float*)d_in[6];
    const float* ln_beta     = (const float*)d_in[7];
    const float* alpha       = (const float*)d_in[8];
    const float* W_cross     = (const float*)d_in[9];
    const float* W_node      = (const float*)d_in[10];
    const float* b_node      = (const float*)d_in[11];
    const float* W_edge      = (const float*)d_in[12];
    const float* b_edge      = (const float*)d_in[13];
    const float* W_p1        = (const float*)d_in[14];
    const float* b_p1        = (const float*)d_in[15];
    const float* W_p2        = (const float*)d_in[16];
    const float* b_p2        = (const float*)d_in[17];
    const float* W_vec       = (const float*)d_in[18];
    const float* W_f         = (const float*)d_in[19];
    const float* b_f         = (const float*)d_in[20];

    float* out = (float*)d_out;
    float* out_scal = out;
    float* out_vec  = out + (size_t)N_NODES * H;
    float* out_edge = out + (size_t)N_NODES * H * 4;

    float* p_ns;    cudaGetSymbolAddress((void**)&p_ns, g_ns);
    float* p_nv;    cudaGetSymbolAddress((void**)&p_nv, g_nv);
    float* p_ns1;   cudaGetSymbolAddress((void**)&p_ns1, g_ns1);
    float* p_nvec1; cudaGetSymbolAddress((void**)&p_nvec1, g_nvec1);
    float* p_wv;    cudaGetSymbolAddress((void**)&p_wv, g_wv);
    float* p_p;     cudaGetSymbolAddress((void**)&p_p, g_p);
    __nv_bfloat16* wp; cudaGetSymbolAddress((void**)&wp, g_wpack);
    int* p_eids;  cudaGetSymbolAddress((void**)&p_eids, g_eids);
    int* p_own;   cudaGetSymbolAddress((void**)&p_own, g_own);
    int* p_ej;    cudaGetSymbolAddress((void**)&p_ej, g_ej);
    float* p_distc; cudaGetSymbolAddress((void**)&p_distc, g_distc);
    float* p_evc;   cudaGetSymbolAddress((void**)&p_evc, g_evc);

    cudaFuncSetAttribute(gemm_tc, cudaFuncAttributeMaxDynamicSharedMemorySize, SM_GEMM);
    cudaFuncSetAttribute(mega_msg, cudaFuncAttributeMaxDynamicSharedMemorySize, SM_MEGA);
    cudaFuncSetAttribute(csr_build, cudaFuncAttributeMaxDynamicSharedMemorySize, N_NODES * 4);

    const int GB_N  = (N_NODES + 63) / 64;        // 313
    const int GB_E  = N_EDGES / 64;               // 5000
    const int GB_3N = (3 * N_NODES + 63) / 64;    // 938

    // 1
    pack_all<<<dim3(11, 8), 256>>>(W_node, W_edge, W_p1, W_cross, W_f, W_vec, W_p2);
    // 2
    csr_build<<<1, 1024, N_NODES * 4>>>(edge_index);
    // 3
    csr_scatter<<<(N_EDGES + 255) / 256, 256>>>(edge_index, dist, edge_vector);
    // 4: ns = LN(node_scalar) @ W_node + b ; also ns1 = node_scalar
    gemm_tc<<<dim3(GB_N, 1), 256, SM_GEMM>>>(node_scalar, N_NODES, wp + 0 * 32768, b_node,
                                             p_ns, 128, 1, ln_gamma, ln_beta, p_ns1);
    // 5: nv = node_vector @ W_cross ; also nvec1 = node_vector
    gemm_tc<<<dim3(GB_3N, 1), 256, SM_GEMM>>>(node_vector, 3 * N_NODES, wp + 4 * 32768, nullptr,
                                              p_nv, 128, 2, nullptr, nullptr, p_nvec1);
    // 6: whole message path + edge update in one kernel (PROFILED)
    mega_msg<<<GB_E, 256, SM_MEGA>>>(edge_feats, wp + 1 * 32768, wp + 2 * 32768, wp + 5 * 32768,
                                     b_edge, b_p1, b_f, p_eids, p_own, p_ej, p_distc,
                                     alpha, p_evc, p_ns, node_vector, p_nv,
                                     p_ns1, p_nvec1, out_edge);
    // 7: wv = nvec1 @ W_vec (both tiles)
    gemm_tc<<<dim3(GB_3N, 2), 256, SM_GEMM>>>(p_nvec1, 3 * N_NODES, wp + 6 * 32768, nullptr,
                                              p_wv, 256, 0, nullptr, nullptr, nullptr);
    // 8: p = ns1 @ W_p2 + b (3 tiles)
    gemm_tc<<<dim3(GB_N, 3), 256, SM_GEMM>>>(p_ns1, N_NODES, wp + 8 * 32768, b_p2,
                                             p_p, 384, 0, nullptr, nullptr, nullptr);
    // 9
    node_final<<<N_NODES, 128>>>(out_scal, out_vec);
}

// round 10
// speedup vs baseline: 1.5151x; 1.0216x over previous
#include <cuda_runtime.h>
#include <cuda_bf16.h>
#include <math.h>
#include <stdint.h>

#define N_NODES 20000
#define N_EDGES 320000
#define H 128
#define CUTOFF_R 5.0f
#define PI_F 3.14159265358979323846f

// ========================= scratch (device globals) =========================
__device__ __align__(16) float g_ns[N_NODES * H];
__device__ __align__(16) float g_nv[N_NODES * 3 * H];
__device__ __align__(16) float g_ns1[N_NODES * H];
__device__ __align__(16) float g_nvec1[N_NODES * 3 * H];
__device__ __align__(16) float g_wv[N_NODES * 3 * 2 * H];
__device__ __align__(16) float g_p[N_NODES * 3 * H];
__device__ __align__(16) __nv_bfloat16 g_wpack[11 * 32768];

__device__ int g_off[N_NODES + 1];
__device__ int g_cur[N_NODES];
__device__ int g_eids[N_EDGES];
__device__ int g_own[N_EDGES];
__device__ int g_ej[N_EDGES];
__device__ float g_distc[N_EDGES];
__device__ float g_evc[N_EDGES * 3];

// ========================= helpers =========================
__device__ __forceinline__ uint32_t smem_u32(const void* p) {
    uint32_t a;
    asm("{ .reg .u64 t; cvta.to.shared.u64 t, %1; cvt.u32.u64 %0, t; }" : "=r"(a) : "l"(p));
    return a;
}
__device__ __forceinline__ float silu_f(float x) { return x / (1.0f + __expf(-x)); }

#define LDSM4(r, addr) \
    asm volatile("ldmatrix.sync.aligned.m8n8.x4.shared.b16 {%0,%1,%2,%3}, [%4];" \
        : "=r"((r)[0]), "=r"((r)[1]), "=r"((r)[2]), "=r"((r)[3]) : "r"(addr))

#define MMA16816(c, a, b) \
    asm volatile("mma.sync.aligned.m16n8k16.row.col.f32.bf16.bf16.f32 " \
        "{%0,%1,%2,%3}, {%4,%5,%6,%7}, {%8,%9}, {%0,%1,%2,%3};" \
        : "+f"((c)[0]), "+f"((c)[1]), "+f"((c)[2]), "+f"((c)[3]) \
        : "r"((a)[0]), "r"((a)[1]), "r"((a)[2]), "r"((a)[3]), "r"((b)[0]), "r"((b)[1]))

// ========================= weight pre-pack (fragment order) ==================
__global__ void pack_all(const float* __restrict__ Wn, const float* __restrict__ We,
                         const float* __restrict__ Wp1, const float* __restrict__ Wc,
                         const float* __restrict__ Wf, const float* __restrict__ Wv,
                         const float* __restrict__ Wp2) {
    int tile = blockIdx.x;
    const float* W; int ncol, t;
    switch (tile) {
        case 0: W = Wn;  ncol = 128; t = 0; break;
        case 1: W = We;  ncol = 128; t = 0; break;
        case 2: case 3: W = Wp1; ncol = 256; t = tile - 2; break;
        case 4: W = Wc;  ncol = 128; t = 0; break;
        case 5: W = Wf;  ncol = 128; t = 0; break;
        case 6: case 7: W = Wv;  ncol = 256; t = tile - 6; break;
        default: W = Wp2; ncol = 384; t = tile - 8; break;
    }
    uint32_t* dst = (uint32_t*)(g_wpack + (size_t)tile * 32768);
    #pragma unroll
    for (int q = 0; q < 4; q++) {
        int e = (blockIdx.y * 256 + threadIdx.x) * 4 + q;   // 0..8191
        int r = e & 7, lane = (e >> 3) & 31, ks = (e >> 8) & 7, wn = e >> 11;
        int n = wn * 32 + (r >> 1) * 8 + (lane >> 2);
        int k = ks * 16 + (r & 1) * 8 + (lane & 3) * 2;
        float v0 = W[(size_t)k * ncol + t * 128 + n];
        float v1 = W[(size_t)(k + 1) * ncol + t * 128 + n];
        __nv_bfloat16 h0 = __float2bfloat16(v0);
        __nv_bfloat16 h1 = __float2bfloat16(v1);
        __nv_bfloat16 l0 = __float2bfloat16(v0 - __bfloat162float(h0));
        __nv_bfloat16 l1 = __float2bfloat16(v1 - __bfloat162float(h1));
        uint32_t hp = (uint32_t)*(uint16_t*)&h0 | ((uint32_t)*(uint16_t*)&h1 << 16);
        uint32_t lp = (uint32_t)*(uint16_t*)&l0 | ((uint32_t)*(uint16_t*)&l1 << 16);
        dst[e] = hp;
        dst[8192 + e] = lp;
    }
}

// ========================= single-block CSR build ============================
__global__ void csr_build(const int* __restrict__ ei) {
    extern __shared__ int sh[];          // N_NODES ints
    const int tid = threadIdx.x;
    const int lane = tid & 31, w = tid >> 5;
    __shared__ int wsum[32];
    __shared__ int carry;
    for (int i = tid; i < N_NODES; i += 1024) sh[i] = 0;
    if (tid == 0) carry = 0;
    __syncthreads();
    for (int e = tid; e < N_EDGES; e += 1024)
        atomicAdd(&sh[__ldg(ei + e)], 1);
    __syncthreads();
    for (int base = 0; base < N_NODES; base += 1024) {
        int idx = base + tid;
        int v = (idx < N_NODES) ? sh[idx] : 0;
        int s = v;
        #pragma unroll
        for (int o = 1; o < 32; o <<= 1) {
            int t = __shfl_up_sync(0xffffffffu, s, o);
            if (lane >= o) s += t;
        }
        if (lane == 31) wsum[w] = s;
        __syncthreads();
        if (w == 0) {
            int x = wsum[lane];
            #pragma unroll
            for (int o = 1; o < 32; o <<= 1) {
                int t = __shfl_up_sync(0xffffffffu, x, o);
                if (lane >= o) x += t;
            }
            wsum[lane] = x;
        }
        __syncthreads();
        int blockoff = (w > 0) ? wsum[w - 1] : 0;
        int c = carry;
        if (idx < N_NODES) {
            int excl = c + blockoff + s - v;
            g_off[idx] = excl;
            g_cur[idx] = excl;
        }
        int tot = wsum[31];
        __syncthreads();
        if (tid == 0) carry = c + tot;
        __syncthreads();
    }
    if (tid == 0) g_off[N_NODES] = carry;
}

__global__ void csr_scatter(const int* __restrict__ ei,
                            const float* __restrict__ dist,
                            const float* __restrict__ ev) {
    int e = blockIdx.x * blockDim.x + threadIdx.x;
    if (e < N_EDGES) {
        int i = ei[e];
        int j = ei[N_EDGES + e];
        int pos = atomicAdd(&g_cur[i], 1);
        g_eids[pos] = e;
        g_own[pos] = i;
        g_ej[pos] = j;
        g_distc[pos] = dist[e];
        g_evc[pos * 3 + 0] = ev[e * 3 + 0];
        g_evc[pos * 3 + 1] = ev[e * 3 + 1];
        g_evc[pos * 3 + 2] = ev[e * 3 + 2];
    }
}

// ========================= shared GEMM plumbing ==============================
#define ASTRIDE 136
#define CSTRIDE 132
#define SM_GEMM 34816            // A region; Cs reuses it post-mainloop
#define SM_MEGA 103936

__device__ __forceinline__ void a_split_store(char* smem, int r, int k0, float4 a) {
    __nv_bfloat162 h01 = __float22bfloat162_rn(make_float2(a.x, a.y));
    __nv_bfloat162 h23 = __float22bfloat162_rn(make_float2(a.z, a.w));
    float2 f01 = __bfloat1622float2(h01);
    float2 f23 = __bfloat1622float2(h23);
    __nv_bfloat162 l01 = __float22bfloat162_rn(make_float2(a.x - f01.x, a.y - f01.y));
    __nv_bfloat162 l23 = __float22bfloat162_rn(make_float2(a.z - f23.x, a.w - f23.y));
    uint2 hv, lv;
    hv.x = *(uint32_t*)&h01; hv.y = *(uint32_t*)&h23;
    lv.x = *(uint32_t*)&l01; lv.y = *(uint32_t*)&l23;
    *(uint2*)(smem + (r * ASTRIDE + k0) * 2) = hv;
    *(uint2*)(smem + 17408 + (r * ASTRIDE + k0) * 2) = lv;
}

__device__ __forceinline__ void mma_setup(uint32_t aoff[2], int lane, int warp_m) {
    const int rin = lane & 7, sel = lane >> 3;
    #pragma unroll
    for (int mt = 0; mt < 2; mt++) {
        int row = warp_m * 32 + mt * 16 + (sel & 1) * 8 + rin;
        int col = (sel >> 1) * 8;
        aoff[mt] = (uint32_t)((row * ASTRIDE + col) * 2);
    }
}

__device__ __forceinline__ void zero_acc(float acc[2][4][4]) {
    #pragma unroll
    for (int mt = 0; mt < 2; mt++)
        #pragma unroll
        for (int nt = 0; nt < 4; nt++)
            #pragma unroll
            for (int u = 0; u < 4; u++) acc[mt][nt][u] = 0.f;
}

__device__ __forceinline__ void mma_mainloop(float acc[2][4][4], const uint32_t aoff[2],
                                             uint32_t sb, const uint4* __restrict__ Bp,
                                             int warp_n, int lane) {
    const uint32_t aHi = sb, aLo = sb + 17408;
    #pragma unroll
    for (int ks = 0; ks < 8; ks++) {
        uint32_t kb = ks * 32;
        uint32_t ah[2][4], al[2][4];
        int idx = ((warp_n * 8 + ks) * 32 + lane) * 2;
        uint4 u0 = __ldg(Bp + idx);
        uint4 u1 = __ldg(Bp + idx + 1);
        uint4 l0 = __ldg(Bp + idx + 2048);
        uint4 l1 = __ldg(Bp + idx + 2049);
        LDSM4(ah[0], aHi + aoff[0] + kb);
        LDSM4(ah[1], aHi + aoff[1] + kb);
        LDSM4(al[0], aLo + aoff[0] + kb);
        LDSM4(al[1], aLo + aoff[1] + kb);
        uint32_t bh[4][2], bl[4][2];
        bh[0][0] = u0.x; bh[0][1] = u0.y; bh[1][0] = u0.z; bh[1][1] = u0.w;
        bh[2][0] = u1.x; bh[2][1] = u1.y; bh[3][0] = u1.z; bh[3][1] = u1.w;
        bl[0][0] = l0.x; bl[0][1] = l0.y; bl[1][0] = l0.z; bl[1][1] = l0.w;
        bl[2][0] = l1.x; bl[2][1] = l1.y; bl[3][0] = l1.z; bl[3][1] = l1.w;
        #pragma unroll
        for (int mt = 0; mt < 2; mt++)
            #pragma unroll
            for (int nt = 0; nt < 4; nt++) {
                MMA16816(acc[mt][nt], ah[mt], bh[nt]);
                MMA16816(acc[mt][nt], ah[mt], bl[nt]);
                MMA16816(acc[mt][nt], al[mt], bh[nt]);
            }
    }
}

__device__ __forceinline__ void stage_c(float* Cs, const float acc[2][4][4],
                                        int lane, int warp_m, int warp_n) {
    int gid = lane >> 2, tig = lane & 3;
    #pragma unroll
    for (int mt = 0; mt < 2; mt++) {
        int r = warp_m * 32 + mt * 16 + gid;
        #pragma unroll
        for (int nt = 0; nt < 4; nt++) {
            int cc = warp_n * 32 + nt * 8 + tig * 2;
            *(float2*)&Cs[r * CSTRIDE + cc] = make_float2(acc[mt][nt][0], acc[mt][nt][1]);
            *(float2*)&Cs[(r + 8) * CSTRIDE + cc] = make_float2(acc[mt][nt][2], acc[mt][nt][3]);
        }
    }
}

// ========================= GEMM body (modes 0,1,2) ===========================
// mode 0: C = gemm + bias
// mode 1: LayerNorm prologue on A; raw A -> aux
// mode 2: raw A -> aux
__device__ __forceinline__ void gemm_body(
        char* smem,
        const float* __restrict__ A, int M,
        const __nv_bfloat16* __restrict__ Bpack,
        const float* __restrict__ bias,
        float* __restrict__ C, int ldc, int mode,
        const float* __restrict__ gamma,
        const float* __restrict__ beta,
        float* __restrict__ aux,
        int row0, int ncoff) {
    const int tid = threadIdx.x;
    const int lane = tid & 31, wid = tid >> 5;
    const int warp_m = wid >> 2, warp_n = wid & 3;
    const uint4* Bp = (const uint4*)Bpack;
    const uint32_t sb = smem_u32(smem);

    {
        int r = tid >> 2, k0 = (tid & 3) * 32;
        int arow = row0 + r;
        bool vr = arow < M;
        const float4* src = (const float4*)(A + (size_t)arow * 128 + k0);
        float4 av[8];
        #pragma unroll
        for (int q = 0; q < 8; q++)
            av[q] = vr ? __ldg(src + q) : make_float4(0.f, 0.f, 0.f, 0.f);

        if (mode >= 1 && vr) {
            float4* dstaux = (float4*)(aux + (size_t)arow * 128 + k0);
            #pragma unroll
            for (int q = 0; q < 8; q++) dstaux[q] = av[q];
        }
        if (mode == 1) {
            float s = 0.f, s2 = 0.f;
            #pragma unroll
            for (int q = 0; q < 8; q++) {
                s  += av[q].x + av[q].y + av[q].z + av[q].w;
                s2 += av[q].x*av[q].x + av[q].y*av[q].y + av[q].z*av[q].z + av[q].w*av[q].w;
            }
            s  += __shfl_xor_sync(0xffffffffu, s, 1);
            s  += __shfl_xor_sync(0xffffffffu, s, 2);
            s2 += __shfl_xor_sync(0xffffffffu, s2, 1);
            s2 += __shfl_xor_sync(0xffffffffu, s2, 2);
            float mu = s * (1.0f / H);
            float var = s2 * (1.0f / H) - mu * mu;
            float inv = rsqrtf(var + 1e-5f);
            #pragma unroll
            for (int q = 0; q < 8; q++) {
                int k = k0 + q * 4;
                float4 gm = __ldg((const float4*)(gamma + k));
                float4 bt = __ldg((const float4*)(beta + k));
                av[q].x = (av[q].x - mu) * inv * gm.x + bt.x;
                av[q].y = (av[q].y - mu) * inv * gm.y + bt.y;
                av[q].z = (av[q].z - mu) * inv * gm.z + bt.z;
                av[q].w = (av[q].w - mu) * inv * gm.w + bt.w;
            }
        }
        #pragma unroll
        for (int q = 0; q < 8; q++)
            a_split_store(smem, r, k0 + q * 4, av[q]);
    }
    __syncthreads();

    float acc[2][4][4];
    zero_acc(acc);
    uint32_t aoff[2];
    mma_setup(aoff, lane, warp_m);
    mma_mainloop(acc, aoff, sb, Bp, warp_n, lane);
    __syncthreads();                       // all LDSM reads of A done

    float* Cs = (float*)smem;              // reuse A region
    stage_c(Cs, acc, lane, warp_m, warp_n);
    __syncthreads();

    const int r = tid >> 2;
    const int c0g = (tid & 3) * 32;
    const int grow = row0 + r;
    if (grow >= M) return;
    float* dst = C + (size_t)grow * ldc + ncoff + c0g;

    #pragma unroll
    for (int ch = 0; ch < 2; ch++) {
        const int cl = c0g + ch * 16;
        float d[16];
        #pragma unroll
        for (int c = 0; c < 16; c++) d[c] = Cs[r * CSTRIDE + cl + c];
        if (bias) {
            #pragma unroll
            for (int c = 0; c < 16; c++) d[c] += __ldg(bias + cl + c);
        }
        #pragma unroll
        for (int q = 0; q < 4; q++)
            *(float4*)(dst + ch * 16 + 4 * q) =
                make_float4(d[4*q], d[4*q+1], d[4*q+2], d[4*q+3]);
    }
}

#define GB_N  ((N_NODES + 63) / 64)       // 313
#define GB_3N ((3 * N_NODES + 63) / 64)   // 938
#define GB_E  (N_EDGES / 64)              // 5000

// ===== combined launch A: ns = LN(ns0)@Wn + b  AND  nv = nvec@Wc ============
__global__ __launch_bounds__(256, 4)
void gemmA(const float* __restrict__ node_scalar,
           const float* __restrict__ node_vector,
           const __nv_bfloat16* __restrict__ wpN,
           const __nv_bfloat16* __restrict__ wpC,
           const float* __restrict__ b_node,
           const float* __restrict__ gamma,
           const float* __restrict__ beta,
           float* __restrict__ ns, float* __restrict__ nv,
           float* __restrict__ ns1, float* __restrict__ nvec1) {
    extern __shared__ char smem[];
    int bx = blockIdx.x;
    if (bx < GB_3N) {
        gemm_body(smem, node_vector, 3 * N_NODES, wpC, nullptr,
                  nv, 128, 2, nullptr, nullptr, nvec1, bx * 64, 0);
    } else {
        gemm_body(smem, node_scalar, N_NODES, wpN, b_node,
                  ns, 128, 1, gamma, beta, ns1, (bx - GB_3N) * 64, 0);
    }
}

// ===== combined launch B: wv = nvec1@Wv (2 tiles) AND p = ns1@Wp2 (3 tiles) ==
__global__ __launch_bounds__(256, 4)
void gemmB(const float* __restrict__ nvec1,
           const float* __restrict__ ns1,
           const __nv_bfloat16* __restrict__ wpV,
           const __nv_bfloat16* __restrict__ wpP2,
           const float* __restrict__ b_p2,
           float* __restrict__ wv, float* __restrict__ p) {
    extern __shared__ char smem[];
    int bx = blockIdx.x;
    if (bx < GB_3N * 2) {
        int yt = bx & 1, rb = bx >> 1;
        gemm_body(smem, nvec1, 3 * N_NODES, wpV + (size_t)yt * 32768, nullptr,
                  wv, 256, 0, nullptr, nullptr, nullptr, rb * 64, yt * 128);
    } else {
        int idx = bx - GB_3N * 2;
        int yt = idx % 3, rb = idx / 3;
        gemm_body(smem, ns1, N_NODES, wpP2 + (size_t)yt * 32768, b_p2 + yt * 128,
                  p, 384, 0, nullptr, nullptr, nullptr, rb * 64, yt * 128);
    }
}

// ========================= MEGA message + edge-final kernel ==================
__global__ __launch_bounds__(256, 2)
void mega_msg(const float* __restrict__ efeat,
              const __nv_bfloat16* __restrict__ Wedge,
              const __nv_bfloat16* __restrict__ Wp1,
              const __nv_bfloat16* __restrict__ Wf,
              const float* __restrict__ b_edge,
              const float* __restrict__ b_p1,
              const float* __restrict__ b_f,
              const int* __restrict__ eids,
              const int* __restrict__ own,
              const int* __restrict__ ejArr,
              const float* __restrict__ distc,
              const float* __restrict__ alpha,
              const float* __restrict__ evc,
              const float* __restrict__ ns,
              const float* __restrict__ nvec,
              const float* __restrict__ nv_cross,
              float* __restrict__ ns1,
              float* __restrict__ nvec1,
              float* __restrict__ out_edge) {
    extern __shared__ char smem[];
    const int tid = threadIdx.x;
    const int lane = tid & 31, wid = tid >> 5;
    const int warp_m = wid >> 2, warp_n = wid & 3;
    const int row0 = blockIdx.x * 64;
    const uint32_t sb = smem_u32(smem);
    const uint4* BpE = (const uint4*)Wedge;
    const uint4* Bp1a = (const uint4*)Wp1;
    const uint4* Bp1b = (const uint4*)(Wp1 + 32768);
    const uint4* BpF = (const uint4*)Wf;

    float* Cs0 = (float*)(smem + 34816);
    float* Cs1 = (float*)(smem + 68608);
    int* sOwn = (int*)(smem + 102400);
    int* sEj  = (int*)(smem + 102656);
    float* sEv = (float*)(smem + 102912);
    int* sEid = (int*)(smem + 103680);

    // Phase A: A = gathered edge_feats rows, split
    {
        int r = tid >> 2, k0 = (tid & 3) * 32;
        int e = eids[row0 + r];
        const float4* src = (const float4*)(efeat + (size_t)e * 128 + k0);
        float4 av[8];
        #pragma unroll
        for (int q = 0; q < 8; q++) av[q] = __ldg(src + q);
        #pragma unroll
        for (int q = 0; q < 8; q++) a_split_store(smem, r, k0 + q * 4, av[q]);
    }
    if (tid < 64) {
        sOwn[tid] = own[row0 + tid];
        sEj[tid]  = ejArr[row0 + tid];
        sEid[tid] = eids[row0 + tid];
        sEv[tid * 3 + 0] = evc[(row0 + tid) * 3 + 0];
        sEv[tid * 3 + 1] = evc[(row0 + tid) * 3 + 1];
        sEv[tid * 3 + 2] = evc[(row0 + tid) * 3 + 2];
    }
    __syncthreads();

    uint32_t aoff[2];
    mma_setup(aoff, lane, warp_m);

    // Phase B: ef GEMM (W_edge)
    float acc0[2][4][4], acc1[2][4][4];
    zero_acc(acc0);
    mma_mainloop(acc0, aoff, sb, BpE, warp_n, lane);
    stage_c(Cs0, acc0, lane, warp_m, warp_n);
    __syncthreads();

    // Phase C: per-row msg epilogue (msg back into Cs0)
    {
        const int r = tid >> 2;
        const int c0g = (tid & 3) * 32;
        const int grow = row0 + r;
        int ii = sOwn[r], jj = sEj[r];
        float dd = __ldg(distc + grow);
        float cut = (dd < CUTOFF_R) ? 0.5f * (__cosf(PI_F * dd / CUTOFF_R) + 1.0f) : 0.0f;
        #pragma unroll
        for (int ch = 0; ch < 2; ch++) {
            const int cl = c0g + ch * 16;
            float d[16], nsi[16], nsj[16];
            #pragma unroll
            for (int c = 0; c < 16; c++) d[c] = Cs0[r * CSTRIDE + cl + c] + __ldg(b_edge + cl + c);
            const float4* pi4 = (const float4*)(ns + (size_t)ii * H + cl);
            const float4* pj4 = (const float4*)(ns + (size_t)jj * H + cl);
            #pragma unroll
            for (int q = 0; q < 4; q++) {
                float4 a = __ldg(pi4 + q);
                nsi[4*q] = a.x; nsi[4*q+1] = a.y; nsi[4*q+2] = a.z; nsi[4*q+3] = a.w;
                float4 b = __ldg(pj4 + q);
                nsj[4*q] = b.x; nsj[4*q+1] = b.y; nsj[4*q+2] = b.z; nsj[4*q+3] = b.w;
            }
            float s = 0.f;
            #pragma unroll
            for (int c = 0; c < 16; c++) {
                float ef = silu_f(d[c]);
                d[c] = ef;
                s += silu_f(nsi[c] + nsj[c] + ef) * __ldg(alpha + cl + c);
            }
            float attn = s * cut;
            #pragma unroll
            for (int c = 0; c < 16; c++)
                Cs0[r * CSTRIDE + cl + c] = nsj[c] * d[c] * attn;
        }
    }
    __syncthreads();

    // Phase D2a: W_f GEMM (A still holds efeat)
    zero_acc(acc1);
    mma_mainloop(acc1, aoff, sb, BpF, warp_n, lane);
    stage_c(Cs1, acc1, lane, warp_m, warp_n);
    __syncthreads();

    // Phase D2b: edge-final epilogue -> out_edge
    {
        const int r = tid >> 2;
        const int c0g = (tid & 3) * 32;
        int ii = sOwn[r], jj = sEj[r];
        int eorig = sEid[r];
        float v0 = sEv[r * 3 + 0], v1 = sEv[r * 3 + 1], v2 = sEv[r * 3 + 2];
        float vvq = v0 * v0 + v1 * v1 + v2 * v2;
        const float* arow = nv_cross + (size_t)ii * 3 * H;
        const float* brow = nv_cross + (size_t)jj * 3 * H;
        float* dst = out_edge + (size_t)eorig * H + c0g;
        #pragma unroll
        for (int ch = 0; ch < 2; ch++) {
            const int cl = c0g + ch * 16;
            float d[16];
            #pragma unroll
            for (int c = 0; c < 16; c++) d[c] = Cs1[r * CSTRIDE + cl + c] + __ldg(b_f + cl + c);
            float efv[16];
            #pragma unroll
            for (int q = 0; q < 8; q++) {
                uint32_t h2 = *(uint32_t*)(smem + (r * ASTRIDE + cl + q * 2) * 2);
                uint32_t l2 = *(uint32_t*)(smem + 17408 + (r * ASTRIDE + cl + q * 2) * 2);
                __nv_bfloat162 hb = *(__nv_bfloat162*)&h2;
                __nv_bfloat162 lb = *(__nv_bfloat162*)&l2;
                float2 hf = __bfloat1622float2(hb);
                float2 lf = __bfloat1622float2(lb);
                efv[q*2] = hf.x + lf.x; efv[q*2+1] = hf.y + lf.y;
            }
            #pragma unroll
            for (int q = 0; q < 4; q++) {
                int c = cl + 4 * q;
                float4 a0 = __ldg((const float4*)(arow + 0 * H + c));
                float4 a1 = __ldg((const float4*)(arow + 1 * H + c));
                float4 a2 = __ldg((const float4*)(arow + 2 * H + c));
                float4 b0 = __ldg((const float4*)(brow + 0 * H + c));
                float4 b1 = __ldg((const float4*)(brow + 1 * H + c));
                float4 b2 = __ldg((const float4*)(brow + 2 * H + c));
                float o4[4];
                #pragma unroll
                for (int u = 0; u < 4; u++) {
                    float ax = (&a0.x)[u], ay = (&a1.x)[u], az = (&a2.x)[u];
                    float bx = (&b0.x)[u], by = (&b1.x)[u], bz = (&b2.x)[u];
                    float ab = ax * bx + ay * by + az * bz;
                    float avd = ax * v0 + ay * v1 + az * v2;
                    float bvd = bx * v0 + by * v1 + bz * v2;
                    float sphi = ab * vvq - avd * bvd;
                    float gf = silu_f(d[4 * q + u]);
                    o4[u] = efv[4 * q + u] + gf * sphi;
                }
                *(float4*)(dst + ch * 16 + 4 * q) = make_float4(o4[0], o4[1], o4[2], o4[3]);
            }
        }
    }

    // Phase D: scalar agg walk (reads Cs0)
    {
        int col = tid & 127, hf = tid >> 7;
        int rbeg = hf * 32, rend = rbeg + 32;
        float a = 0.f;
        int prev = sOwn[rbeg];
        #pragma unroll 4
        for (int r2 = rbeg; r2 < rend; r2++) {
            int o = sOwn[r2];
            float v = Cs0[r2 * CSTRIDE + col];
            if (o != prev) { atomicAdd(&ns1[(size_t)prev * H + col], a); a = 0.f; prev = o; }
            a += v;
        }
        atomicAdd(&ns1[(size_t)prev * H + col], a);
    }

    // Phase E: re-split msg (own Cs0 row) into bf16 A region (own quarter)
    {
        int r = tid >> 2, k0 = (tid & 3) * 32;
        #pragma unroll
        for (int q = 0; q < 8; q++) {
            int k = k0 + q * 4;
            float4 a = make_float4(Cs0[r * CSTRIDE + k], Cs0[r * CSTRIDE + k + 1],
                                   Cs0[r * CSTRIDE + k + 2], Cs0[r * CSTRIDE + k + 3]);
            a_split_store(smem, r, k0 + q * 4, a);
        }
    }
    __syncthreads();

    // Phase F/G: two W_p1 GEMM passes
    zero_acc(acc0);
    mma_mainloop(acc0, aoff, sb, Bp1a, warp_n, lane);
    zero_acc(acc1);
    mma_mainloop(acc1, aoff, sb, Bp1b, warp_n, lane);
    __syncthreads();

    stage_c(Cs0, acc0, lane, warp_m, warp_n);
    stage_c(Cs1, acc1, lane, warp_m, warp_n);
    __syncthreads();

    // Phase I: vmsg walk
    {
        const int col = tid & 127, hf = tid >> 7;
        const int rbeg = hf * 32, rend = rbeg + 32;
        const float b1 = __ldg(b_p1 + col);
        const float b2 = __ldg(b_p1 + 128 + col);
        float a0 = 0.f, a1 = 0.f, a2 = 0.f;
        int prev = sOwn[rbeg];
        #pragma unroll 4
        for (int r2 = rbeg; r2 < rend; r2++) {
            int o = sOwn[r2];
            int j = sEj[r2];
            float s1 = silu_f(Cs0[r2 * CSTRIDE + col] + b1);
            float s2 = silu_f(Cs1[r2 * CSTRIDE + col] + b2);
            const float* nv = nvec + (size_t)j * 384 + col;
            float n0 = __ldg(nv);
            float n1 = __ldg(nv + 128);
            float n2 = __ldg(nv + 256);
            float e0 = sEv[r2 * 3 + 0], e1 = sEv[r2 * 3 + 1], e2 = sEv[r2 * 3 + 2];
            if (o != prev) {
                atomicAdd(&nvec1[(size_t)prev * 384 + col], a0);
                atomicAdd(&nvec1[(size_t)prev * 384 + 128 + col], a1);
                atomicAdd(&nvec1[(size_t)prev * 384 + 256 + col], a2);
                a0 = a1 = a2 = 0.f; prev = o;
            }
            a0 = fmaf(n0, s1, fmaf(s2, e0, a0));
            a1 = fmaf(n1, s1, fmaf(s2, e1, a1));
            a2 = fmaf(n2, s1, fmaf(s2, e2, a2));
        }
        atomicAdd(&nvec1[(size_t)prev * 384 + col], a0);
        atomicAdd(&nvec1[(size_t)prev * 384 + 128 + col], a1);
        atomicAdd(&nvec1[(size_t)prev * 384 + 256 + col], a2);
    }
}

// ========================= node final =========================
__global__ void node_final(float* __restrict__ out_scal,
                           float* __restrict__ out_vec) {
    int n = blockIdx.x;
    int h = threadIdx.x;
    float v1d[3], v2d[3];
    #pragma unroll
    for (int d = 0; d < 3; d++) {
        v1d[d] = g_wv[((size_t)n * 3 + d) * 256 + h];
        v2d[d] = g_wv[((size_t)n * 3 + d) * 256 + 128 + h];
    }
    float tri = v1d[0] * v2d[0] + v1d[1] * v2d[1] + v1d[2] * v2d[2];
    float sq  = v2d[0] * v2d[0] + v2d[1] * v2d[1] + v2d[2] * v2d[2];
    float nrm = sqrtf(sq + 1e-8f);
    float qua = nrm * nrm * nrm;
    float p1 = g_p[(size_t)n * 384 + h];
    float p2 = g_p[(size_t)n * 384 + 128 + h];
    float p3 = g_p[(size_t)n * 384 + 256 + h];
    out_scal[(size_t)n * H + h] = g_ns1[(size_t)n * H + h] + (qua + tri) * p1 + p2;
    #pragma unroll
    for (int d = 0; d < 3; d++) {
        out_vec[((size_t)n * 3 + d) * H + h] =
            g_nvec1[((size_t)n * 3 + d) * H + h] + v1d[d] * p3;
    }
}

// ========================= launch =========================
extern "C" void kernel_launch(void* const* d_in, const int* in_sizes, int n_in,
                              void* d_out, int out_size) {
    const float* node_scalar = (const float*)d_in[0];
    const float* node_vector = (const float*)d_in[1];
    const int*   edge_index  = (const int*)  d_in[2];
    const float* dist        = (const float*)d_in[3];
    const float* edge_feats  = (const float*)d_in[4];
    const float* edge_vector = (const float*)d_in[5];
    const float* ln_gamma    = (const float*)d_in[6];
    const float* ln_beta     = (const float*)d_in[7];
    const float* alpha       = (const float*)d_in[8];
    const float* W_cross     = (const float*)d_in[9];
    const float* W_node      = (const float*)d_in[10];
    const float* b_node      = (const float*)d_in[11];
    const float* W_edge      = (const float*)d_in[12];
    const float* b_edge      = (const float*)d_in[13];
    const float* W_p1        = (const float*)d_in[14];
    const float* b_p1        = (const float*)d_in[15];
    const float* W_p2        = (const float*)d_in[16];
    const float* b_p2        = (const float*)d_in[17];
    const float* W_vec       = (const float*)d_in[18];
    const float* W_f         = (const float*)d_in[19];
    const float* b_f         = (const float*)d_in[20];

    float* out = (float*)d_out;
    float* out_scal = out;
    float* out_vec  = out + (size_t)N_NODES * H;
    float* out_edge = out + (size_t)N_NODES * H * 4;

    float* p_ns;    cudaGetSymbolAddress((void**)&p_ns, g_ns);
    float* p_nv;    cudaGetSymbolAddress((void**)&p_nv, g_nv);
    float* p_ns1;   cudaGetSymbolAddress((void**)&p_ns1, g_ns1);
    float* p_nvec1; cudaGetSymbolAddress((void**)&p_nvec1, g_nvec1);
    float* p_wv;    cudaGetSymbolAddress((void**)&p_wv, g_wv);
    float* p_p;     cudaGetSymbolAddress((void**)&p_p, g_p);
    __nv_bfloat16* wp; cudaGetSymbolAddress((void**)&wp, g_wpack);
    int* p_eids;  cudaGetSymbolAddress((void**)&p_eids, g_eids);
    int* p_own;   cudaGetSymbolAddress((void**)&p_own, g_own);
    int* p_ej;    cudaGetSymbolAddress((void**)&p_ej, g_ej);
    float* p_distc; cudaGetSymbolAddress((void**)&p_distc, g_distc);
    float* p_evc;   cudaGetSymbolAddress((void**)&p_evc, g_evc);

    cudaFuncSetAttribute(gemmA, cudaFuncAttributeMaxDynamicSharedMemorySize, SM_GEMM);
    cudaFuncSetAttribute(gemmB, cudaFuncAttributeMaxDynamicSharedMemorySize, SM_GEMM);
    cudaFuncSetAttribute(mega_msg, cudaFuncAttributeMaxDynamicSharedMemorySize, SM_MEGA);
    cudaFuncSetAttribute(csr_build, cudaFuncAttributeMaxDynamicSharedMemorySize, N_NODES * 4);

    // 1
    pack_all<<<dim3(11, 8), 256>>>(W_node, W_edge, W_p1, W_cross, W_f, W_vec, W_p2);
    // 2
    csr_build<<<1, 1024, N_NODES * 4>>>(edge_index);
    // 3
    csr_scatter<<<(N_EDGES + 255) / 256, 256>>>(edge_index, dist, edge_vector);
    // 4: ns + nv (combined); also ns1/nvec1 residual init
    gemmA<<<GB_3N + GB_N, 256, SM_GEMM>>>(node_scalar, node_vector,
                                          wp + 0 * 32768, wp + 4 * 32768,
                                          b_node, ln_gamma, ln_beta,
                                          p_ns, p_nv, p_ns1, p_nvec1);
    // 5: whole message path + edge update
    mega_msg<<<GB_E, 256, SM_MEGA>>>(edge_feats, wp + 1 * 32768, wp + 2 * 32768, wp + 5 * 32768,
                                     b_edge, b_p1, b_f, p_eids, p_own, p_ej, p_distc,
                                     alpha, p_evc, p_ns, node_vector, p_nv,
                                     p_ns1, p_nvec1, out_edge);
    // 6: wv + p (combined)
    gemmB<<<GB_3N * 2 + GB_N * 3, 256, SM_GEMM>>>(p_nvec1, p_ns1,
                                                  wp + 6 * 32768, wp + 8 * 32768,
                                                  b_p2, p_wv, p_p);
    // 7
    node_final<<<N_NODES, 128>>>(out_scal, out_vec);
}